// round 10
// baseline (speedup 1.0000x reference)
#include <cuda_runtime.h>
#include <cuda_fp16.h>
#include <math.h>
#include <stdint.h>

#define B_   32
#define S_   512
#define D_   1024
#define NH_  16
#define E_   16
#define H_   256
#define DH_  64
#define T_   (B_ * S_)          // 16384
#define CAP_ 16384

// ---------------- scratch (static device memory) ---------------------------
__device__ __half g_h16[(size_t)T_ * D_];
__device__ __half g_qkv16[(size_t)T_ * 3 * D_];
__device__ __half g_vt16[(size_t)B_ * NH_ * DH_ * S_];
__device__ __half g_ctx16[(size_t)T_ * D_];
__device__ float  g_x[(size_t)T_ * D_];
__device__ float  g_gate[(size_t)T_ * E_];
__device__ __half g_wi16[(size_t)3 * D_ * D_];
__device__ __half g_wo16[(size_t)D_ * D_];
__device__ __half g_w1t16[(size_t)E_ * H_ * D_];
__device__ __half g_w2te16[(size_t)E_ * D_ * H_];
__device__ __half g_uws[(size_t)E_ * CAP_ * H_];
__device__ __half g_outs[(size_t)E_ * CAP_ * D_];
__device__ int    g_cnt[E_];
__device__ int    g_rowidx[(size_t)E_ * CAP_];
__device__ int    g_pairpos[(size_t)T_ * 8];
__device__ float  g_auxp[128 * E_];

// ---------------- helpers ---------------------------------------------------
__device__ __forceinline__ uint32_t smem_u32(const void* p) {
    uint32_t a;
    asm("{ .reg .u64 t; cvta.to.shared.u64 t, %1; cvt.u32.u64 %0, t; }" : "=r"(a) : "l"(p));
    return a;
}
__device__ __forceinline__ uint32_t h2_as_u32(__half2 h) {
    return *reinterpret_cast<uint32_t*>(&h);
}
#define CP_ASYNC16(dst, src) \
    asm volatile("cp.async.ca.shared.global [%0], [%1], 16;" :: "r"(dst), "l"(src) : "memory")
#define CP_COMMIT() asm volatile("cp.async.commit_group;" ::: "memory")
#define CP_WAIT1()  asm volatile("cp.async.wait_group 1;" ::: "memory")
#define CP_WAIT0()  asm volatile("cp.async.wait_group 0;" ::: "memory")

#define LDSM_X4(r0, r1, r2, r3, addr) \
    asm volatile("ldmatrix.sync.aligned.m8n8.x4.shared.b16 {%0,%1,%2,%3}, [%4];" \
        : "=r"(r0), "=r"(r1), "=r"(r2), "=r"(r3) : "r"(addr))

__device__ __forceinline__ void mma16(float* d, const uint32_t* a, const uint32_t* b) {
    asm volatile(
        "mma.sync.aligned.m16n8k16.row.col.f32.f16.f16.f32 "
        "{%0,%1,%2,%3},{%4,%5,%6,%7},{%8,%9},{%0,%1,%2,%3};"
        : "+f"(d[0]), "+f"(d[1]), "+f"(d[2]), "+f"(d[3])
        : "r"(a[0]), "r"(a[1]), "r"(a[2]), "r"(a[3]), "r"(b[0]), "r"(b[1]));
}

// smem tile: 64 halfs (128B) per row, SW128
__device__ __forceinline__ uint32_t qoff(int m, int c) {
    return (uint32_t)(m * 128 + ((c ^ (m & 7)) << 4));
}
__device__ __forceinline__ float gelu_f(float v) {
    return 0.5f * v * (1.f + erff(v * 0.70710678118654752f));
}

// ---------------- LayerNorm (fp32 in -> half out), float4 loads -------------
__global__ void ln_kernel(const float* __restrict__ x, const float* __restrict__ g,
                          const float* __restrict__ b, __half* __restrict__ y16) {
    long t = blockIdx.x;
    const float* row = x + t * D_;
    int tid = threadIdx.x;
    float4 v = *(const float4*)(row + tid * 4);
    float s = v.x + v.y + v.z + v.w;
    float sq = v.x * v.x + v.y * v.y + v.z * v.z + v.w * v.w;
#pragma unroll
    for (int o = 16; o; o >>= 1) {
        s  += __shfl_xor_sync(0xffffffffu, s, o);
        sq += __shfl_xor_sync(0xffffffffu, sq, o);
    }
    __shared__ float ws[8], wq[8];
    int w = tid >> 5, l = tid & 31;
    if (l == 0) { ws[w] = s; wq[w] = sq; }
    __syncthreads();
    if (tid == 0) {
        float a = 0.f, c = 0.f;
        for (int i = 0; i < 8; i++) { a += ws[i]; c += wq[i]; }
        ws[0] = a; wq[0] = c;
    }
    __syncthreads();
    float mean = ws[0] * (1.f / D_);
    float var  = wq[0] * (1.f / D_) - mean * mean;
    float inv  = rsqrtf(var + 1e-5f);
    int d = tid * 4;
    float4 gv = *(const float4*)(g + d);
    float4 bv = *(const float4*)(b + d);
    __half2 o0 = __floats2half2_rn((v.x - mean) * inv * gv.x + bv.x,
                                   (v.y - mean) * inv * gv.y + bv.y);
    __half2 o1 = __floats2half2_rn((v.z - mean) * inv * gv.z + bv.z,
                                   (v.w - mean) * inv * gv.w + bv.w);
    *(__half2*)(y16 + t * D_ + d)     = o0;
    *(__half2*)(y16 + t * D_ + d + 2) = o1;
}

// ---------------- fp32 -> fp16 convert --------------------------------------
__global__ void conv_f2h(const float* __restrict__ in, __half* __restrict__ out, long n) {
    long i = (long)blockIdx.x * 1024 + threadIdx.x * 4;
    if (i < n) {
        float4 v = *(const float4*)(in + i);
        *(__half2*)(out + i)     = __floats2half2_rn(v.x, v.y);
        *(__half2*)(out + i + 2) = __floats2half2_rn(v.z, v.w);
    }
}

// ---------------- batched tiled transpose -> half ---------------------------
template <typename TI>
__global__ void transpose_h(const TI* __restrict__ src, __half* __restrict__ dst,
                            int R, int C, long srcRS,
                            long sSo, long sSi, long sDo, long sDi, int nInner) {
    int zo = blockIdx.z / nInner, zi = blockIdx.z - zo * nInner;
    src += (long)zo * sSo + (long)zi * sSi;
    dst += (long)zo * sDo + (long)zi * sDi;
    __shared__ float tile[32][33];
    int r0 = blockIdx.y * 32, c0 = blockIdx.x * 32;
    int tx = threadIdx.x & 31, ty = threadIdx.x >> 5;
#pragma unroll
    for (int k = 0; k < 4; k++) {
        int r = r0 + ty + 8 * k;
        if (r < R && c0 + tx < C) tile[ty + 8 * k][tx] = (float)src[(long)r * srcRS + c0 + tx];
    }
    __syncthreads();
#pragma unroll
    for (int k = 0; k < 4; k++) {
        int c = c0 + ty + 8 * k;
        if (c < C && r0 + tx < R) dst[(long)c * R + r0 + tx] = __float2half(tile[tx][ty + 8 * k]);
    }
}

// ---------------- fused flash attention (unchanged, validated) --------------
__global__ void __launch_bounds__(256) flash_k(
    const __half* __restrict__ qkv, const __half* __restrict__ vt,
    __half* __restrict__ ctx) {
    int bh = blockIdx.y;
    int b = bh >> 4, hh = bh & 15;
    int qb = blockIdx.x;
    const __half* Qb = qkv + ((long)b * S_ + qb * 128) * (3 * D_) + hh * DH_;
    const __half* Kb = qkv + (long)b * S_ * (3 * D_) + D_ + hh * DH_;
    const __half* Vb = vt + (long)bh * DH_ * S_;

    __shared__ __align__(16) __half Qs[128 * 64];
    __shared__ __align__(16) __half Ks[2][64 * 64];
    __shared__ __align__(16) __half Vs[2][64 * 64];
    uint32_t qB = smem_u32(Qs), kB = smem_u32(Ks), vB = smem_u32(Vs);

    int tid = threadIdx.x, lane = tid & 31, warp = tid >> 5;
    int wm = warp * 16;
    int g = lane >> 2, tq = lane & 3;
    int q2 = lane >> 3, r7 = lane & 7;
    const float L2E = 1.44269504088896f;

#pragma unroll
    for (int j = 0; j < 4; j++) {
        int s = tid + 256 * j;
        int r = s >> 3, cu = s & 7;
        CP_ASYNC16(qB + qoff(r, cu), Qb + (long)r * (3 * D_) + cu * 8);
    }
    CP_COMMIT();
#pragma unroll
    for (int j = 0; j < 2; j++) {
        int s = tid + 256 * j;
        int r = s >> 3, cu = s & 7;
        CP_ASYNC16(kB + qoff(r, cu), Kb + (long)r * (3 * D_) + cu * 8);
        CP_ASYNC16(vB + qoff(r, cu), Vb + (long)r * S_ + cu * 8);
    }
    CP_COMMIT();
    CP_WAIT0();
    __syncthreads();
    {
        __half2 sc = __floats2half2_rn(0.125f, 0.125f);
        __half2* qh = (__half2*)Qs;
#pragma unroll
        for (int i = 0; i < 16; i++) qh[tid + 256 * i] = __hmul2(qh[tid + 256 * i], sc);
    }
    __syncthreads();

    float o[8][4];
#pragma unroll
    for (int ni = 0; ni < 8; ni++)
#pragma unroll
        for (int r = 0; r < 4; r++) o[ni][r] = 0.f;
    float m0 = -1e30f, m1 = -1e30f, l0 = 0.f, l1 = 0.f;

    for (int c = 0; c < 8; c++) {
        int buf = c & 1;
        if (c + 1 < 8) {
            int nb = 1 - buf;
#pragma unroll
            for (int j = 0; j < 2; j++) {
                int s = tid + 256 * j;
                int r = s >> 3, cu = s & 7;
                CP_ASYNC16(kB + nb * 8192 + qoff(r, cu),
                           Kb + (long)((c + 1) * 64 + r) * (3 * D_) + cu * 8);
                CP_ASYNC16(vB + nb * 8192 + qoff(r, cu),
                           Vb + (long)r * S_ + (c + 1) * 64 + cu * 8);
            }
            CP_COMMIT();
            CP_WAIT1();
        } else {
            CP_WAIT0();
        }
        __syncthreads();

        uint32_t kBuf = kB + buf * 8192, vBuf = vB + buf * 8192;
        float sv[8][4];
#pragma unroll
        for (int ni = 0; ni < 8; ni++)
#pragma unroll
            for (int r = 0; r < 4; r++) sv[ni][r] = 0.f;
#pragma unroll
        for (int ks = 0; ks < 4; ks++) {
            uint32_t af[4], bf[8][2];
            int am = wm + (q2 & 1) * 8 + r7;
            LDSM_X4(af[0], af[1], af[2], af[3], qB + qoff(am, 2 * ks + (q2 >> 1)));
#pragma unroll
            for (int nj = 0; nj < 4; nj++) {
                int bn = nj * 16 + (q2 >> 1) * 8 + r7;
                LDSM_X4(bf[2 * nj][0], bf[2 * nj][1], bf[2 * nj + 1][0], bf[2 * nj + 1][1],
                        kBuf + qoff(bn, 2 * ks + (q2 & 1)));
            }
#pragma unroll
            for (int ni = 0; ni < 8; ni++) mma16(sv[ni], af, bf[ni]);
        }

        float cm0 = -1e30f, cm1 = -1e30f;
#pragma unroll
        for (int ni = 0; ni < 8; ni++) {
            cm0 = fmaxf(cm0, fmaxf(sv[ni][0], sv[ni][1]));
            cm1 = fmaxf(cm1, fmaxf(sv[ni][2], sv[ni][3]));
        }
        cm0 = fmaxf(cm0, __shfl_xor_sync(0xffffffffu, cm0, 1));
        cm0 = fmaxf(cm0, __shfl_xor_sync(0xffffffffu, cm0, 2));
        cm1 = fmaxf(cm1, __shfl_xor_sync(0xffffffffu, cm1, 1));
        cm1 = fmaxf(cm1, __shfl_xor_sync(0xffffffffu, cm1, 2));
        float mn0 = fmaxf(m0, cm0), mn1 = fmaxf(m1, cm1);
        float sc0 = exp2f((m0 - mn0) * L2E), sc1 = exp2f((m1 - mn1) * L2E);
        m0 = mn0; m1 = mn1;
        l0 *= sc0; l1 *= sc1;
#pragma unroll
        for (int ni = 0; ni < 8; ni++) {
            o[ni][0] *= sc0; o[ni][1] *= sc0;
            o[ni][2] *= sc1; o[ni][3] *= sc1;
        }
        uint32_t pa[4][4];
        float rs0 = 0.f, rs1 = 0.f;
#pragma unroll
        for (int ni = 0; ni < 8; ni++) {
            float p0 = exp2f((sv[ni][0] - mn0) * L2E);
            float p1 = exp2f((sv[ni][1] - mn0) * L2E);
            float p2 = exp2f((sv[ni][2] - mn1) * L2E);
            float p3 = exp2f((sv[ni][3] - mn1) * L2E);
            rs0 += p0 + p1; rs1 += p2 + p3;
            int kk = ni >> 1, hi = ni & 1;
            pa[kk][hi * 2]     = h2_as_u32(__floats2half2_rn(p0, p1));
            pa[kk][hi * 2 + 1] = h2_as_u32(__floats2half2_rn(p2, p3));
        }
        rs0 += __shfl_xor_sync(0xffffffffu, rs0, 1);
        rs0 += __shfl_xor_sync(0xffffffffu, rs0, 2);
        rs1 += __shfl_xor_sync(0xffffffffu, rs1, 1);
        rs1 += __shfl_xor_sync(0xffffffffu, rs1, 2);
        l0 += rs0; l1 += rs1;

#pragma unroll
        for (int ks = 0; ks < 4; ks++) {
            uint32_t bf[8][2];
#pragma unroll
            for (int nj = 0; nj < 4; nj++) {
                int bn = nj * 16 + (q2 >> 1) * 8 + r7;
                LDSM_X4(bf[2 * nj][0], bf[2 * nj][1], bf[2 * nj + 1][0], bf[2 * nj + 1][1],
                        vBuf + qoff(bn, 2 * ks + (q2 & 1)));
            }
#pragma unroll
            for (int ni = 0; ni < 8; ni++) mma16(o[ni], pa[ks], bf[ni]);
        }
        __syncthreads();
    }

    float li0 = 1.f / l0, li1 = 1.f / l1;
    long row0 = (long)b * S_ + qb * 128 + wm + g;
    __half* c0p = ctx + (row0)     * D_ + hh * DH_;
    __half* c1p = ctx + (row0 + 8) * D_ + hh * DH_;
#pragma unroll
    for (int ni = 0; ni < 8; ni++) {
        int nc = ni * 8 + tq * 2;
        *(__half2*)(c0p + nc) = __floats2half2_rn(o[ni][0] * li0, o[ni][1] * li0);
        *(__half2*)(c1p + nc) = __floats2half2_rn(o[ni][2] * li1, o[ni][3] * li1);
    }
}

// ---------------- fp16 GEMM: 128x128 tile, BK=64, 3 stages, 2 CTAs/SM -------
template <bool BI, bool RE, bool HOUT>
__global__ void __launch_bounds__(256, 2) gemm_h(
    const __half* __restrict__ A, const __half* __restrict__ Bm, void* __restrict__ C,
    const float* __restrict__ bias, const float* __restrict__ resid,
    int Kd, int lda, int ldb, int ldc) {
    constexpr int STAGE = 32768, BOFF = 16384;
    extern __shared__ __align__(16) char smdyn[];
    uint32_t sb = smem_u32(smdyn);

    int tid = threadIdx.x, lane = tid & 31, warp = tid >> 5;
    int bm = blockIdx.y * 128, bn = blockIdx.x * 128;
    int wm = (warp % 4) * 32, wn = (warp / 4) * 64;
    int g = lane >> 2, tq = lane & 3;
    int q2 = lane >> 3, r7 = lane & 7;

    float acc[2][8][4];
#pragma unroll
    for (int mi = 0; mi < 2; mi++)
#pragma unroll
        for (int ni = 0; ni < 8; ni++)
#pragma unroll
            for (int r = 0; r < 4; r++) acc[mi][ni][r] = 0.f;

    int NC = Kd >> 6;
#define GH_ISSUE(st, k0)                                                              \
    do {                                                                              \
        uint32_t _as = sb + (st) * STAGE, _bs = _as + BOFF;                           \
        _Pragma("unroll")                                                             \
        for (int j = 0; j < 4; j++) {                                                 \
            int s = tid + 256 * j; int r = s >> 3, cu = s & 7;                        \
            CP_ASYNC16(_as + qoff(r, cu), A + (long)(bm + r) * lda + (k0) + cu * 8);  \
            CP_ASYNC16(_bs + qoff(r, cu), Bm + (long)(bn + r) * ldb + (k0) + cu * 8); \
        }                                                                             \
    } while (0)

    GH_ISSUE(0, 0); CP_COMMIT();
    GH_ISSUE(1, 64); CP_COMMIT();

    for (int ck = 0; ck < NC; ck++) {
        CP_WAIT1();
        __syncthreads();
        if (ck + 2 < NC) { int st = (ck + 2) % 3; GH_ISSUE(st, (ck + 2) << 6); }
        CP_COMMIT();
        uint32_t aBase = sb + (ck % 3) * STAGE, bBase = aBase + BOFF;
#pragma unroll
        for (int s = 0; s < 4; s++) {
            uint32_t af[2][4], bf[8][2];
#pragma unroll
            for (int mi = 0; mi < 2; mi++) {
                int m = wm + mi * 16 + (q2 & 1) * 8 + r7;
                LDSM_X4(af[mi][0], af[mi][1], af[mi][2], af[mi][3],
                        aBase + qoff(m, 2 * s + (q2 >> 1)));
            }
#pragma unroll
            for (int nj = 0; nj < 4; nj++) {
                int n = wn + nj * 16 + (q2 >> 1) * 8 + r7;
                LDSM_X4(bf[2 * nj][0], bf[2 * nj][1], bf[2 * nj + 1][0], bf[2 * nj + 1][1],
                        bBase + qoff(n, 2 * s + (q2 & 1)));
            }
#pragma unroll
            for (int mi = 0; mi < 2; mi++)
#pragma unroll
                for (int ni = 0; ni < 8; ni++)
                    mma16(acc[mi][ni], af[mi], bf[ni]);
        }
        __syncthreads();
    }
#undef GH_ISSUE

    __half* Ch = (__half*)C;
    float*  Cf = (float*)C;
#pragma unroll
    for (int mi = 0; mi < 2; mi++) {
#pragma unroll
        for (int rh = 0; rh < 2; rh++) {
            int row = bm + wm + mi * 16 + g + rh * 8;
#pragma unroll
            for (int ni = 0; ni < 8; ni++) {
                int n = bn + wn + ni * 8 + tq * 2;
                float v0 = acc[mi][ni][rh * 2], v1 = acc[mi][ni][rh * 2 + 1];
                if (BI) { v0 += bias[n]; v1 += bias[n + 1]; }
                if (HOUT) {
                    *(__half2*)(Ch + (long)row * ldc + n) = __floats2half2_rn(v0, v1);
                } else {
                    if (RE) {
                        float2 rv = *(const float2*)(resid + (long)row * ldc + n);
                        v0 += rv.x; v1 += rv.y;
                    }
                    float2 ov; ov.x = v0; ov.y = v1;
                    *(float2*)(Cf + (long)row * ldc + n) = ov;
                }
            }
        }
    }
}

// ---------------- MoE up: indexed-A grouped GEMM, GELU*gate epilogue --------
__global__ void __launch_bounds__(256, 2) gemm_up(
    const __half* __restrict__ Ah, const __half* __restrict__ w1t,
    __half* __restrict__ uws, const float* __restrict__ b1,
    const float* __restrict__ gd, const int* __restrict__ rowidx,
    const int* __restrict__ cnt) {
    constexpr int STAGE = 32768, BOFF = 16384;
    extern __shared__ __align__(16) char smdyn[];
    uint32_t sb = smem_u32(smdyn);

    int e = blockIdx.z;
    int c = cnt[e];
    int cp = (c + 127) & ~127;
    int bm = blockIdx.y * 128;
    if (bm >= cp) return;
    int bn = blockIdx.x * 128;

    int tid = threadIdx.x, lane = tid & 31, warp = tid >> 5;
    int wm = (warp % 4) * 32, wn = (warp / 4) * 64;
    int g = lane >> 2, tq = lane & 3;
    int q2 = lane >> 3, r7 = lane & 7;
    const __half* Bp = w1t + (long)e * (H_ * D_);
    const int* ridx = rowidx + (long)e * CAP_;

    int tokA[4];
#pragma unroll
    for (int j = 0; j < 4; j++) {
        int r = (tid + 256 * j) >> 3;
        tokA[j] = ridx[bm + r];
    }

    float acc[2][8][4];
#pragma unroll
    for (int mi = 0; mi < 2; mi++)
#pragma unroll
        for (int ni = 0; ni < 8; ni++)
#pragma unroll
            for (int r = 0; r < 4; r++) acc[mi][ni][r] = 0.f;

#define UP_ISSUE(st, k0)                                                              \
    do {                                                                              \
        uint32_t _as = sb + (st) * STAGE, _bs = _as + BOFF;                           \
        _Pragma("unroll")                                                             \
        for (int j = 0; j < 4; j++) {                                                 \
            int s = tid + 256 * j; int r = s >> 3, cu = s & 7;                        \
            CP_ASYNC16(_as + qoff(r, cu), Ah + (long)tokA[j] * D_ + (k0) + cu * 8);   \
            CP_ASYNC16(_bs + qoff(r, cu), Bp + (long)(bn + r) * D_ + (k0) + cu * 8);  \
        }                                                                             \
    } while (0)

    UP_ISSUE(0, 0); CP_COMMIT();
    UP_ISSUE(1, 64); CP_COMMIT();

    for (int ck = 0; ck < 16; ck++) {
        CP_WAIT1();
        __syncthreads();
        if (ck + 2 < 16) { int st = (ck + 2) % 3; UP_ISSUE(st, (ck + 2) << 6); }
        CP_COMMIT();
        uint32_t aBase = sb + (ck % 3) * STAGE, bBase = aBase + BOFF;
#pragma unroll
        for (int s = 0; s < 4; s++) {
            uint32_t af[2][4], bf[8][2];
#pragma unroll
            for (int mi = 0; mi < 2; mi++) {
                int m = wm + mi * 16 + (q2 & 1) * 8 + r7;
                LDSM_X4(af[mi][0], af[mi][1], af[mi][2], af[mi][3],
                        aBase + qoff(m, 2 * s + (q2 >> 1)));
            }
#pragma unroll
            for (int nj = 0; nj < 4; nj++) {
                int n = wn + nj * 16 + (q2 >> 1) * 8 + r7;
                LDSM_X4(bf[2 * nj][0], bf[2 * nj][1], bf[2 * nj + 1][0], bf[2 * nj + 1][1],
                        bBase + qoff(n, 2 * s + (q2 & 1)));
            }
#pragma unroll
            for (int mi = 0; mi < 2; mi++)
#pragma unroll
                for (int ni = 0; ni < 8; ni++)
                    mma16(acc[mi][ni], af[mi], bf[ni]);
        }
        __syncthreads();
    }
#undef UP_ISSUE

    const float* b1e = b1 + (long)e * H_;
#pragma unroll
    for (int mi = 0; mi < 2; mi++) {
#pragma unroll
        for (int rh = 0; rh < 2; rh++) {
            int row = bm + wm + mi * 16 + g + rh * 8;
            int tok = ridx[row];
            float gv = gd[(long)tok * 16 + e];
            __half* orow = uws + ((long)e * CAP_ + row) * H_;
#pragma unroll
            for (int ni = 0; ni < 8; ni++) {
                int n = bn + wn + ni * 8 + tq * 2;
                float v0 = gelu_f(acc[mi][ni][rh * 2]     + b1e[n])     * gv;
                float v1 = gelu_f(acc[mi][ni][rh * 2 + 1] + b1e[n + 1]) * gv;
                *(__half2*)(orow + n) = __floats2half2_rn(v0, v1);
            }
        }
    }
}

// ---------------- MoE down: grouped GEMM, K=256 -----------------------------
__global__ void __launch_bounds__(256, 2) gemm_dn(
    const __half* __restrict__ uws, const __half* __restrict__ w2te,
    __half* __restrict__ outs, const int* __restrict__ cnt) {
    constexpr int STAGE = 32768, BOFF = 16384;
    extern __shared__ __align__(16) char smdyn[];
    uint32_t sb = smem_u32(smdyn);

    int e = blockIdx.z;
    int c = cnt[e];
    int cp = (c + 127) & ~127;
    int bm = blockIdx.y * 128;
    if (bm >= cp) return;
    int bn = blockIdx.x * 128;

    int tid = threadIdx.x, lane = tid & 31, warp = tid >> 5;
    int wm = (warp % 4) * 32, wn = (warp / 4) * 64;
    int g = lane >> 2, tq = lane & 3;
    int q2 = lane >> 3, r7 = lane & 7;
    const __half* Ap = uws + (long)e * CAP_ * H_;
    const __half* Bp = w2te + (long)e * (D_ * H_);

    float acc[2][8][4];
#pragma unroll
    for (int mi = 0; mi < 2; mi++)
#pragma unroll
        for (int ni = 0; ni < 8; ni++)
#pragma unroll
            for (int r = 0; r < 4; r++) acc[mi][ni][r] = 0.f;

#define DN_ISSUE(st, k0)                                                              \
    do {                                                                              \
        uint32_t _as = sb + (st) * STAGE, _bs = _as + BOFF;                           \
        _Pragma("unroll")                                                             \
        for (int j = 0; j < 4; j++) {                                                 \
            int s = tid + 256 * j; int r = s >> 3, cu = s & 7;                        \
            CP_ASYNC16(_as + qoff(r, cu), Ap + (long)(bm + r) * H_ + (k0) + cu * 8);  \
            CP_ASYNC16(_bs + qoff(r, cu), Bp + (long)(bn + r) * H_ + (k0) + cu * 8);  \
        }                                                                             \
    } while (0)

    DN_ISSUE(0, 0); CP_COMMIT();
    DN_ISSUE(1, 64); CP_COMMIT();

    for (int ck = 0; ck < 4; ck++) {
        CP_WAIT1();
        __syncthreads();
        if (ck + 2 < 4) { int st = (ck + 2) % 3; DN_ISSUE(st, (ck + 2) << 6); }
        CP_COMMIT();
        uint32_t aBase = sb + (ck % 3) * STAGE, bBase = aBase + BOFF;
#pragma unroll
        for (int s = 0; s < 4; s++) {
            uint32_t af[2][4], bf[8][2];
#pragma unroll
            for (int mi = 0; mi < 2; mi++) {
                int m = wm + mi * 16 + (q2 & 1) * 8 + r7;
                LDSM_X4(af[mi][0], af[mi][1], af[mi][2], af[mi][3],
                        aBase + qoff(m, 2 * s + (q2 >> 1)));
            }
#pragma unroll
            for (int nj = 0; nj < 4; nj++) {
                int n = wn + nj * 16 + (q2 >> 1) * 8 + r7;
                LDSM_X4(bf[2 * nj][0], bf[2 * nj][1], bf[2 * nj + 1][0], bf[2 * nj + 1][1],
                        bBase + qoff(n, 2 * s + (q2 & 1)));
            }
#pragma unroll
            for (int mi = 0; mi < 2; mi++)
#pragma unroll
                for (int ni = 0; ni < 8; ni++)
                    mma16(acc[mi][ni], af[mi], bf[ni]);
        }
        __syncthreads();
    }
#undef DN_ISSUE

#pragma unroll
    for (int mi = 0; mi < 2; mi++) {
#pragma unroll
        for (int rh = 0; rh < 2; rh++) {
            int row = bm + wm + mi * 16 + g + rh * 8;
            __half* orow = outs + ((long)e * CAP_ + row) * D_;
#pragma unroll
            for (int ni = 0; ni < 8; ni++) {
                int n = bn + wn + ni * 8 + tq * 2;
                *(__half2*)(orow + n) =
                    __floats2half2_rn(acc[mi][ni][rh * 2], acc[mi][ni][rh * 2 + 1]);
            }
        }
    }
}

// ---------------- gate v3: logits + softmax + top8 + routing + aux partial --
__global__ void __launch_bounds__(256) gate_v3(
    const __half* __restrict__ h3, const float* __restrict__ gate_w,
    const int* __restrict__ task_id,
    float* __restrict__ probs, float* __restrict__ gate_dense,
    int* __restrict__ cnt, int* __restrict__ rowidx, int* __restrict__ pairpos,
    float* __restrict__ auxp) {
    extern __shared__ float gwT[];   // [16][1024] + aux red [8][16]
    float* auxred = gwT + 16 * 1024;
    const float* gw = gate_w + (long)(*task_id) * (D_ * E_);
    int tid = threadIdx.x;
#pragma unroll 8
    for (int j = 0; j < 64; j++) {
        int idx = tid + 256 * j;
        int d = idx >> 4, e = idx & 15;
        gwT[e * 1024 + d] = gw[idx];
    }
    int warp = tid >> 5, lane = tid & 31;
    if (lane < 16) auxred[warp * 16 + lane] = 0.f;
    __syncthreads();
    float auxacc[16];
#pragma unroll
    for (int e = 0; e < 16; e++) auxacc[e] = 0.f;

    for (int i = 0; i < 16; i++) {
        long tok = (long)blockIdx.x * 128 + i * 8 + warp;
        const __half* hrow = h3 + tok * D_;
        float acc[16];
#pragma unroll
        for (int e = 0; e < 16; e++) acc[e] = 0.f;
#pragma unroll
        for (int j = 0; j < 8; j++) {
            int d0 = (j * 32 + lane) * 4;
            __half2 a = *(const __half2*)(hrow + d0);
            __half2 b = *(const __half2*)(hrow + d0 + 2);
            float2 fa = __half22float2(a), fb = __half22float2(b);
#pragma unroll
            for (int e = 0; e < 16; e++) {
                float4 g4 = *(const float4*)&gwT[e * 1024 + d0];
                acc[e] += fa.x * g4.x + fa.y * g4.y + fb.x * g4.z + fb.y * g4.w;
            }
        }
#pragma unroll
        for (int e = 0; e < 16; e++) {
#pragma unroll
            for (int o = 16; o; o >>= 1)
                acc[e] += __shfl_xor_sync(0xffffffffu, acc[e], o);
        }
        if (lane == 0) {
            float mx = -1e30f;
#pragma unroll
            for (int e = 0; e < 16; e++) mx = fmaxf(mx, acc[e]);
            float sum = 0.f;
#pragma unroll
            for (int e = 0; e < 16; e++) { acc[e] = expf(acc[e] - mx); sum += acc[e]; }
            float inv = 1.f / sum;
            float p[16];
#pragma unroll
            for (int e = 0; e < 16; e++) {
                p[e] = acc[e] * inv;
                probs[tok * 16 + e] = p[e];
                auxacc[e] += p[e];
            }
            bool used[16];
#pragma unroll
            for (int e = 0; e < 16; e++) used[e] = false;
            int tix[8]; float tvl[8]; float gsum = 0.f;
            for (int kk = 0; kk < 8; kk++) {
                float best = -1.f; int bi = 0;
                for (int e = 0; e < 16; e++)
                    if (!used[e] && p[e] > best) { best = p[e]; bi = e; }
                used[bi] = true; tix[kk] = bi; tvl[kk] = best; gsum += best;
            }
            float ginv = 1.f / (gsum + 1e-6f);
            float gdv[16];
#pragma unroll
            for (int e = 0; e < 16; e++) gdv[e] = 0.f;
            for (int kk = 0; kk < 8; kk++) gdv[tix[kk]] = tvl[kk] * ginv;
#pragma unroll
            for (int e = 0; e < 16; e++) gate_dense[tok * 16 + e] = gdv[e];
            // routing (k-order fixed per token -> deterministic gather)
            for (int kk = 0; kk < 8; kk++) {
                int e = tix[kk];
                int pos = atomicAdd(&cnt[e], 1);
                rowidx[(long)e * CAP_ + pos] = (int)tok;
                pairpos[tok * 8 + kk] = e * CAP_ + pos;
            }
        }
    }
    // aux partial: lane0 of each warp holds its 16-token sums
    if (lane == 0) {
#pragma unroll
        for (int e = 0; e < 16; e++) auxred[warp * 16 + e] = auxacc[e];
    }
    __syncthreads();
    if (tid < 16) {
        float s = 0.f;
#pragma unroll
        for (int w = 0; w < 8; w++) s += auxred[w * 16 + tid];
        auxp[blockIdx.x * 16 + tid] = s;
    }
}

__global__ void zero_cnt(int* cnt) {
    if (threadIdx.x < E_) cnt[threadIdx.x] = 0;
}
__global__ void aux_fin(const float* __restrict__ part, float* __restrict__ outv) {
    if (threadIdx.x == 0) {
        float aux = 0.f;
        for (int e = 0; e < 16; e++) {
            float s = 0.f;
            for (int b = 0; b < 128; b++) s += part[b * 16 + e];
            float mp = s * (1.f / T_);
            aux += mp * logf(mp + 1e-6f);
        }
        outv[0] = 5e-4f * aux;
    }
}

// ---------------- gather: 2 tokens/block ------------------------------------
__global__ void __launch_bounds__(512) gather_k(
    const float* __restrict__ x, const __half* __restrict__ outs,
    const int* __restrict__ pairpos, const float* __restrict__ gd,
    const float* __restrict__ b2, float* __restrict__ out) {
    int half_ = threadIdx.x >> 8;
    int tid = threadIdx.x & 255;
    long t = (long)blockIdx.x * 2 + half_;
    __shared__ int pp[2][8];
    __shared__ float gdv[2][16];
    if (tid < 8) pp[half_][tid] = pairpos[t * 8 + tid];
    if (tid < 16) gdv[half_][tid] = gd[t * 16 + tid];
    __syncthreads();
    int d = tid * 4;
    float4 a = *(const float4*)(x + t * D_ + d);
#pragma unroll
    for (int k = 0; k < 8; k++) {
        const __half2* o2 = (const __half2*)(outs + (long)pp[half_][k] * D_ + d);
        float2 f0 = __half22float2(o2[0]), f1 = __half22float2(o2[1]);
        a.x += f0.x; a.y += f0.y; a.z += f1.x; a.w += f1.y;
    }
#pragma unroll
    for (int e = 0; e < 16; e++) {
        float4 bv = *(const float4*)(b2 + (long)e * D_ + d);
        float gv = gdv[half_][e];
        a.x += gv * bv.x; a.y += gv * bv.y; a.z += gv * bv.z; a.w += gv * bv.w;
    }
    *(float4*)(out + t * D_ + d) = a;
}

// ---------------- launch -----------------------------------------------------
extern "C" void kernel_launch(void* const* d_in, const int* in_sizes, int n_in,
                              void* d_out, int out_size) {
    const float* tgt        = (const float*)d_in[0];
    const float* ln1_g      = (const float*)d_in[2];
    const float* ln1_b      = (const float*)d_in[3];
    const float* ln3_g      = (const float*)d_in[4];
    const float* ln3_b      = (const float*)d_in[5];
    const float* in_proj_w  = (const float*)d_in[6];
    const float* in_proj_b  = (const float*)d_in[7];
    const float* out_proj_w = (const float*)d_in[8];
    const float* out_proj_b = (const float*)d_in[9];
    const float* gate_w     = (const float*)d_in[10];
    const float* w1         = (const float*)d_in[11];
    const float* b1         = (const float*)d_in[12];
    const float* w2         = (const float*)d_in[13];
    const float* b2         = (const float*)d_in[14];
    const int*   task_id    = (const int*)d_in[15];

    float* out       = (float*)d_out;
    float* out_x     = out;
    float* out_aux   = out + (size_t)T_ * D_;
    float* out_probs = out_aux + 1;

    __half *h16, *qkv16, *vt16, *ctx16, *wi16, *wo16, *w1t16, *w2te16, *uws, *outs;
    float *x, *gd, *auxp;
    int *cnt, *rowidx, *pairpos;
    cudaGetSymbolAddress((void**)&h16,    g_h16);
    cudaGetSymbolAddress((void**)&qkv16,  g_qkv16);
    cudaGetSymbolAddress((void**)&vt16,   g_vt16);
    cudaGetSymbolAddress((void**)&ctx16,  g_ctx16);
    cudaGetSymbolAddress((void**)&x,      g_x);
    cudaGetSymbolAddress((void**)&gd,     g_gate);
    cudaGetSymbolAddress((void**)&wi16,   g_wi16);
    cudaGetSymbolAddress((void**)&wo16,   g_wo16);
    cudaGetSymbolAddress((void**)&w1t16,  g_w1t16);
    cudaGetSymbolAddress((void**)&w2te16, g_w2te16);
    cudaGetSymbolAddress((void**)&uws,    g_uws);
    cudaGetSymbolAddress((void**)&outs,   g_outs);
    cudaGetSymbolAddress((void**)&cnt,    g_cnt);
    cudaGetSymbolAddress((void**)&rowidx, g_rowidx);
    cudaGetSymbolAddress((void**)&pairpos,g_pairpos);
    cudaGetSymbolAddress((void**)&auxp,   g_auxp);

    const int GSM = 3 * 32768;      // 98304
    const int GATESM = 65536 + 8 * 16 * 4;
    cudaFuncSetAttribute(gemm_h<true, false, true >, cudaFuncAttributeMaxDynamicSharedMemorySize, GSM);
    cudaFuncSetAttribute(gemm_h<true, true,  false>, cudaFuncAttributeMaxDynamicSharedMemorySize, GSM);
    cudaFuncSetAttribute(gemm_up, cudaFuncAttributeMaxDynamicSharedMemorySize, GSM);
    cudaFuncSetAttribute(gemm_dn, cudaFuncAttributeMaxDynamicSharedMemorySize, GSM);
    cudaFuncSetAttribute(gate_v3, cudaFuncAttributeMaxDynamicSharedMemorySize, GATESM);

    // 0. weight preprocessing
    conv_f2h<<<(unsigned)(3L * D_ * D_ / 1024), 256>>>(in_proj_w, wi16, 3L * D_ * D_);
    conv_f2h<<<(unsigned)(1L * D_ * D_ / 1024), 256>>>(out_proj_w, wo16, 1L * D_ * D_);
    transpose_h<float><<<dim3(8, 32, E_), 256>>>(
        w1, w1t16, D_, H_, H_, (long)D_ * H_, 0, (long)H_ * D_, 0, 1);
    transpose_h<float><<<dim3(32, 8, E_), 256>>>(
        w2, w2te16, H_, D_, D_, (long)H_ * D_, 0, (long)D_ * H_, 0, 1);

    // 1. h = LN1(tgt)
    ln_kernel<<<T_, 256>>>(tgt, ln1_g, ln1_b, h16);

    // 2. qkv = h @ in_proj_w^T + b (half out)
    gemm_h<true, false, true><<<dim3(24, 128), 256, GSM>>>(
        h16, wi16, qkv16, in_proj_b, nullptr, D_, D_, D_, 3 * D_);

    // 3. Vt = V^T per (b,h)
    transpose_h<__half><<<dim3(2, 16, B_ * NH_), 256>>>(
        qkv16 + 2 * D_, vt16, S_, DH_, 3 * D_,
        (long)S_ * 3 * D_, DH_, (long)NH_ * DH_ * S_, (long)DH_ * S_, NH_);

    // 4. fused flash attention -> ctx16
    flash_k<<<dim3(4, B_ * NH_), 256>>>(qkv16, vt16, ctx16);

    // 5. x = tgt + ctx @ out_proj_w^T + b (fp32 out)
    gemm_h<true, true, false><<<dim3(8, 128), 256, GSM>>>(
        ctx16, wo16, x, out_proj_b, tgt, D_, D_, D_, D_);

    // 6. h3 = LN3(x)
    ln_kernel<<<T_, 256>>>(x, ln3_g, ln3_b, h16);

    // 7. gate + routing + aux partials (fused), then aux final
    zero_cnt<<<1, 32>>>(cnt);
    gate_v3<<<T_ / 128, 256, GATESM>>>(h16, gate_w, task_id, out_probs, gd,
                                       cnt, rowidx, pairpos, auxp);
    aux_fin<<<1, 32>>>(auxp, out_aux);

    // 8. sparse MoE up
    gemm_up<<<dim3(2, 128, E_), 256, GSM>>>(h16, w1t16, uws, b1, gd, rowidx, cnt);

    // 9. sparse MoE down
    gemm_dn<<<dim3(8, 128, E_), 256, GSM>>>(uws, w2te16, outs, cnt);

    // 10. gather: out = x + sum_k outs + gd @ b2
    gather_k<<<T_ / 2, 512>>>(x, outs, pairpos, gd, b2, out_x);

    (void)in_sizes; (void)n_in; (void)out_size;
}

// round 11
// speedup vs baseline: 1.0379x; 1.0379x over previous
#include <cuda_runtime.h>
#include <cuda_fp16.h>
#include <math.h>
#include <stdint.h>

#define B_   32
#define S_   512
#define D_   1024
#define NH_  16
#define E_   16
#define H_   256
#define DH_  64
#define T_   (B_ * S_)          // 16384
#define CAP_ 16384

// ---------------- scratch (static device memory) ---------------------------
__device__ __half g_h16[(size_t)T_ * D_];
__device__ __half g_qkv16[(size_t)T_ * 3 * D_];
__device__ __half g_vt16[(size_t)B_ * NH_ * DH_ * S_];
__device__ __half g_ctx16[(size_t)T_ * D_];
__device__ float  g_x[(size_t)T_ * D_];
__device__ float  g_gate[(size_t)T_ * E_];
__device__ __half g_wi16[(size_t)3 * D_ * D_];
__device__ __half g_wo16[(size_t)D_ * D_];
__device__ __half g_w1t16[(size_t)E_ * H_ * D_];
__device__ __half g_w2te16[(size_t)E_ * D_ * H_];
__device__ __half g_uws[(size_t)E_ * CAP_ * H_];
__device__ __half g_outs[(size_t)E_ * CAP_ * D_];
__device__ int    g_cnt[E_];
__device__ int    g_rowidx[(size_t)E_ * CAP_];
__device__ int    g_pairpos[(size_t)T_ * 8];
__device__ float  g_auxp[64 * E_];

// ---------------- helpers ---------------------------------------------------
__device__ __forceinline__ uint32_t smem_u32(const void* p) {
    uint32_t a;
    asm("{ .reg .u64 t; cvta.to.shared.u64 t, %1; cvt.u32.u64 %0, t; }" : "=r"(a) : "l"(p));
    return a;
}
__device__ __forceinline__ uint32_t h2_as_u32(__half2 h) {
    return *reinterpret_cast<uint32_t*>(&h);
}
#define CP_ASYNC16(dst, src) \
    asm volatile("cp.async.ca.shared.global [%0], [%1], 16;" :: "r"(dst), "l"(src) : "memory")
#define CP_COMMIT() asm volatile("cp.async.commit_group;" ::: "memory")
#define CP_WAIT1()  asm volatile("cp.async.wait_group 1;" ::: "memory")
#define CP_WAIT0()  asm volatile("cp.async.wait_group 0;" ::: "memory")

#define LDSM_X4(r0, r1, r2, r3, addr) \
    asm volatile("ldmatrix.sync.aligned.m8n8.x4.shared.b16 {%0,%1,%2,%3}, [%4];" \
        : "=r"(r0), "=r"(r1), "=r"(r2), "=r"(r3) : "r"(addr))

__device__ __forceinline__ void mma16(float* d, const uint32_t* a, const uint32_t* b) {
    asm volatile(
        "mma.sync.aligned.m16n8k16.row.col.f32.f16.f16.f32 "
        "{%0,%1,%2,%3},{%4,%5,%6,%7},{%8,%9},{%0,%1,%2,%3};"
        : "+f"(d[0]), "+f"(d[1]), "+f"(d[2]), "+f"(d[3])
        : "r"(a[0]), "r"(a[1]), "r"(a[2]), "r"(a[3]), "r"(b[0]), "r"(b[1]));
}

// smem tile: 64 halfs (128B) per row, SW128
__device__ __forceinline__ uint32_t qoff(int m, int c) {
    return (uint32_t)(m * 128 + ((c ^ (m & 7)) << 4));
}
__device__ __forceinline__ float gelu_f(float v) {
    return 0.5f * v * (1.f + erff(v * 0.70710678118654752f));
}

// ---------------- LayerNorm (fp32 in -> half out), float4 loads -------------
__global__ void ln_kernel(const float* __restrict__ x, const float* __restrict__ g,
                          const float* __restrict__ b, __half* __restrict__ y16) {
    long t = blockIdx.x;
    const float* row = x + t * D_;
    int tid = threadIdx.x;
    float4 v = *(const float4*)(row + tid * 4);
    float s = v.x + v.y + v.z + v.w;
    float sq = v.x * v.x + v.y * v.y + v.z * v.z + v.w * v.w;
#pragma unroll
    for (int o = 16; o; o >>= 1) {
        s  += __shfl_xor_sync(0xffffffffu, s, o);
        sq += __shfl_xor_sync(0xffffffffu, sq, o);
    }
    __shared__ float ws[8], wq[8];
    int w = tid >> 5, l = tid & 31;
    if (l == 0) { ws[w] = s; wq[w] = sq; }
    __syncthreads();
    if (tid == 0) {
        float a = 0.f, c = 0.f;
        for (int i = 0; i < 8; i++) { a += ws[i]; c += wq[i]; }
        ws[0] = a; wq[0] = c;
    }
    __syncthreads();
    float mean = ws[0] * (1.f / D_);
    float var  = wq[0] * (1.f / D_) - mean * mean;
    float inv  = rsqrtf(var + 1e-5f);
    int d = tid * 4;
    float4 gv = *(const float4*)(g + d);
    float4 bv = *(const float4*)(b + d);
    __half2 o0 = __floats2half2_rn((v.x - mean) * inv * gv.x + bv.x,
                                   (v.y - mean) * inv * gv.y + bv.y);
    __half2 o1 = __floats2half2_rn((v.z - mean) * inv * gv.z + bv.z,
                                   (v.w - mean) * inv * gv.w + bv.w);
    *(__half2*)(y16 + t * D_ + d)     = o0;
    *(__half2*)(y16 + t * D_ + d + 2) = o1;
}

// ---------------- fp32 -> fp16 convert --------------------------------------
__global__ void conv_f2h(const float* __restrict__ in, __half* __restrict__ out, long n) {
    long i = (long)blockIdx.x * 1024 + threadIdx.x * 4;
    if (i < n) {
        float4 v = *(const float4*)(in + i);
        *(__half2*)(out + i)     = __floats2half2_rn(v.x, v.y);
        *(__half2*)(out + i + 2) = __floats2half2_rn(v.z, v.w);
    }
}

// ---------------- batched tiled transpose -> half ---------------------------
template <typename TI>
__global__ void transpose_h(const TI* __restrict__ src, __half* __restrict__ dst,
                            int R, int C, long srcRS,
                            long sSo, long sSi, long sDo, long sDi, int nInner) {
    int zo = blockIdx.z / nInner, zi = blockIdx.z - zo * nInner;
    src += (long)zo * sSo + (long)zi * sSi;
    dst += (long)zo * sDo + (long)zi * sDi;
    __shared__ float tile[32][33];
    int r0 = blockIdx.y * 32, c0 = blockIdx.x * 32;
    int tx = threadIdx.x & 31, ty = threadIdx.x >> 5;
#pragma unroll
    for (int k = 0; k < 4; k++) {
        int r = r0 + ty + 8 * k;
        if (r < R && c0 + tx < C) tile[ty + 8 * k][tx] = (float)src[(long)r * srcRS + c0 + tx];
    }
    __syncthreads();
#pragma unroll
    for (int k = 0; k < 4; k++) {
        int c = c0 + ty + 8 * k;
        if (c < C && r0 + tx < R) dst[(long)c * R + r0 + tx] = __float2half(tile[tx][ty + 8 * k]);
    }
}

// ---------------- fused flash attention (unchanged, validated) --------------
__global__ void __launch_bounds__(256) flash_k(
    const __half* __restrict__ qkv, const __half* __restrict__ vt,
    __half* __restrict__ ctx) {
    int bh = blockIdx.y;
    int b = bh >> 4, hh = bh & 15;
    int qb = blockIdx.x;
    const __half* Qb = qkv + ((long)b * S_ + qb * 128) * (3 * D_) + hh * DH_;
    const __half* Kb = qkv + (long)b * S_ * (3 * D_) + D_ + hh * DH_;
    const __half* Vb = vt + (long)bh * DH_ * S_;

    __shared__ __align__(16) __half Qs[128 * 64];
    __shared__ __align__(16) __half Ks[2][64 * 64];
    __shared__ __align__(16) __half Vs[2][64 * 64];
    uint32_t qB = smem_u32(Qs), kB = smem_u32(Ks), vB = smem_u32(Vs);

    int tid = threadIdx.x, lane = tid & 31, warp = tid >> 5;
    int wm = warp * 16;
    int g = lane >> 2, tq = lane & 3;
    int q2 = lane >> 3, r7 = lane & 7;
    const float L2E = 1.44269504088896f;

#pragma unroll
    for (int j = 0; j < 4; j++) {
        int s = tid + 256 * j;
        int r = s >> 3, cu = s & 7;
        CP_ASYNC16(qB + qoff(r, cu), Qb + (long)r * (3 * D_) + cu * 8);
    }
    CP_COMMIT();
#pragma unroll
    for (int j = 0; j < 2; j++) {
        int s = tid + 256 * j;
        int r = s >> 3, cu = s & 7;
        CP_ASYNC16(kB + qoff(r, cu), Kb + (long)r * (3 * D_) + cu * 8);
        CP_ASYNC16(vB + qoff(r, cu), Vb + (long)r * S_ + cu * 8);
    }
    CP_COMMIT();
    CP_WAIT0();
    __syncthreads();
    {
        __half2 sc = __floats2half2_rn(0.125f, 0.125f);
        __half2* qh = (__half2*)Qs;
#pragma unroll
        for (int i = 0; i < 16; i++) qh[tid + 256 * i] = __hmul2(qh[tid + 256 * i], sc);
    }
    __syncthreads();

    float o[8][4];
#pragma unroll
    for (int ni = 0; ni < 8; ni++)
#pragma unroll
        for (int r = 0; r < 4; r++) o[ni][r] = 0.f;
    float m0 = -1e30f, m1 = -1e30f, l0 = 0.f, l1 = 0.f;

    for (int c = 0; c < 8; c++) {
        int buf = c & 1;
        if (c + 1 < 8) {
            int nb = 1 - buf;
#pragma unroll
            for (int j = 0; j < 2; j++) {
                int s = tid + 256 * j;
                int r = s >> 3, cu = s & 7;
                CP_ASYNC16(kB + nb * 8192 + qoff(r, cu),
                           Kb + (long)((c + 1) * 64 + r) * (3 * D_) + cu * 8);
                CP_ASYNC16(vB + nb * 8192 + qoff(r, cu),
                           Vb + (long)r * S_ + (c + 1) * 64 + cu * 8);
            }
            CP_COMMIT();
            CP_WAIT1();
        } else {
            CP_WAIT0();
        }
        __syncthreads();

        uint32_t kBuf = kB + buf * 8192, vBuf = vB + buf * 8192;
        float sv[8][4];
#pragma unroll
        for (int ni = 0; ni < 8; ni++)
#pragma unroll
            for (int r = 0; r < 4; r++) sv[ni][r] = 0.f;
#pragma unroll
        for (int ks = 0; ks < 4; ks++) {
            uint32_t af[4], bf[8][2];
            int am = wm + (q2 & 1) * 8 + r7;
            LDSM_X4(af[0], af[1], af[2], af[3], qB + qoff(am, 2 * ks + (q2 >> 1)));
#pragma unroll
            for (int nj = 0; nj < 4; nj++) {
                int bn = nj * 16 + (q2 >> 1) * 8 + r7;
                LDSM_X4(bf[2 * nj][0], bf[2 * nj][1], bf[2 * nj + 1][0], bf[2 * nj + 1][1],
                        kBuf + qoff(bn, 2 * ks + (q2 & 1)));
            }
#pragma unroll
            for (int ni = 0; ni < 8; ni++) mma16(sv[ni], af, bf[ni]);
        }

        float cm0 = -1e30f, cm1 = -1e30f;
#pragma unroll
        for (int ni = 0; ni < 8; ni++) {
            cm0 = fmaxf(cm0, fmaxf(sv[ni][0], sv[ni][1]));
            cm1 = fmaxf(cm1, fmaxf(sv[ni][2], sv[ni][3]));
        }
        cm0 = fmaxf(cm0, __shfl_xor_sync(0xffffffffu, cm0, 1));
        cm0 = fmaxf(cm0, __shfl_xor_sync(0xffffffffu, cm0, 2));
        cm1 = fmaxf(cm1, __shfl_xor_sync(0xffffffffu, cm1, 1));
        cm1 = fmaxf(cm1, __shfl_xor_sync(0xffffffffu, cm1, 2));
        float mn0 = fmaxf(m0, cm0), mn1 = fmaxf(m1, cm1);
        float sc0 = exp2f((m0 - mn0) * L2E), sc1 = exp2f((m1 - mn1) * L2E);
        m0 = mn0; m1 = mn1;
        l0 *= sc0; l1 *= sc1;
#pragma unroll
        for (int ni = 0; ni < 8; ni++) {
            o[ni][0] *= sc0; o[ni][1] *= sc0;
            o[ni][2] *= sc1; o[ni][3] *= sc1;
        }
        uint32_t pa[4][4];
        float rs0 = 0.f, rs1 = 0.f;
#pragma unroll
        for (int ni = 0; ni < 8; ni++) {
            float p0 = exp2f((sv[ni][0] - mn0) * L2E);
            float p1 = exp2f((sv[ni][1] - mn0) * L2E);
            float p2 = exp2f((sv[ni][2] - mn1) * L2E);
            float p3 = exp2f((sv[ni][3] - mn1) * L2E);
            rs0 += p0 + p1; rs1 += p2 + p3;
            int kk = ni >> 1, hi = ni & 1;
            pa[kk][hi * 2]     = h2_as_u32(__floats2half2_rn(p0, p1));
            pa[kk][hi * 2 + 1] = h2_as_u32(__floats2half2_rn(p2, p3));
        }
        rs0 += __shfl_xor_sync(0xffffffffu, rs0, 1);
        rs0 += __shfl_xor_sync(0xffffffffu, rs0, 2);
        rs1 += __shfl_xor_sync(0xffffffffu, rs1, 1);
        rs1 += __shfl_xor_sync(0xffffffffu, rs1, 2);
        l0 += rs0; l1 += rs1;

#pragma unroll
        for (int ks = 0; ks < 4; ks++) {
            uint32_t bf[8][2];
#pragma unroll
            for (int nj = 0; nj < 4; nj++) {
                int bn = nj * 16 + (q2 >> 1) * 8 + r7;
                LDSM_X4(bf[2 * nj][0], bf[2 * nj][1], bf[2 * nj + 1][0], bf[2 * nj + 1][1],
                        vBuf + qoff(bn, 2 * ks + (q2 & 1)));
            }
#pragma unroll
            for (int ni = 0; ni < 8; ni++) mma16(o[ni], pa[ks], bf[ni]);
        }
        __syncthreads();
    }

    float li0 = 1.f / l0, li1 = 1.f / l1;
    long row0 = (long)b * S_ + qb * 128 + wm + g;
    __half* c0p = ctx + (row0)     * D_ + hh * DH_;
    __half* c1p = ctx + (row0 + 8) * D_ + hh * DH_;
#pragma unroll
    for (int ni = 0; ni < 8; ni++) {
        int nc = ni * 8 + tq * 2;
        *(__half2*)(c0p + nc) = __floats2half2_rn(o[ni][0] * li0, o[ni][1] * li0);
        *(__half2*)(c1p + nc) = __floats2half2_rn(o[ni][2] * li1, o[ni][3] * li1);
    }
}

// ---------------- fp16 GEMM: 128x128 tile, BK=64, 3 stages, 2 CTAs/SM -------
template <bool BI, bool RE, bool HOUT>
__global__ void __launch_bounds__(256, 2) gemm_h(
    const __half* __restrict__ A, const __half* __restrict__ Bm, void* __restrict__ C,
    const float* __restrict__ bias, const float* __restrict__ resid,
    int Kd, int lda, int ldb, int ldc) {
    constexpr int STAGE = 32768, BOFF = 16384;
    extern __shared__ __align__(16) char smdyn[];
    uint32_t sb = smem_u32(smdyn);

    int tid = threadIdx.x, lane = tid & 31, warp = tid >> 5;
    int bm = blockIdx.y * 128, bn = blockIdx.x * 128;
    int wm = (warp % 4) * 32, wn = (warp / 4) * 64;
    int g = lane >> 2, tq = lane & 3;
    int q2 = lane >> 3, r7 = lane & 7;

    float acc[2][8][4];
#pragma unroll
    for (int mi = 0; mi < 2; mi++)
#pragma unroll
        for (int ni = 0; ni < 8; ni++)
#pragma unroll
            for (int r = 0; r < 4; r++) acc[mi][ni][r] = 0.f;

    int NC = Kd >> 6;
#define GH_ISSUE(st, k0)                                                              \
    do {                                                                              \
        uint32_t _as = sb + (st) * STAGE, _bs = _as + BOFF;                           \
        _Pragma("unroll")                                                             \
        for (int j = 0; j < 4; j++) {                                                 \
            int s = tid + 256 * j; int r = s >> 3, cu = s & 7;                        \
            CP_ASYNC16(_as + qoff(r, cu), A + (long)(bm + r) * lda + (k0) + cu * 8);  \
            CP_ASYNC16(_bs + qoff(r, cu), Bm + (long)(bn + r) * ldb + (k0) + cu * 8); \
        }                                                                             \
    } while (0)

    GH_ISSUE(0, 0); CP_COMMIT();
    GH_ISSUE(1, 64); CP_COMMIT();

    for (int ck = 0; ck < NC; ck++) {
        CP_WAIT1();
        __syncthreads();
        if (ck + 2 < NC) { int st = (ck + 2) % 3; GH_ISSUE(st, (ck + 2) << 6); }
        CP_COMMIT();
        uint32_t aBase = sb + (ck % 3) * STAGE, bBase = aBase + BOFF;
#pragma unroll
        for (int s = 0; s < 4; s++) {
            uint32_t af[2][4], bf[8][2];
#pragma unroll
            for (int mi = 0; mi < 2; mi++) {
                int m = wm + mi * 16 + (q2 & 1) * 8 + r7;
                LDSM_X4(af[mi][0], af[mi][1], af[mi][2], af[mi][3],
                        aBase + qoff(m, 2 * s + (q2 >> 1)));
            }
#pragma unroll
            for (int nj = 0; nj < 4; nj++) {
                int n = wn + nj * 16 + (q2 >> 1) * 8 + r7;
                LDSM_X4(bf[2 * nj][0], bf[2 * nj][1], bf[2 * nj + 1][0], bf[2 * nj + 1][1],
                        bBase + qoff(n, 2 * s + (q2 & 1)));
            }
#pragma unroll
            for (int mi = 0; mi < 2; mi++)
#pragma unroll
                for (int ni = 0; ni < 8; ni++)
                    mma16(acc[mi][ni], af[mi], bf[ni]);
        }
        __syncthreads();
    }
#undef GH_ISSUE

    __half* Ch = (__half*)C;
    float*  Cf = (float*)C;
#pragma unroll
    for (int mi = 0; mi < 2; mi++) {
#pragma unroll
        for (int rh = 0; rh < 2; rh++) {
            int row = bm + wm + mi * 16 + g + rh * 8;
#pragma unroll
            for (int ni = 0; ni < 8; ni++) {
                int n = bn + wn + ni * 8 + tq * 2;
                float v0 = acc[mi][ni][rh * 2], v1 = acc[mi][ni][rh * 2 + 1];
                if (BI) { v0 += bias[n]; v1 += bias[n + 1]; }
                if (HOUT) {
                    *(__half2*)(Ch + (long)row * ldc + n) = __floats2half2_rn(v0, v1);
                } else {
                    if (RE) {
                        float2 rv = *(const float2*)(resid + (long)row * ldc + n);
                        v0 += rv.x; v1 += rv.y;
                    }
                    float2 ov; ov.x = v0; ov.y = v1;
                    *(float2*)(Cf + (long)row * ldc + n) = ov;
                }
            }
        }
    }
}

// ---------------- MoE up: indexed-A grouped GEMM, GELU*gate epilogue --------
__global__ void __launch_bounds__(256, 2) gemm_up(
    const __half* __restrict__ Ah, const __half* __restrict__ w1t,
    __half* __restrict__ uws, const float* __restrict__ b1,
    const float* __restrict__ gd, const int* __restrict__ rowidx,
    const int* __restrict__ cnt) {
    constexpr int STAGE = 32768, BOFF = 16384;
    extern __shared__ __align__(16) char smdyn[];
    uint32_t sb = smem_u32(smdyn);

    int e = blockIdx.z;
    int c = cnt[e];
    int cp = (c + 127) & ~127;
    int bm = blockIdx.y * 128;
    if (bm >= cp) return;
    int bn = blockIdx.x * 128;

    int tid = threadIdx.x, lane = tid & 31, warp = tid >> 5;
    int wm = (warp % 4) * 32, wn = (warp / 4) * 64;
    int g = lane >> 2, tq = lane & 3;
    int q2 = lane >> 3, r7 = lane & 7;
    const __half* Bp = w1t + (long)e * (H_ * D_);
    const int* ridx = rowidx + (long)e * CAP_;

    int tokA[4];
#pragma unroll
    for (int j = 0; j < 4; j++) {
        int r = (tid + 256 * j) >> 3;
        tokA[j] = ridx[bm + r];
    }

    float acc[2][8][4];
#pragma unroll
    for (int mi = 0; mi < 2; mi++)
#pragma unroll
        for (int ni = 0; ni < 8; ni++)
#pragma unroll
            for (int r = 0; r < 4; r++) acc[mi][ni][r] = 0.f;

#define UP_ISSUE(st, k0)                                                              \
    do {                                                                              \
        uint32_t _as = sb + (st) * STAGE, _bs = _as + BOFF;                           \
        _Pragma("unroll")                                                             \
        for (int j = 0; j < 4; j++) {                                                 \
            int s = tid + 256 * j; int r = s >> 3, cu = s & 7;                        \
            CP_ASYNC16(_as + qoff(r, cu), Ah + (long)tokA[j] * D_ + (k0) + cu * 8);   \
            CP_ASYNC16(_bs + qoff(r, cu), Bp + (long)(bn + r) * D_ + (k0) + cu * 8);  \
        }                                                                             \
    } while (0)

    UP_ISSUE(0, 0); CP_COMMIT();
    UP_ISSUE(1, 64); CP_COMMIT();

    for (int ck = 0; ck < 16; ck++) {
        CP_WAIT1();
        __syncthreads();
        if (ck + 2 < 16) { int st = (ck + 2) % 3; UP_ISSUE(st, (ck + 2) << 6); }
        CP_COMMIT();
        uint32_t aBase = sb + (ck % 3) * STAGE, bBase = aBase + BOFF;
#pragma unroll
        for (int s = 0; s < 4; s++) {
            uint32_t af[2][4], bf[8][2];
#pragma unroll
            for (int mi = 0; mi < 2; mi++) {
                int m = wm + mi * 16 + (q2 & 1) * 8 + r7;
                LDSM_X4(af[mi][0], af[mi][1], af[mi][2], af[mi][3],
                        aBase + qoff(m, 2 * s + (q2 >> 1)));
            }
#pragma unroll
            for (int nj = 0; nj < 4; nj++) {
                int n = wn + nj * 16 + (q2 >> 1) * 8 + r7;
                LDSM_X4(bf[2 * nj][0], bf[2 * nj][1], bf[2 * nj + 1][0], bf[2 * nj + 1][1],
                        bBase + qoff(n, 2 * s + (q2 & 1)));
            }
#pragma unroll
            for (int mi = 0; mi < 2; mi++)
#pragma unroll
                for (int ni = 0; ni < 8; ni++)
                    mma16(acc[mi][ni], af[mi], bf[ni]);
        }
        __syncthreads();
    }
#undef UP_ISSUE

    const float* b1e = b1 + (long)e * H_;
#pragma unroll
    for (int mi = 0; mi < 2; mi++) {
#pragma unroll
        for (int rh = 0; rh < 2; rh++) {
            int row = bm + wm + mi * 16 + g + rh * 8;
            int tok = ridx[row];
            float gv = gd[(long)tok * 16 + e];
            __half* orow = uws + ((long)e * CAP_ + row) * H_;
#pragma unroll
            for (int ni = 0; ni < 8; ni++) {
                int n = bn + wn + ni * 8 + tq * 2;
                float v0 = gelu_f(acc[mi][ni][rh * 2]     + b1e[n])     * gv;
                float v1 = gelu_f(acc[mi][ni][rh * 2 + 1] + b1e[n + 1]) * gv;
                *(__half2*)(orow + n) = __floats2half2_rn(v0, v1);
            }
        }
    }
}

// ---------------- MoE down: grouped GEMM, K=256 -----------------------------
__global__ void __launch_bounds__(256, 2) gemm_dn(
    const __half* __restrict__ uws, const __half* __restrict__ w2te,
    __half* __restrict__ outs, const int* __restrict__ cnt) {
    constexpr int STAGE = 32768, BOFF = 16384;
    extern __shared__ __align__(16) char smdyn[];
    uint32_t sb = smem_u32(smdyn);

    int e = blockIdx.z;
    int c = cnt[e];
    int cp = (c + 127) & ~127;
    int bm = blockIdx.y * 128;
    if (bm >= cp) return;
    int bn = blockIdx.x * 128;

    int tid = threadIdx.x, lane = tid & 31, warp = tid >> 5;
    int wm = (warp % 4) * 32, wn = (warp / 4) * 64;
    int g = lane >> 2, tq = lane & 3;
    int q2 = lane >> 3, r7 = lane & 7;
    const __half* Ap = uws + (long)e * CAP_ * H_;
    const __half* Bp = w2te + (long)e * (D_ * H_);

    float acc[2][8][4];
#pragma unroll
    for (int mi = 0; mi < 2; mi++)
#pragma unroll
        for (int ni = 0; ni < 8; ni++)
#pragma unroll
            for (int r = 0; r < 4; r++) acc[mi][ni][r] = 0.f;

#define DN_ISSUE(st, k0)                                                              \
    do {                                                                              \
        uint32_t _as = sb + (st) * STAGE, _bs = _as + BOFF;                           \
        _Pragma("unroll")                                                             \
        for (int j = 0; j < 4; j++) {                                                 \
            int s = tid + 256 * j; int r = s >> 3, cu = s & 7;                        \
            CP_ASYNC16(_as + qoff(r, cu), Ap + (long)(bm + r) * H_ + (k0) + cu * 8);  \
            CP_ASYNC16(_bs + qoff(r, cu), Bp + (long)(bn + r) * H_ + (k0) + cu * 8);  \
        }                                                                             \
    } while (0)

    DN_ISSUE(0, 0); CP_COMMIT();
    DN_ISSUE(1, 64); CP_COMMIT();

    for (int ck = 0; ck < 4; ck++) {
        CP_WAIT1();
        __syncthreads();
        if (ck + 2 < 4) { int st = (ck + 2) % 3; DN_ISSUE(st, (ck + 2) << 6); }
        CP_COMMIT();
        uint32_t aBase = sb + (ck % 3) * STAGE, bBase = aBase + BOFF;
#pragma unroll
        for (int s = 0; s < 4; s++) {
            uint32_t af[2][4], bf[8][2];
#pragma unroll
            for (int mi = 0; mi < 2; mi++) {
                int m = wm + mi * 16 + (q2 & 1) * 8 + r7;
                LDSM_X4(af[mi][0], af[mi][1], af[mi][2], af[mi][3],
                        aBase + qoff(m, 2 * s + (q2 >> 1)));
            }
#pragma unroll
            for (int nj = 0; nj < 4; nj++) {
                int n = wn + nj * 16 + (q2 >> 1) * 8 + r7;
                LDSM_X4(bf[2 * nj][0], bf[2 * nj][1], bf[2 * nj + 1][0], bf[2 * nj + 1][1],
                        bBase + qoff(n, 2 * s + (q2 & 1)));
            }
#pragma unroll
            for (int mi = 0; mi < 2; mi++)
#pragma unroll
                for (int ni = 0; ni < 8; ni++)
                    mma16(acc[mi][ni], af[mi], bf[ni]);
        }
        __syncthreads();
    }
#undef DN_ISSUE

#pragma unroll
    for (int mi = 0; mi < 2; mi++) {
#pragma unroll
        for (int rh = 0; rh < 2; rh++) {
            int row = bm + wm + mi * 16 + g + rh * 8;
            __half* orow = outs + ((long)e * CAP_ + row) * D_;
#pragma unroll
            for (int ni = 0; ni < 8; ni++) {
                int n = bn + wn + ni * 8 + tq * 2;
                *(__half2*)(orow + n) =
                    __floats2half2_rn(acc[mi][ni][rh * 2], acc[mi][ni][rh * 2 + 1]);
            }
        }
    }
}

// ---------------- gate v2: smem-cached gate matrix, 128 tokens/block --------
__global__ void __launch_bounds__(256) gate_v2(
    const __half* __restrict__ h3, const float* __restrict__ gate_w,
    const int* __restrict__ task_id,
    float* __restrict__ probs, float* __restrict__ gate_dense) {
    extern __shared__ float gwT[];   // [16][1024]
    const float* gw = gate_w + (long)(*task_id) * (D_ * E_);
    int tid = threadIdx.x;
#pragma unroll 8
    for (int j = 0; j < 64; j++) {
        int idx = tid + 256 * j;
        int d = idx >> 4, e = idx & 15;
        gwT[e * 1024 + d] = gw[idx];
    }
    __syncthreads();
    int warp = tid >> 5, lane = tid & 31;
    for (int i = 0; i < 16; i++) {
        long tok = (long)blockIdx.x * 128 + i * 8 + warp;
        const __half* hrow = h3 + tok * D_;
        float acc[16];
#pragma unroll
        for (int e = 0; e < 16; e++) acc[e] = 0.f;
#pragma unroll
        for (int j = 0; j < 8; j++) {
            int d0 = (j * 32 + lane) * 4;
            __half2 a = *(const __half2*)(hrow + d0);
            __half2 b = *(const __half2*)(hrow + d0 + 2);
            float2 fa = __half22float2(a), fb = __half22float2(b);
#pragma unroll
            for (int e = 0; e < 16; e++) {
                float4 g4 = *(const float4*)&gwT[e * 1024 + d0];
                acc[e] += fa.x * g4.x + fa.y * g4.y + fb.x * g4.z + fb.y * g4.w;
            }
        }
#pragma unroll
        for (int e = 0; e < 16; e++) {
#pragma unroll
            for (int o = 16; o; o >>= 1)
                acc[e] += __shfl_xor_sync(0xffffffffu, acc[e], o);
        }
        if (lane == 0) {
            float mx = -1e30f;
#pragma unroll
            for (int e = 0; e < 16; e++) mx = fmaxf(mx, acc[e]);
            float sum = 0.f;
#pragma unroll
            for (int e = 0; e < 16; e++) { acc[e] = expf(acc[e] - mx); sum += acc[e]; }
            float inv = 1.f / sum;
            float p[16];
#pragma unroll
            for (int e = 0; e < 16; e++) { p[e] = acc[e] * inv; probs[tok * 16 + e] = p[e]; }
            bool used[16];
#pragma unroll
            for (int e = 0; e < 16; e++) used[e] = false;
            int tix[8]; float tvl[8]; float gsum = 0.f;
            for (int kk = 0; kk < 8; kk++) {
                float best = -1.f; int bi = 0;
                for (int e = 0; e < 16; e++)
                    if (!used[e] && p[e] > best) { best = p[e]; bi = e; }
                used[bi] = true; tix[kk] = bi; tvl[kk] = best; gsum += best;
            }
            float ginv = 1.f / (gsum + 1e-6f);
            float gdv[16];
#pragma unroll
            for (int e = 0; e < 16; e++) gdv[e] = 0.f;
            for (int kk = 0; kk < 8; kk++) gdv[tix[kk]] = tvl[kk] * ginv;
#pragma unroll
            for (int e = 0; e < 16; e++) gate_dense[tok * 16 + e] = gdv[e];
        }
    }
}

// ---------------- routing ----------------------------------------------------
__global__ void zero_cnt(int* cnt) {
    if (threadIdx.x < E_) cnt[threadIdx.x] = 0;
}
__global__ void route_k(const float* __restrict__ gd, int* __restrict__ cnt,
                        int* __restrict__ rowidx, int* __restrict__ pairpos) {
    int t = blockIdx.x * 128 + threadIdx.x;
    int k = 0;
#pragma unroll
    for (int e = 0; e < E_; e++) {
        float v = gd[(long)t * 16 + e];
        if (v > 0.f && k < 8) {
            int pos = atomicAdd(&cnt[e], 1);
            rowidx[(long)e * CAP_ + pos] = t;
            pairpos[(long)t * 8 + k] = e * CAP_ + pos;
            k++;
        }
    }
}

// ---------------- gather: 2 tokens/block ------------------------------------
__global__ void __launch_bounds__(512) gather_k(
    const float* __restrict__ x, const __half* __restrict__ outs,
    const int* __restrict__ pairpos, const float* __restrict__ gd,
    const float* __restrict__ b2, float* __restrict__ out) {
    int half_ = threadIdx.x >> 8;
    int tid = threadIdx.x & 255;
    long t = (long)blockIdx.x * 2 + half_;
    __shared__ int pp[2][8];
    __shared__ float gdv[2][16];
    if (tid < 8) pp[half_][tid] = pairpos[t * 8 + tid];
    if (tid < 16) gdv[half_][tid] = gd[t * 16 + tid];
    __syncthreads();
    int d = tid * 4;
    float4 a = *(const float4*)(x + t * D_ + d);
#pragma unroll
    for (int k = 0; k < 8; k++) {
        const __half2* o2 = (const __half2*)(outs + (long)pp[half_][k] * D_ + d);
        float2 f0 = __half22float2(o2[0]), f1 = __half22float2(o2[1]);
        a.x += f0.x; a.y += f0.y; a.z += f1.x; a.w += f1.y;
    }
#pragma unroll
    for (int e = 0; e < 16; e++) {
        float4 bv = *(const float4*)(b2 + (long)e * D_ + d);
        float gv = gdv[half_][e];
        a.x += gv * bv.x; a.y += gv * bv.y; a.z += gv * bv.z; a.w += gv * bv.w;
    }
    *(float4*)(out + t * D_ + d) = a;
}

// ---------------- aux loss: 64 deterministic partials + final ----------------
__global__ void aux_part(const float* __restrict__ probs, float* __restrict__ part) {
    int b = blockIdx.x, tid = threadIdx.x;
    const float* p = probs + ((long)b * 256 + tid) * 16;
    float v[16];
#pragma unroll
    for (int e = 0; e < 16; e++) v[e] = p[e];
    __shared__ float red[256][17];
#pragma unroll
    for (int e = 0; e < 16; e++) red[tid][e] = v[e];
    __syncthreads();
    for (int s = 128; s; s >>= 1) {
        if (tid < s) {
#pragma unroll
            for (int e = 0; e < 16; e++) red[tid][e] += red[tid + s][e];
        }
        __syncthreads();
    }
    if (tid == 0) {
#pragma unroll
        for (int e = 0; e < 16; e++) part[b * 16 + e] = red[0][e];
    }
}
__global__ void aux_fin(const float* __restrict__ part, float* __restrict__ outv) {
    if (threadIdx.x == 0) {
        float aux = 0.f;
        for (int e = 0; e < 16; e++) {
            float s = 0.f;
            for (int b = 0; b < 64; b++) s += part[b * 16 + e];
            float mp = s * (1.f / T_);
            aux += mp * logf(mp + 1e-6f);
        }
        outv[0] = 5e-4f * aux;
    }
}

// ---------------- launch -----------------------------------------------------
extern "C" void kernel_launch(void* const* d_in, const int* in_sizes, int n_in,
                              void* d_out, int out_size) {
    const float* tgt        = (const float*)d_in[0];
    const float* ln1_g      = (const float*)d_in[2];
    const float* ln1_b      = (const float*)d_in[3];
    const float* ln3_g      = (const float*)d_in[4];
    const float* ln3_b      = (const float*)d_in[5];
    const float* in_proj_w  = (const float*)d_in[6];
    const float* in_proj_b  = (const float*)d_in[7];
    const float* out_proj_w = (const float*)d_in[8];
    const float* out_proj_b = (const float*)d_in[9];
    const float* gate_w     = (const float*)d_in[10];
    const float* w1         = (const float*)d_in[11];
    const float* b1         = (const float*)d_in[12];
    const float* w2         = (const float*)d_in[13];
    const float* b2         = (const float*)d_in[14];
    const int*   task_id    = (const int*)d_in[15];

    float* out       = (float*)d_out;
    float* out_x     = out;
    float* out_aux   = out + (size_t)T_ * D_;
    float* out_probs = out_aux + 1;

    __half *h16, *qkv16, *vt16, *ctx16, *wi16, *wo16, *w1t16, *w2te16, *uws, *outs;
    float *x, *gd, *auxp;
    int *cnt, *rowidx, *pairpos;
    cudaGetSymbolAddress((void**)&h16,    g_h16);
    cudaGetSymbolAddress((void**)&qkv16,  g_qkv16);
    cudaGetSymbolAddress((void**)&vt16,   g_vt16);
    cudaGetSymbolAddress((void**)&ctx16,  g_ctx16);
    cudaGetSymbolAddress((void**)&x,      g_x);
    cudaGetSymbolAddress((void**)&gd,     g_gate);
    cudaGetSymbolAddress((void**)&wi16,   g_wi16);
    cudaGetSymbolAddress((void**)&wo16,   g_wo16);
    cudaGetSymbolAddress((void**)&w1t16,  g_w1t16);
    cudaGetSymbolAddress((void**)&w2te16, g_w2te16);
    cudaGetSymbolAddress((void**)&uws,    g_uws);
    cudaGetSymbolAddress((void**)&outs,   g_outs);
    cudaGetSymbolAddress((void**)&cnt,    g_cnt);
    cudaGetSymbolAddress((void**)&rowidx, g_rowidx);
    cudaGetSymbolAddress((void**)&pairpos,g_pairpos);
    cudaGetSymbolAddress((void**)&auxp,   g_auxp);

    const int GSM = 3 * 32768;      // 98304
    const int GATESM = 65536;
    cudaFuncSetAttribute(gemm_h<true, false, true >, cudaFuncAttributeMaxDynamicSharedMemorySize, GSM);
    cudaFuncSetAttribute(gemm_h<true, true,  false>, cudaFuncAttributeMaxDynamicSharedMemorySize, GSM);
    cudaFuncSetAttribute(gemm_up, cudaFuncAttributeMaxDynamicSharedMemorySize, GSM);
    cudaFuncSetAttribute(gemm_dn, cudaFuncAttributeMaxDynamicSharedMemorySize, GSM);
    cudaFuncSetAttribute(gate_v2, cudaFuncAttributeMaxDynamicSharedMemorySize, GATESM);

    // 0. weight preprocessing
    conv_f2h<<<(unsigned)(3L * D_ * D_ / 1024), 256>>>(in_proj_w, wi16, 3L * D_ * D_);
    conv_f2h<<<(unsigned)(1L * D_ * D_ / 1024), 256>>>(out_proj_w, wo16, 1L * D_ * D_);
    transpose_h<float><<<dim3(8, 32, E_), 256>>>(
        w1, w1t16, D_, H_, H_, (long)D_ * H_, 0, (long)H_ * D_, 0, 1);
    transpose_h<float><<<dim3(32, 8, E_), 256>>>(
        w2, w2te16, H_, D_, D_, (long)H_ * D_, 0, (long)D_ * H_, 0, 1);

    // 1. h = LN1(tgt)
    ln_kernel<<<T_, 256>>>(tgt, ln1_g, ln1_b, h16);

    // 2. qkv = h @ in_proj_w^T + b (half out)
    gemm_h<true, false, true><<<dim3(24, 128), 256, GSM>>>(
        h16, wi16, qkv16, in_proj_b, nullptr, D_, D_, D_, 3 * D_);

    // 3. Vt = V^T per (b,h)
    transpose_h<__half><<<dim3(2, 16, B_ * NH_), 256>>>(
        qkv16 + 2 * D_, vt16, S_, DH_, 3 * D_,
        (long)S_ * 3 * D_, DH_, (long)NH_ * DH_ * S_, (long)DH_ * S_, NH_);

    // 4. fused flash attention -> ctx16
    flash_k<<<dim3(4, B_ * NH_), 256>>>(qkv16, vt16, ctx16);

    // 5. x = tgt + ctx @ out_proj_w^T + b (fp32 out)
    gemm_h<true, true, false><<<dim3(8, 128), 256, GSM>>>(
        ctx16, wo16, x, out_proj_b, tgt, D_, D_, D_, D_);

    // 6. h3 = LN3(x)
    ln_kernel<<<T_, 256>>>(x, ln3_g, ln3_b, h16);

    // 7. gate / aux
    gate_v2<<<T_ / 128, 256, GATESM>>>(h16, gate_w, task_id, out_probs, gd);
    aux_part<<<64, 256>>>(out_probs, auxp);
    aux_fin<<<1, 32>>>(auxp, out_aux);

    // 8. routing
    zero_cnt<<<1, 32>>>(cnt);
    route_k<<<T_ / 128, 128>>>(gd, cnt, rowidx, pairpos);

    // 9. sparse MoE up
    gemm_up<<<dim3(2, 128, E_), 256, GSM>>>(h16, w1t16, uws, b1, gd, rowidx, cnt);

    // 10. sparse MoE down
    gemm_dn<<<dim3(8, 128, E_), 256, GSM>>>(uws, w2te16, outs, cnt);

    // 11. gather: out = x + sum_k outs + gd @ b2
    gather_k<<<T_ / 2, 512>>>(x, outs, pairpos, gd, b2, out_x);

    (void)in_sizes; (void)n_in; (void)out_size;
}

// round 12
// speedup vs baseline: 1.0510x; 1.0125x over previous
#include <cuda_runtime.h>
#include <cuda_fp16.h>
#include <math.h>
#include <stdint.h>

#define B_   32
#define S_   512
#define D_   1024
#define NH_  16
#define E_   16
#define H_   256
#define DH_  64
#define T_   (B_ * S_)          // 16384
#define CAP_ 16384

// ---------------- scratch (static device memory) ---------------------------
__device__ __half g_h16[(size_t)T_ * D_];
__device__ __half g_qkv16[(size_t)T_ * 3 * D_];
__device__ __half g_vt16[(size_t)B_ * NH_ * DH_ * S_];
__device__ __half g_ctx16[(size_t)T_ * D_];
__device__ float  g_x[(size_t)T_ * D_];
__device__ float  g_gate[(size_t)T_ * E_];
__device__ __half g_wi16[(size_t)3 * D_ * D_];
__device__ __half g_wo16[(size_t)D_ * D_];
__device__ __half g_w1t16[(size_t)E_ * H_ * D_];
__device__ __half g_w2te16[(size_t)E_ * D_ * H_];
__device__ __half g_uws[(size_t)E_ * CAP_ * H_];
__device__ __half g_outs[(size_t)E_ * CAP_ * D_];
__device__ int    g_cnt[E_];
__device__ int    g_rowidx[(size_t)E_ * CAP_];
__device__ int    g_pairpos[(size_t)T_ * 8];
__device__ float  g_auxp[64 * E_];

// ---------------- helpers ---------------------------------------------------
__device__ __forceinline__ uint32_t smem_u32(const void* p) {
    uint32_t a;
    asm("{ .reg .u64 t; cvta.to.shared.u64 t, %1; cvt.u32.u64 %0, t; }" : "=r"(a) : "l"(p));
    return a;
}
__device__ __forceinline__ uint32_t h2_as_u32(__half2 h) {
    return *reinterpret_cast<uint32_t*>(&h);
}
#define CP_ASYNC16(dst, src) \
    asm volatile("cp.async.ca.shared.global [%0], [%1], 16;" :: "r"(dst), "l"(src) : "memory")
#define CP_COMMIT() asm volatile("cp.async.commit_group;" ::: "memory")
#define CP_WAIT1()  asm volatile("cp.async.wait_group 1;" ::: "memory")
#define CP_WAIT0()  asm volatile("cp.async.wait_group 0;" ::: "memory")

#define LDSM_X4(r0, r1, r2, r3, addr) \
    asm volatile("ldmatrix.sync.aligned.m8n8.x4.shared.b16 {%0,%1,%2,%3}, [%4];" \
        : "=r"(r0), "=r"(r1), "=r"(r2), "=r"(r3) : "r"(addr))

__device__ __forceinline__ void mma16(float* d, const uint32_t* a, const uint32_t* b) {
    asm volatile(
        "mma.sync.aligned.m16n8k16.row.col.f32.f16.f16.f32 "
        "{%0,%1,%2,%3},{%4,%5,%6,%7},{%8,%9},{%0,%1,%2,%3};"
        : "+f"(d[0]), "+f"(d[1]), "+f"(d[2]), "+f"(d[3])
        : "r"(a[0]), "r"(a[1]), "r"(a[2]), "r"(a[3]), "r"(b[0]), "r"(b[1]));
}

// smem tile: 64 halfs (128B) per row, SW128
__device__ __forceinline__ uint32_t qoff(int m, int c) {
    return (uint32_t)(m * 128 + ((c ^ (m & 7)) << 4));
}
__device__ __forceinline__ float gelu_f(float v) {
    return 0.5f * v * (1.f + erff(v * 0.70710678118654752f));
}

// ---------------- LayerNorm (fp32 in -> half out), float4 loads -------------
__global__ void ln_kernel(const float* __restrict__ x, const float* __restrict__ g,
                          const float* __restrict__ b, __half* __restrict__ y16) {
    long t = blockIdx.x;
    const float* row = x + t * D_;
    int tid = threadIdx.x;
    float4 v = *(const float4*)(row + tid * 4);
    float s = v.x + v.y + v.z + v.w;
    float sq = v.x * v.x + v.y * v.y + v.z * v.z + v.w * v.w;
#pragma unroll
    for (int o = 16; o; o >>= 1) {
        s  += __shfl_xor_sync(0xffffffffu, s, o);
        sq += __shfl_xor_sync(0xffffffffu, sq, o);
    }
    __shared__ float ws[8], wq[8];
    int w = tid >> 5, l = tid & 31;
    if (l == 0) { ws[w] = s; wq[w] = sq; }
    __syncthreads();
    if (tid == 0) {
        float a = 0.f, c = 0.f;
        for (int i = 0; i < 8; i++) { a += ws[i]; c += wq[i]; }
        ws[0] = a; wq[0] = c;
    }
    __syncthreads();
    float mean = ws[0] * (1.f / D_);
    float var  = wq[0] * (1.f / D_) - mean * mean;
    float inv  = rsqrtf(var + 1e-5f);
    int d = tid * 4;
    float4 gv = *(const float4*)(g + d);
    float4 bv = *(const float4*)(b + d);
    __half2 o0 = __floats2half2_rn((v.x - mean) * inv * gv.x + bv.x,
                                   (v.y - mean) * inv * gv.y + bv.y);
    __half2 o1 = __floats2half2_rn((v.z - mean) * inv * gv.z + bv.z,
                                   (v.w - mean) * inv * gv.w + bv.w);
    *(__half2*)(y16 + t * D_ + d)     = o0;
    *(__half2*)(y16 + t * D_ + d + 2) = o1;
}

// ---------------- fp32 -> fp16 convert --------------------------------------
__global__ void conv_f2h(const float* __restrict__ in, __half* __restrict__ out, long n) {
    long i = (long)blockIdx.x * 1024 + threadIdx.x * 4;
    if (i < n) {
        float4 v = *(const float4*)(in + i);
        *(__half2*)(out + i)     = __floats2half2_rn(v.x, v.y);
        *(__half2*)(out + i + 2) = __floats2half2_rn(v.z, v.w);
    }
}

// ---------------- batched tiled transpose -> half ---------------------------
template <typename TI>
__global__ void transpose_h(const TI* __restrict__ src, __half* __restrict__ dst,
                            int R, int C, long srcRS,
                            long sSo, long sSi, long sDo, long sDi, int nInner) {
    int zo = blockIdx.z / nInner, zi = blockIdx.z - zo * nInner;
    src += (long)zo * sSo + (long)zi * sSi;
    dst += (long)zo * sDo + (long)zi * sDi;
    __shared__ float tile[32][33];
    int r0 = blockIdx.y * 32, c0 = blockIdx.x * 32;
    int tx = threadIdx.x & 31, ty = threadIdx.x >> 5;
#pragma unroll
    for (int k = 0; k < 4; k++) {
        int r = r0 + ty + 8 * k;
        if (r < R && c0 + tx < C) tile[ty + 8 * k][tx] = (float)src[(long)r * srcRS + c0 + tx];
    }
    __syncthreads();
#pragma unroll
    for (int k = 0; k < 4; k++) {
        int c = c0 + ty + 8 * k;
        if (c < C && r0 + tx < R) dst[(long)c * R + r0 + tx] = __float2half(tile[tx][ty + 8 * k]);
    }
}

// ---------------- fused flash attention (unchanged, validated) --------------
__global__ void __launch_bounds__(256) flash_k(
    const __half* __restrict__ qkv, const __half* __restrict__ vt,
    __half* __restrict__ ctx) {
    int bh = blockIdx.y;
    int b = bh >> 4, hh = bh & 15;
    int qb = blockIdx.x;
    const __half* Qb = qkv + ((long)b * S_ + qb * 128) * (3 * D_) + hh * DH_;
    const __half* Kb = qkv + (long)b * S_ * (3 * D_) + D_ + hh * DH_;
    const __half* Vb = vt + (long)bh * DH_ * S_;

    __shared__ __align__(16) __half Qs[128 * 64];
    __shared__ __align__(16) __half Ks[2][64 * 64];
    __shared__ __align__(16) __half Vs[2][64 * 64];
    uint32_t qB = smem_u32(Qs), kB = smem_u32(Ks), vB = smem_u32(Vs);

    int tid = threadIdx.x, lane = tid & 31, warp = tid >> 5;
    int wm = warp * 16;
    int g = lane >> 2, tq = lane & 3;
    int q2 = lane >> 3, r7 = lane & 7;
    const float L2E = 1.44269504088896f;

#pragma unroll
    for (int j = 0; j < 4; j++) {
        int s = tid + 256 * j;
        int r = s >> 3, cu = s & 7;
        CP_ASYNC16(qB + qoff(r, cu), Qb + (long)r * (3 * D_) + cu * 8);
    }
    CP_COMMIT();
#pragma unroll
    for (int j = 0; j < 2; j++) {
        int s = tid + 256 * j;
        int r = s >> 3, cu = s & 7;
        CP_ASYNC16(kB + qoff(r, cu), Kb + (long)r * (3 * D_) + cu * 8);
        CP_ASYNC16(vB + qoff(r, cu), Vb + (long)r * S_ + cu * 8);
    }
    CP_COMMIT();
    CP_WAIT0();
    __syncthreads();
    {
        __half2 sc = __floats2half2_rn(0.125f, 0.125f);
        __half2* qh = (__half2*)Qs;
#pragma unroll
        for (int i = 0; i < 16; i++) qh[tid + 256 * i] = __hmul2(qh[tid + 256 * i], sc);
    }
    __syncthreads();

    float o[8][4];
#pragma unroll
    for (int ni = 0; ni < 8; ni++)
#pragma unroll
        for (int r = 0; r < 4; r++) o[ni][r] = 0.f;
    float m0 = -1e30f, m1 = -1e30f, l0 = 0.f, l1 = 0.f;

    for (int c = 0; c < 8; c++) {
        int buf = c & 1;
        if (c + 1 < 8) {
            int nb = 1 - buf;
#pragma unroll
            for (int j = 0; j < 2; j++) {
                int s = tid + 256 * j;
                int r = s >> 3, cu = s & 7;
                CP_ASYNC16(kB + nb * 8192 + qoff(r, cu),
                           Kb + (long)((c + 1) * 64 + r) * (3 * D_) + cu * 8);
                CP_ASYNC16(vB + nb * 8192 + qoff(r, cu),
                           Vb + (long)r * S_ + (c + 1) * 64 + cu * 8);
            }
            CP_COMMIT();
            CP_WAIT1();
        } else {
            CP_WAIT0();
        }
        __syncthreads();

        uint32_t kBuf = kB + buf * 8192, vBuf = vB + buf * 8192;
        float sv[8][4];
#pragma unroll
        for (int ni = 0; ni < 8; ni++)
#pragma unroll
            for (int r = 0; r < 4; r++) sv[ni][r] = 0.f;
#pragma unroll
        for (int ks = 0; ks < 4; ks++) {
            uint32_t af[4], bf[8][2];
            int am = wm + (q2 & 1) * 8 + r7;
            LDSM_X4(af[0], af[1], af[2], af[3], qB + qoff(am, 2 * ks + (q2 >> 1)));
#pragma unroll
            for (int nj = 0; nj < 4; nj++) {
                int bn = nj * 16 + (q2 >> 1) * 8 + r7;
                LDSM_X4(bf[2 * nj][0], bf[2 * nj][1], bf[2 * nj + 1][0], bf[2 * nj + 1][1],
                        kBuf + qoff(bn, 2 * ks + (q2 & 1)));
            }
#pragma unroll
            for (int ni = 0; ni < 8; ni++) mma16(sv[ni], af, bf[ni]);
        }

        float cm0 = -1e30f, cm1 = -1e30f;
#pragma unroll
        for (int ni = 0; ni < 8; ni++) {
            cm0 = fmaxf(cm0, fmaxf(sv[ni][0], sv[ni][1]));
            cm1 = fmaxf(cm1, fmaxf(sv[ni][2], sv[ni][3]));
        }
        cm0 = fmaxf(cm0, __shfl_xor_sync(0xffffffffu, cm0, 1));
        cm0 = fmaxf(cm0, __shfl_xor_sync(0xffffffffu, cm0, 2));
        cm1 = fmaxf(cm1, __shfl_xor_sync(0xffffffffu, cm1, 1));
        cm1 = fmaxf(cm1, __shfl_xor_sync(0xffffffffu, cm1, 2));
        float mn0 = fmaxf(m0, cm0), mn1 = fmaxf(m1, cm1);
        float sc0 = exp2f((m0 - mn0) * L2E), sc1 = exp2f((m1 - mn1) * L2E);
        m0 = mn0; m1 = mn1;
        l0 *= sc0; l1 *= sc1;
#pragma unroll
        for (int ni = 0; ni < 8; ni++) {
            o[ni][0] *= sc0; o[ni][1] *= sc0;
            o[ni][2] *= sc1; o[ni][3] *= sc1;
        }
        uint32_t pa[4][4];
        float rs0 = 0.f, rs1 = 0.f;
#pragma unroll
        for (int ni = 0; ni < 8; ni++) {
            float p0 = exp2f((sv[ni][0] - mn0) * L2E);
            float p1 = exp2f((sv[ni][1] - mn0) * L2E);
            float p2 = exp2f((sv[ni][2] - mn1) * L2E);
            float p3 = exp2f((sv[ni][3] - mn1) * L2E);
            rs0 += p0 + p1; rs1 += p2 + p3;
            int kk = ni >> 1, hi = ni & 1;
            pa[kk][hi * 2]     = h2_as_u32(__floats2half2_rn(p0, p1));
            pa[kk][hi * 2 + 1] = h2_as_u32(__floats2half2_rn(p2, p3));
        }
        rs0 += __shfl_xor_sync(0xffffffffu, rs0, 1);
        rs0 += __shfl_xor_sync(0xffffffffu, rs0, 2);
        rs1 += __shfl_xor_sync(0xffffffffu, rs1, 1);
        rs1 += __shfl_xor_sync(0xffffffffu, rs1, 2);
        l0 += rs0; l1 += rs1;

#pragma unroll
        for (int ks = 0; ks < 4; ks++) {
            uint32_t bf[8][2];
#pragma unroll
            for (int nj = 0; nj < 4; nj++) {
                int bn = nj * 16 + (q2 >> 1) * 8 + r7;
                LDSM_X4(bf[2 * nj][0], bf[2 * nj][1], bf[2 * nj + 1][0], bf[2 * nj + 1][1],
                        vBuf + qoff(bn, 2 * ks + (q2 & 1)));
            }
#pragma unroll
            for (int ni = 0; ni < 8; ni++) mma16(o[ni], pa[ks], bf[ni]);
        }
        __syncthreads();   // load-bearing: refill is issued BEFORE the wait here
    }

    float li0 = 1.f / l0, li1 = 1.f / l1;
    long row0 = (long)b * S_ + qb * 128 + wm + g;
    __half* c0p = ctx + (row0)     * D_ + hh * DH_;
    __half* c1p = ctx + (row0 + 8) * D_ + hh * DH_;
#pragma unroll
    for (int ni = 0; ni < 8; ni++) {
        int nc = ni * 8 + tq * 2;
        *(__half2*)(c0p + nc) = __floats2half2_rn(o[ni][0] * li0, o[ni][1] * li0);
        *(__half2*)(c1p + nc) = __floats2half2_rn(o[ni][2] * li1, o[ni][3] * li1);
    }
}

// ---------------- fp16 GEMM: 128x128 tile, BK=64, 3 stages, 2 CTAs/SM -------
// One __syncthreads per chunk: the top sync of iter ck also protects the
// refill target stage (ck+2)%3 == (ck-1)%3 (last read in iter ck-1).
template <bool BI, bool RE, bool HOUT>
__global__ void __launch_bounds__(256, 2) gemm_h(
    const __half* __restrict__ A, const __half* __restrict__ Bm, void* __restrict__ C,
    const float* __restrict__ bias, const float* __restrict__ resid,
    int Kd, int lda, int ldb, int ldc) {
    constexpr int STAGE = 32768, BOFF = 16384;
    extern __shared__ __align__(16) char smdyn[];
    uint32_t sb = smem_u32(smdyn);

    int tid = threadIdx.x, lane = tid & 31, warp = tid >> 5;
    int bm = blockIdx.y * 128, bn = blockIdx.x * 128;
    int wm = (warp % 4) * 32, wn = (warp / 4) * 64;
    int g = lane >> 2, tq = lane & 3;
    int q2 = lane >> 3, r7 = lane & 7;

    float acc[2][8][4];
#pragma unroll
    for (int mi = 0; mi < 2; mi++)
#pragma unroll
        for (int ni = 0; ni < 8; ni++)
#pragma unroll
            for (int r = 0; r < 4; r++) acc[mi][ni][r] = 0.f;

    int NC = Kd >> 6;
#define GH_ISSUE(st, k0)                                                              \
    do {                                                                              \
        uint32_t _as = sb + (st) * STAGE, _bs = _as + BOFF;                           \
        _Pragma("unroll")                                                             \
        for (int j = 0; j < 4; j++) {                                                 \
            int s = tid + 256 * j; int r = s >> 3, cu = s & 7;                        \
            CP_ASYNC16(_as + qoff(r, cu), A + (long)(bm + r) * lda + (k0) + cu * 8);  \
            CP_ASYNC16(_bs + qoff(r, cu), Bm + (long)(bn + r) * ldb + (k0) + cu * 8); \
        }                                                                             \
    } while (0)

    GH_ISSUE(0, 0); CP_COMMIT();
    GH_ISSUE(1, 64); CP_COMMIT();

    for (int ck = 0; ck < NC; ck++) {
        CP_WAIT1();
        __syncthreads();
        if (ck + 2 < NC) { int st = (ck + 2) % 3; GH_ISSUE(st, (ck + 2) << 6); }
        CP_COMMIT();
        uint32_t aBase = sb + (ck % 3) * STAGE, bBase = aBase + BOFF;
#pragma unroll
        for (int s = 0; s < 4; s++) {
            uint32_t af[2][4], bf[8][2];
#pragma unroll
            for (int mi = 0; mi < 2; mi++) {
                int m = wm + mi * 16 + (q2 & 1) * 8 + r7;
                LDSM_X4(af[mi][0], af[mi][1], af[mi][2], af[mi][3],
                        aBase + qoff(m, 2 * s + (q2 >> 1)));
            }
#pragma unroll
            for (int nj = 0; nj < 4; nj++) {
                int n = wn + nj * 16 + (q2 >> 1) * 8 + r7;
                LDSM_X4(bf[2 * nj][0], bf[2 * nj][1], bf[2 * nj + 1][0], bf[2 * nj + 1][1],
                        bBase + qoff(n, 2 * s + (q2 & 1)));
            }
#pragma unroll
            for (int mi = 0; mi < 2; mi++)
#pragma unroll
                for (int ni = 0; ni < 8; ni++)
                    mma16(acc[mi][ni], af[mi], bf[ni]);
        }
        // no tail sync: next iteration's top sync protects the stage rotation
    }
#undef GH_ISSUE

    __half* Ch = (__half*)C;
    float*  Cf = (float*)C;
#pragma unroll
    for (int mi = 0; mi < 2; mi++) {
#pragma unroll
        for (int rh = 0; rh < 2; rh++) {
            int row = bm + wm + mi * 16 + g + rh * 8;
#pragma unroll
            for (int ni = 0; ni < 8; ni++) {
                int n = bn + wn + ni * 8 + tq * 2;
                float v0 = acc[mi][ni][rh * 2], v1 = acc[mi][ni][rh * 2 + 1];
                if (BI) { v0 += bias[n]; v1 += bias[n + 1]; }
                if (HOUT) {
                    *(__half2*)(Ch + (long)row * ldc + n) = __floats2half2_rn(v0, v1);
                } else {
                    if (RE) {
                        float2 rv = *(const float2*)(resid + (long)row * ldc + n);
                        v0 += rv.x; v1 += rv.y;
                    }
                    float2 ov; ov.x = v0; ov.y = v1;
                    *(float2*)(Cf + (long)row * ldc + n) = ov;
                }
            }
        }
    }
}

// ---------------- MoE up: indexed-A grouped GEMM, GELU*gate epilogue --------
__global__ void __launch_bounds__(256, 2) gemm_up(
    const __half* __restrict__ Ah, const __half* __restrict__ w1t,
    __half* __restrict__ uws, const float* __restrict__ b1,
    const float* __restrict__ gd, const int* __restrict__ rowidx,
    const int* __restrict__ cnt) {
    constexpr int STAGE = 32768, BOFF = 16384;
    extern __shared__ __align__(16) char smdyn[];
    uint32_t sb = smem_u32(smdyn);

    int e = blockIdx.z;
    int c = cnt[e];
    int cp = (c + 127) & ~127;
    int bm = blockIdx.y * 128;
    if (bm >= cp) return;
    int bn = blockIdx.x * 128;

    int tid = threadIdx.x, lane = tid & 31, warp = tid >> 5;
    int wm = (warp % 4) * 32, wn = (warp / 4) * 64;
    int g = lane >> 2, tq = lane & 3;
    int q2 = lane >> 3, r7 = lane & 7;
    const __half* Bp = w1t + (long)e * (H_ * D_);
    const int* ridx = rowidx + (long)e * CAP_;

    int tokA[4];
#pragma unroll
    for (int j = 0; j < 4; j++) {
        int r = (tid + 256 * j) >> 3;
        tokA[j] = ridx[bm + r];
    }

    float acc[2][8][4];
#pragma unroll
    for (int mi = 0; mi < 2; mi++)
#pragma unroll
        for (int ni = 0; ni < 8; ni++)
#pragma unroll
            for (int r = 0; r < 4; r++) acc[mi][ni][r] = 0.f;

#define UP_ISSUE(st, k0)                                                              \
    do {                                                                              \
        uint32_t _as = sb + (st) * STAGE, _bs = _as + BOFF;                           \
        _Pragma("unroll")                                                             \
        for (int j = 0; j < 4; j++) {                                                 \
            int s = tid + 256 * j; int r = s >> 3, cu = s & 7;                        \
            CP_ASYNC16(_as + qoff(r, cu), Ah + (long)tokA[j] * D_ + (k0) + cu * 8);   \
            CP_ASYNC16(_bs + qoff(r, cu), Bp + (long)(bn + r) * D_ + (k0) + cu * 8);  \
        }                                                                             \
    } while (0)

    UP_ISSUE(0, 0); CP_COMMIT();
    UP_ISSUE(1, 64); CP_COMMIT();

    for (int ck = 0; ck < 16; ck++) {
        CP_WAIT1();
        __syncthreads();
        if (ck + 2 < 16) { int st = (ck + 2) % 3; UP_ISSUE(st, (ck + 2) << 6); }
        CP_COMMIT();
        uint32_t aBase = sb + (ck % 3) * STAGE, bBase = aBase + BOFF;
#pragma unroll
        for (int s = 0; s < 4; s++) {
            uint32_t af[2][4], bf[8][2];
#pragma unroll
            for (int mi = 0; mi < 2; mi++) {
                int m = wm + mi * 16 + (q2 & 1) * 8 + r7;
                LDSM_X4(af[mi][0], af[mi][1], af[mi][2], af[mi][3],
                        aBase + qoff(m, 2 * s + (q2 >> 1)));
            }
#pragma unroll
            for (int nj = 0; nj < 4; nj++) {
                int n = wn + nj * 16 + (q2 >> 1) * 8 + r7;
                LDSM_X4(bf[2 * nj][0], bf[2 * nj][1], bf[2 * nj + 1][0], bf[2 * nj + 1][1],
                        bBase + qoff(n, 2 * s + (q2 & 1)));
            }
#pragma unroll
            for (int mi = 0; mi < 2; mi++)
#pragma unroll
                for (int ni = 0; ni < 8; ni++)
                    mma16(acc[mi][ni], af[mi], bf[ni]);
        }
        // no tail sync (see gemm_h)
    }
#undef UP_ISSUE

    const float* b1e = b1 + (long)e * H_;
#pragma unroll
    for (int mi = 0; mi < 2; mi++) {
#pragma unroll
        for (int rh = 0; rh < 2; rh++) {
            int row = bm + wm + mi * 16 + g + rh * 8;
            int tok = ridx[row];
            float gv = gd[(long)tok * 16 + e];
            __half* orow = uws + ((long)e * CAP_ + row) * H_;
#pragma unroll
            for (int ni = 0; ni < 8; ni++) {
                int n = bn + wn + ni * 8 + tq * 2;
                float v0 = gelu_f(acc[mi][ni][rh * 2]     + b1e[n])     * gv;
                float v1 = gelu_f(acc[mi][ni][rh * 2 + 1] + b1e[n + 1]) * gv;
                *(__half2*)(orow + n) = __floats2half2_rn(v0, v1);
            }
        }
    }
}

// ---------------- MoE down: grouped GEMM, K=256 -----------------------------
__global__ void __launch_bounds__(256, 2) gemm_dn(
    const __half* __restrict__ uws, const __half* __restrict__ w2te,
    __half* __restrict__ outs, const int* __restrict__ cnt) {
    constexpr int STAGE = 32768, BOFF = 16384;
    extern __shared__ __align__(16) char smdyn[];
    uint32_t sb = smem_u32(smdyn);

    int e = blockIdx.z;
    int c = cnt[e];
    int cp = (c + 127) & ~127;
    int bm = blockIdx.y * 128;
    if (bm >= cp) return;
    int bn = blockIdx.x * 128;

    int tid = threadIdx.x, lane = tid & 31, warp = tid >> 5;
    int wm = (warp % 4) * 32, wn = (warp / 4) * 64;
    int g = lane >> 2, tq = lane & 3;
    int q2 = lane >> 3, r7 = lane & 7;
    const __half* Ap = uws + (long)e * CAP_ * H_;
    const __half* Bp = w2te + (long)e * (D_ * H_);

    float acc[2][8][4];
#pragma unroll
    for (int mi = 0; mi < 2; mi++)
#pragma unroll
        for (int ni = 0; ni < 8; ni++)
#pragma unroll
            for (int r = 0; r < 4; r++) acc[mi][ni][r] = 0.f;

#define DN_ISSUE(st, k0)                                                              \
    do {                                                                              \
        uint32_t _as = sb + (st) * STAGE, _bs = _as + BOFF;                           \
        _Pragma("unroll")                                                             \
        for (int j = 0; j < 4; j++) {                                                 \
            int s = tid + 256 * j; int r = s >> 3, cu = s & 7;                        \
            CP_ASYNC16(_as + qoff(r, cu), Ap + (long)(bm + r) * H_ + (k0) + cu * 8);  \
            CP_ASYNC16(_bs + qoff(r, cu), Bp + (long)(bn + r) * H_ + (k0) + cu * 8);  \
        }                                                                             \
    } while (0)

    DN_ISSUE(0, 0); CP_COMMIT();
    DN_ISSUE(1, 64); CP_COMMIT();

    for (int ck = 0; ck < 4; ck++) {
        CP_WAIT1();
        __syncthreads();
        if (ck + 2 < 4) { int st = (ck + 2) % 3; DN_ISSUE(st, (ck + 2) << 6); }
        CP_COMMIT();
        uint32_t aBase = sb + (ck % 3) * STAGE, bBase = aBase + BOFF;
#pragma unroll
        for (int s = 0; s < 4; s++) {
            uint32_t af[2][4], bf[8][2];
#pragma unroll
            for (int mi = 0; mi < 2; mi++) {
                int m = wm + mi * 16 + (q2 & 1) * 8 + r7;
                LDSM_X4(af[mi][0], af[mi][1], af[mi][2], af[mi][3],
                        aBase + qoff(m, 2 * s + (q2 >> 1)));
            }
#pragma unroll
            for (int nj = 0; nj < 4; nj++) {
                int n = wn + nj * 16 + (q2 >> 1) * 8 + r7;
                LDSM_X4(bf[2 * nj][0], bf[2 * nj][1], bf[2 * nj + 1][0], bf[2 * nj + 1][1],
                        bBase + qoff(n, 2 * s + (q2 & 1)));
            }
#pragma unroll
            for (int mi = 0; mi < 2; mi++)
#pragma unroll
                for (int ni = 0; ni < 8; ni++)
                    mma16(acc[mi][ni], af[mi], bf[ni]);
        }
        // no tail sync (see gemm_h)
    }
#undef DN_ISSUE

#pragma unroll
    for (int mi = 0; mi < 2; mi++) {
#pragma unroll
        for (int rh = 0; rh < 2; rh++) {
            int row = bm + wm + mi * 16 + g + rh * 8;
            __half* orow = outs + ((long)e * CAP_ + row) * D_;
#pragma unroll
            for (int ni = 0; ni < 8; ni++) {
                int n = bn + wn + ni * 8 + tq * 2;
                *(__half2*)(orow + n) =
                    __floats2half2_rn(acc[mi][ni][rh * 2], acc[mi][ni][rh * 2 + 1]);
            }
        }
    }
}

// ---------------- gate v2: smem-cached gate matrix, 128 tokens/block --------
__global__ void __launch_bounds__(256) gate_v2(
    const __half* __restrict__ h3, const float* __restrict__ gate_w,
    const int* __restrict__ task_id,
    float* __restrict__ probs, float* __restrict__ gate_dense) {
    extern __shared__ float gwT[];   // [16][1024]
    const float* gw = gate_w + (long)(*task_id) * (D_ * E_);
    int tid = threadIdx.x;
#pragma unroll 8
    for (int j = 0; j < 64; j++) {
        int idx = tid + 256 * j;
        int d = idx >> 4, e = idx & 15;
        gwT[e * 1024 + d] = gw[idx];
    }
    __syncthreads();
    int warp = tid >> 5, lane = tid & 31;
    for (int i = 0; i < 16; i++) {
        long tok = (long)blockIdx.x * 128 + i * 8 + warp;
        const __half* hrow = h3 + tok * D_;
        float acc[16];
#pragma unroll
        for (int e = 0; e < 16; e++) acc[e] = 0.f;
#pragma unroll
        for (int j = 0; j < 8; j++) {
            int d0 = (j * 32 + lane) * 4;
            __half2 a = *(const __half2*)(hrow + d0);
            __half2 b = *(const __half2*)(hrow + d0 + 2);
            float2 fa = __half22float2(a), fb = __half22float2(b);
#pragma unroll
            for (int e = 0; e < 16; e++) {
                float4 g4 = *(const float4*)&gwT[e * 1024 + d0];
                acc[e] += fa.x * g4.x + fa.y * g4.y + fb.x * g4.z + fb.y * g4.w;
            }
        }
#pragma unroll
        for (int e = 0; e < 16; e++) {
#pragma unroll
            for (int o = 16; o; o >>= 1)
                acc[e] += __shfl_xor_sync(0xffffffffu, acc[e], o);
        }
        if (lane == 0) {
            float mx = -1e30f;
#pragma unroll
            for (int e = 0; e < 16; e++) mx = fmaxf(mx, acc[e]);
            float sum = 0.f;
#pragma unroll
            for (int e = 0; e < 16; e++) { acc[e] = expf(acc[e] - mx); sum += acc[e]; }
            float inv = 1.f / sum;
            float p[16];
#pragma unroll
            for (int e = 0; e < 16; e++) { p[e] = acc[e] * inv; probs[tok * 16 + e] = p[e]; }
            bool used[16];
#pragma unroll
            for (int e = 0; e < 16; e++) used[e] = false;
            int tix[8]; float tvl[8]; float gsum = 0.f;
            for (int kk = 0; kk < 8; kk++) {
                float best = -1.f; int bi = 0;
                for (int e = 0; e < 16; e++)
                    if (!used[e] && p[e] > best) { best = p[e]; bi = e; }
                used[bi] = true; tix[kk] = bi; tvl[kk] = best; gsum += best;
            }
            float ginv = 1.f / (gsum + 1e-6f);
            float gdv[16];
#pragma unroll
            for (int e = 0; e < 16; e++) gdv[e] = 0.f;
            for (int kk = 0; kk < 8; kk++) gdv[tix[kk]] = tvl[kk] * ginv;
#pragma unroll
            for (int e = 0; e < 16; e++) gate_dense[tok * 16 + e] = gdv[e];
        }
    }
}

// ---------------- routing ----------------------------------------------------
__global__ void zero_cnt(int* cnt) {
    if (threadIdx.x < E_) cnt[threadIdx.x] = 0;
}
__global__ void route_k(const float* __restrict__ gd, int* __restrict__ cnt,
                        int* __restrict__ rowidx, int* __restrict__ pairpos) {
    int t = blockIdx.x * 128 + threadIdx.x;
    int k = 0;
#pragma unroll
    for (int e = 0; e < E_; e++) {
        float v = gd[(long)t * 16 + e];
        if (v > 0.f && k < 8) {
            int pos = atomicAdd(&cnt[e], 1);
            rowidx[(long)e * CAP_ + pos] = t;
            pairpos[(long)t * 8 + k] = e * CAP_ + pos;
            k++;
        }
    }
}

// ---------------- gather: 2 tokens/block ------------------------------------
__global__ void __launch_bounds__(512) gather_k(
    const float* __restrict__ x, const __half* __restrict__ outs,
    const int* __restrict__ pairpos, const float* __restrict__ gd,
    const float* __restrict__ b2, float* __restrict__ out) {
    int half_ = threadIdx.x >> 8;
    int tid = threadIdx.x & 255;
    long t = (long)blockIdx.x * 2 + half_;
    __shared__ int pp[2][8];
    __shared__ float gdv[2][16];
    if (tid < 8) pp[half_][tid] = pairpos[t * 8 + tid];
    if (tid < 16) gdv[half_][tid] = gd[t * 16 + tid];
    __syncthreads();
    int d = tid * 4;
    float4 a = *(const float4*)(x + t * D_ + d);
#pragma unroll
    for (int k = 0; k < 8; k++) {
        const __half2* o2 = (const __half2*)(outs + (long)pp[half_][k] * D_ + d);
        float2 f0 = __half22float2(o2[0]), f1 = __half22float2(o2[1]);
        a.x += f0.x; a.y += f0.y; a.z += f1.x; a.w += f1.y;
    }
#pragma unroll
    for (int e = 0; e < 16; e++) {
        float4 bv = *(const float4*)(b2 + (long)e * D_ + d);
        float gv = gdv[half_][e];
        a.x += gv * bv.x; a.y += gv * bv.y; a.z += gv * bv.z; a.w += gv * bv.w;
    }
    *(float4*)(out + t * D_ + d) = a;
}

// ---------------- aux loss: 64 deterministic partials + final ----------------
__global__ void aux_part(const float* __restrict__ probs, float* __restrict__ part) {
    int b = blockIdx.x, tid = threadIdx.x;
    const float* p = probs + ((long)b * 256 + tid) * 16;
    float v[16];
#pragma unroll
    for (int e = 0; e < 16; e++) v[e] = p[e];
    __shared__ float red[256][17];
#pragma unroll
    for (int e = 0; e < 16; e++) red[tid][e] = v[e];
    __syncthreads();
    for (int s = 128; s; s >>= 1) {
        if (tid < s) {
#pragma unroll
            for (int e = 0; e < 16; e++) red[tid][e] += red[tid + s][e];
        }
        __syncthreads();
    }
    if (tid == 0) {
#pragma unroll
        for (int e = 0; e < 16; e++) part[b * 16 + e] = red[0][e];
    }
}
__global__ void aux_fin(const float* __restrict__ part, float* __restrict__ outv) {
    if (threadIdx.x == 0) {
        float aux = 0.f;
        for (int e = 0; e < 16; e++) {
            float s = 0.f;
            for (int b = 0; b < 64; b++) s += part[b * 16 + e];
            float mp = s * (1.f / T_);
            aux += mp * logf(mp + 1e-6f);
        }
        outv[0] = 5e-4f * aux;
    }
}

// ---------------- launch -----------------------------------------------------
extern "C" void kernel_launch(void* const* d_in, const int* in_sizes, int n_in,
                              void* d_out, int out_size) {
    const float* tgt        = (const float*)d_in[0];
    const float* ln1_g      = (const float*)d_in[2];
    const float* ln1_b      = (const float*)d_in[3];
    const float* ln3_g      = (const float*)d_in[4];
    const float* ln3_b      = (const float*)d_in[5];
    const float* in_proj_w  = (const float*)d_in[6];
    const float* in_proj_b  = (const float*)d_in[7];
    const float* out_proj_w = (const float*)d_in[8];
    const float* out_proj_b = (const float*)d_in[9];
    const float* gate_w     = (const float*)d_in[10];
    const float* w1         = (const float*)d_in[11];
    const float* b1         = (const float*)d_in[12];
    const float* w2         = (const float*)d_in[13];
    const float* b2         = (const float*)d_in[14];
    const int*   task_id    = (const int*)d_in[15];

    float* out       = (float*)d_out;
    float* out_x     = out;
    float* out_aux   = out + (size_t)T_ * D_;
    float* out_probs = out_aux + 1;

    __half *h16, *qkv16, *vt16, *ctx16, *wi16, *wo16, *w1t16, *w2te16, *uws, *outs;
    float *x, *gd, *auxp;
    int *cnt, *rowidx, *pairpos;
    cudaGetSymbolAddress((void**)&h16,    g_h16);
    cudaGetSymbolAddress((void**)&qkv16,  g_qkv16);
    cudaGetSymbolAddress((void**)&vt16,   g_vt16);
    cudaGetSymbolAddress((void**)&ctx16,  g_ctx16);
    cudaGetSymbolAddress((void**)&x,      g_x);
    cudaGetSymbolAddress((void**)&gd,     g_gate);
    cudaGetSymbolAddress((void**)&wi16,   g_wi16);
    cudaGetSymbolAddress((void**)&wo16,   g_wo16);
    cudaGetSymbolAddress((void**)&w1t16,  g_w1t16);
    cudaGetSymbolAddress((void**)&w2te16, g_w2te16);
    cudaGetSymbolAddress((void**)&uws,    g_uws);
    cudaGetSymbolAddress((void**)&outs,   g_outs);
    cudaGetSymbolAddress((void**)&cnt,    g_cnt);
    cudaGetSymbolAddress((void**)&rowidx, g_rowidx);
    cudaGetSymbolAddress((void**)&pairpos,g_pairpos);
    cudaGetSymbolAddress((void**)&auxp,   g_auxp);

    const int GSM = 3 * 32768;      // 98304
    const int GATESM = 65536;
    cudaFuncSetAttribute(gemm_h<true, false, true >, cudaFuncAttributeMaxDynamicSharedMemorySize, GSM);
    cudaFuncSetAttribute(gemm_h<true, true,  false>, cudaFuncAttributeMaxDynamicSharedMemorySize, GSM);
    cudaFuncSetAttribute(gemm_up, cudaFuncAttributeMaxDynamicSharedMemorySize, GSM);
    cudaFuncSetAttribute(gemm_dn, cudaFuncAttributeMaxDynamicSharedMemorySize, GSM);
    cudaFuncSetAttribute(gate_v2, cudaFuncAttributeMaxDynamicSharedMemorySize, GATESM);

    // 0. weight preprocessing
    conv_f2h<<<(unsigned)(3L * D_ * D_ / 1024), 256>>>(in_proj_w, wi16, 3L * D_ * D_);
    conv_f2h<<<(unsigned)(1L * D_ * D_ / 1024), 256>>>(out_proj_w, wo16, 1L * D_ * D_);
    transpose_h<float><<<dim3(8, 32, E_), 256>>>(
        w1, w1t16, D_, H_, H_, (long)D_ * H_, 0, (long)H_ * D_, 0, 1);
    transpose_h<float><<<dim3(32, 8, E_), 256>>>(
        w2, w2te16, H_, D_, D_, (long)H_ * D_, 0, (long)D_ * H_, 0, 1);

    // 1. h = LN1(tgt)
    ln_kernel<<<T_, 256>>>(tgt, ln1_g, ln1_b, h16);

    // 2. qkv = h @ in_proj_w^T + b (half out)
    gemm_h<true, false, true><<<dim3(24, 128), 256, GSM>>>(
        h16, wi16, qkv16, in_proj_b, nullptr, D_, D_, D_, 3 * D_);

    // 3. Vt = V^T per (b,h)
    transpose_h<__half><<<dim3(2, 16, B_ * NH_), 256>>>(
        qkv16 + 2 * D_, vt16, S_, DH_, 3 * D_,
        (long)S_ * 3 * D_, DH_, (long)NH_ * DH_ * S_, (long)DH_ * S_, NH_);

    // 4. fused flash attention -> ctx16
    flash_k<<<dim3(4, B_ * NH_), 256>>>(qkv16, vt16, ctx16);

    // 5. x = tgt + ctx @ out_proj_w^T + b (fp32 out)
    gemm_h<true, true, false><<<dim3(8, 128), 256, GSM>>>(
        ctx16, wo16, x, out_proj_b, tgt, D_, D_, D_, D_);

    // 6. h3 = LN3(x)
    ln_kernel<<<T_, 256>>>(x, ln3_g, ln3_b, h16);

    // 7. gate / aux
    gate_v2<<<T_ / 128, 256, GATESM>>>(h16, gate_w, task_id, out_probs, gd);
    aux_part<<<64, 256>>>(out_probs, auxp);
    aux_fin<<<1, 32>>>(auxp, out_aux);

    // 8. routing
    zero_cnt<<<1, 32>>>(cnt);
    route_k<<<T_ / 128, 128>>>(gd, cnt, rowidx, pairpos);

    // 9. sparse MoE up
    gemm_up<<<dim3(2, 128, E_), 256, GSM>>>(h16, w1t16, uws, b1, gd, rowidx, cnt);

    // 10. sparse MoE down
    gemm_dn<<<dim3(8, 128, E_), 256, GSM>>>(uws, w2te16, outs, cnt);

    // 11. gather: out = x + sum_k outs + gd @ b2
    gather_k<<<T_ / 2, 512>>>(x, outs, pairpos, gd, b2, out_x);

    (void)in_sizes; (void)n_in; (void)out_size;
}

// round 13
// speedup vs baseline: 1.0689x; 1.0171x over previous
#include <cuda_runtime.h>
#include <cuda_fp16.h>
#include <math.h>
#include <stdint.h>

#define B_   32
#define S_   512
#define D_   1024
#define NH_  16
#define E_   16
#define H_   256
#define DH_  64
#define T_   (B_ * S_)          // 16384
#define CAP_ 16384

// ---------------- scratch (static device memory) ---------------------------
__device__ __half g_h16[(size_t)T_ * D_];
__device__ __half g_qkv16[(size_t)T_ * 3 * D_];
__device__ __half g_ctx16[(size_t)T_ * D_];
__device__ float  g_x[(size_t)T_ * D_];
__device__ float  g_gate[(size_t)T_ * E_];
__device__ __half g_wi16[(size_t)3 * D_ * D_];
__device__ __half g_wo16[(size_t)D_ * D_];
__device__ __half g_w1t16[(size_t)E_ * H_ * D_];
__device__ __half g_w2te16[(size_t)E_ * D_ * H_];
__device__ __half g_uws[(size_t)E_ * CAP_ * H_];
__device__ __half g_outs[(size_t)E_ * CAP_ * D_];
__device__ int    g_cnt[E_];
__device__ int    g_rowidx[(size_t)E_ * CAP_];
__device__ int    g_pairpos[(size_t)T_ * 8];
__device__ float  g_auxp[64 * E_];

// ---------------- helpers ---------------------------------------------------
__device__ __forceinline__ uint32_t smem_u32(const void* p) {
    uint32_t a;
    asm("{ .reg .u64 t; cvta.to.shared.u64 t, %1; cvt.u32.u64 %0, t; }" : "=r"(a) : "l"(p));
    return a;
}
__device__ __forceinline__ uint32_t h2_as_u32(__half2 h) {
    return *reinterpret_cast<uint32_t*>(&h);
}
#define CP_ASYNC16(dst, src) \
    asm volatile("cp.async.ca.shared.global [%0], [%1], 16;" :: "r"(dst), "l"(src) : "memory")
#define CP_COMMIT() asm volatile("cp.async.commit_group;" ::: "memory")
#define CP_WAIT1()  asm volatile("cp.async.wait_group 1;" ::: "memory")
#define CP_WAIT0()  asm volatile("cp.async.wait_group 0;" ::: "memory")

#define LDSM_X4(r0, r1, r2, r3, addr) \
    asm volatile("ldmatrix.sync.aligned.m8n8.x4.shared.b16 {%0,%1,%2,%3}, [%4];" \
        : "=r"(r0), "=r"(r1), "=r"(r2), "=r"(r3) : "r"(addr))
#define LDSM_X4_T(r0, r1, r2, r3, addr) \
    asm volatile("ldmatrix.sync.aligned.m8n8.x4.trans.shared.b16 {%0,%1,%2,%3}, [%4];" \
        : "=r"(r0), "=r"(r1), "=r"(r2), "=r"(r3) : "r"(addr))

__device__ __forceinline__ void mma16(float* d, const uint32_t* a, const uint32_t* b) {
    asm volatile(
        "mma.sync.aligned.m16n8k16.row.col.f32.f16.f16.f32 "
        "{%0,%1,%2,%3},{%4,%5,%6,%7},{%8,%9},{%0,%1,%2,%3};"
        : "+f"(d[0]), "+f"(d[1]), "+f"(d[2]), "+f"(d[3])
        : "r"(a[0]), "r"(a[1]), "r"(a[2]), "r"(a[3]), "r"(b[0]), "r"(b[1]));
}

// smem tile: 64 halfs (128B) per row, SW128
__device__ __forceinline__ uint32_t qoff(int m, int c) {
    return (uint32_t)(m * 128 + ((c ^ (m & 7)) << 4));
}
__device__ __forceinline__ float gelu_f(float v) {
    return 0.5f * v * (1.f + erff(v * 0.70710678118654752f));
}

// ---------------- LayerNorm (fp32 in -> half out), float4 loads -------------
__global__ void ln_kernel(const float* __restrict__ x, const float* __restrict__ g,
                          const float* __restrict__ b, __half* __restrict__ y16) {
    long t = blockIdx.x;
    const float* row = x + t * D_;
    int tid = threadIdx.x;
    float4 v = *(const float4*)(row + tid * 4);
    float s = v.x + v.y + v.z + v.w;
    float sq = v.x * v.x + v.y * v.y + v.z * v.z + v.w * v.w;
#pragma unroll
    for (int o = 16; o; o >>= 1) {
        s  += __shfl_xor_sync(0xffffffffu, s, o);
        sq += __shfl_xor_sync(0xffffffffu, sq, o);
    }
    __shared__ float ws[8], wq[8];
    int w = tid >> 5, l = tid & 31;
    if (l == 0) { ws[w] = s; wq[w] = sq; }
    __syncthreads();
    if (tid == 0) {
        float a = 0.f, c = 0.f;
        for (int i = 0; i < 8; i++) { a += ws[i]; c += wq[i]; }
        ws[0] = a; wq[0] = c;
    }
    __syncthreads();
    float mean = ws[0] * (1.f / D_);
    float var  = wq[0] * (1.f / D_) - mean * mean;
    float inv  = rsqrtf(var + 1e-5f);
    int d = tid * 4;
    float4 gv = *(const float4*)(g + d);
    float4 bv = *(const float4*)(b + d);
    __half2 o0 = __floats2half2_rn((v.x - mean) * inv * gv.x + bv.x,
                                   (v.y - mean) * inv * gv.y + bv.y);
    __half2 o1 = __floats2half2_rn((v.z - mean) * inv * gv.z + bv.z,
                                   (v.w - mean) * inv * gv.w + bv.w);
    *(__half2*)(y16 + t * D_ + d)     = o0;
    *(__half2*)(y16 + t * D_ + d + 2) = o1;
}

// ---------------- fused fp32->fp16 convert (2 tensors) + cnt zero -----------
__global__ void conv2_k(const float* __restrict__ a, __half* __restrict__ oa, long na,
                        const float* __restrict__ b, __half* __restrict__ ob,
                        int* __restrict__ cnt) {
    if (blockIdx.x == 0 && threadIdx.x < E_) cnt[threadIdx.x] = 0;
    long i = (long)blockIdx.x * 1024 + threadIdx.x * 4;
    if (i < na) {
        float4 v = *(const float4*)(a + i);
        *(__half2*)(oa + i)     = __floats2half2_rn(v.x, v.y);
        *(__half2*)(oa + i + 2) = __floats2half2_rn(v.z, v.w);
    } else {
        long j = i - na;
        float4 v = *(const float4*)(b + j);
        *(__half2*)(ob + j)     = __floats2half2_rn(v.x, v.y);
        *(__half2*)(ob + j + 2) = __floats2half2_rn(v.z, v.w);
    }
}

// ---------------- batched tiled transpose -> half ---------------------------
template <typename TI>
__global__ void transpose_h(const TI* __restrict__ src, __half* __restrict__ dst,
                            int R, int C, long srcRS,
                            long sSo, long sSi, long sDo, long sDi, int nInner) {
    int zo = blockIdx.z / nInner, zi = blockIdx.z - zo * nInner;
    src += (long)zo * sSo + (long)zi * sSi;
    dst += (long)zo * sDo + (long)zi * sDi;
    __shared__ float tile[32][33];
    int r0 = blockIdx.y * 32, c0 = blockIdx.x * 32;
    int tx = threadIdx.x & 31, ty = threadIdx.x >> 5;
#pragma unroll
    for (int k = 0; k < 4; k++) {
        int r = r0 + ty + 8 * k;
        if (r < R && c0 + tx < C) tile[ty + 8 * k][tx] = (float)src[(long)r * srcRS + c0 + tx];
    }
    __syncthreads();
#pragma unroll
    for (int k = 0; k < 4; k++) {
        int c = c0 + ty + 8 * k;
        if (c < C && r0 + tx < R) dst[(long)c * R + r0 + tx] = __float2half(tile[tx][ty + 8 * k]);
    }
}

// ---------------- fused flash attention, direct-V (ldmatrix.trans) ----------
__global__ void __launch_bounds__(256) flash_k(
    const __half* __restrict__ qkv, __half* __restrict__ ctx) {
    int bh = blockIdx.y;
    int b = bh >> 4, hh = bh & 15;
    int qb = blockIdx.x;
    const __half* Qb = qkv + ((long)b * S_ + qb * 128) * (3 * D_) + hh * DH_;
    const __half* Kb = qkv + (long)b * S_ * (3 * D_) + D_ + hh * DH_;
    const __half* Vb = qkv + (long)b * S_ * (3 * D_) + 2 * D_ + hh * DH_;

    __shared__ __align__(16) __half Qs[128 * 64];
    __shared__ __align__(16) __half Ks[2][64 * 64];
    __shared__ __align__(16) __half Vs[2][64 * 64];
    uint32_t qB = smem_u32(Qs), kB = smem_u32(Ks), vB = smem_u32(Vs);

    int tid = threadIdx.x, lane = tid & 31, warp = tid >> 5;
    int wm = warp * 16;
    int g = lane >> 2, tq = lane & 3;
    int q2 = lane >> 3, r7 = lane & 7;
    const float L2E = 1.44269504088896f;

#pragma unroll
    for (int j = 0; j < 4; j++) {
        int s = tid + 256 * j;
        int r = s >> 3, cu = s & 7;
        CP_ASYNC16(qB + qoff(r, cu), Qb + (long)r * (3 * D_) + cu * 8);
    }
    CP_COMMIT();
#pragma unroll
    for (int j = 0; j < 2; j++) {
        int s = tid + 256 * j;
        int r = s >> 3, cu = s & 7;
        CP_ASYNC16(kB + qoff(r, cu), Kb + (long)r * (3 * D_) + cu * 8);
        CP_ASYNC16(vB + qoff(r, cu), Vb + (long)r * (3 * D_) + cu * 8);
    }
    CP_COMMIT();
    CP_WAIT0();
    __syncthreads();
    {
        __half2 sc = __floats2half2_rn(0.125f, 0.125f);
        __half2* qh = (__half2*)Qs;
#pragma unroll
        for (int i = 0; i < 16; i++) qh[tid + 256 * i] = __hmul2(qh[tid + 256 * i], sc);
    }
    __syncthreads();

    float o[8][4];
#pragma unroll
    for (int ni = 0; ni < 8; ni++)
#pragma unroll
        for (int r = 0; r < 4; r++) o[ni][r] = 0.f;
    float m0 = -1e30f, m1 = -1e30f, l0 = 0.f, l1 = 0.f;

    for (int c = 0; c < 8; c++) {
        int buf = c & 1;
        if (c + 1 < 8) {
            int nb = 1 - buf;
#pragma unroll
            for (int j = 0; j < 2; j++) {
                int s = tid + 256 * j;
                int r = s >> 3, cu = s & 7;
                CP_ASYNC16(kB + nb * 8192 + qoff(r, cu),
                           Kb + (long)((c + 1) * 64 + r) * (3 * D_) + cu * 8);
                CP_ASYNC16(vB + nb * 8192 + qoff(r, cu),
                           Vb + (long)((c + 1) * 64 + r) * (3 * D_) + cu * 8);
            }
            CP_COMMIT();
            CP_WAIT1();
        } else {
            CP_WAIT0();
        }
        __syncthreads();

        uint32_t kBuf = kB + buf * 8192, vBuf = vB + buf * 8192;
        float sv[8][4];
#pragma unroll
        for (int ni = 0; ni < 8; ni++)
#pragma unroll
            for (int r = 0; r < 4; r++) sv[ni][r] = 0.f;
#pragma unroll
        for (int ks = 0; ks < 4; ks++) {
            uint32_t af[4], bf[8][2];
            int am = wm + (q2 & 1) * 8 + r7;
            LDSM_X4(af[0], af[1], af[2], af[3], qB + qoff(am, 2 * ks + (q2 >> 1)));
#pragma unroll
            for (int nj = 0; nj < 4; nj++) {
                int bn = nj * 16 + (q2 >> 1) * 8 + r7;
                LDSM_X4(bf[2 * nj][0], bf[2 * nj][1], bf[2 * nj + 1][0], bf[2 * nj + 1][1],
                        kBuf + qoff(bn, 2 * ks + (q2 & 1)));
            }
#pragma unroll
            for (int ni = 0; ni < 8; ni++) mma16(sv[ni], af, bf[ni]);
        }

        float cm0 = -1e30f, cm1 = -1e30f;
#pragma unroll
        for (int ni = 0; ni < 8; ni++) {
            cm0 = fmaxf(cm0, fmaxf(sv[ni][0], sv[ni][1]));
            cm1 = fmaxf(cm1, fmaxf(sv[ni][2], sv[ni][3]));
        }
        cm0 = fmaxf(cm0, __shfl_xor_sync(0xffffffffu, cm0, 1));
        cm0 = fmaxf(cm0, __shfl_xor_sync(0xffffffffu, cm0, 2));
        cm1 = fmaxf(cm1, __shfl_xor_sync(0xffffffffu, cm1, 1));
        cm1 = fmaxf(cm1, __shfl_xor_sync(0xffffffffu, cm1, 2));
        float mn0 = fmaxf(m0, cm0), mn1 = fmaxf(m1, cm1);
        float sc0 = exp2f((m0 - mn0) * L2E), sc1 = exp2f((m1 - mn1) * L2E);
        m0 = mn0; m1 = mn1;
        l0 *= sc0; l1 *= sc1;
#pragma unroll
        for (int ni = 0; ni < 8; ni++) {
            o[ni][0] *= sc0; o[ni][1] *= sc0;
            o[ni][2] *= sc1; o[ni][3] *= sc1;
        }
        uint32_t pa[4][4];
        float rs0 = 0.f, rs1 = 0.f;
#pragma unroll
        for (int ni = 0; ni < 8; ni++) {
            float p0 = exp2f((sv[ni][0] - mn0) * L2E);
            float p1 = exp2f((sv[ni][1] - mn0) * L2E);
            float p2 = exp2f((sv[ni][2] - mn1) * L2E);
            float p3 = exp2f((sv[ni][3] - mn1) * L2E);
            rs0 += p0 + p1; rs1 += p2 + p3;
            int kk = ni >> 1, hi = ni & 1;
            pa[kk][hi * 2]     = h2_as_u32(__floats2half2_rn(p0, p1));
            pa[kk][hi * 2 + 1] = h2_as_u32(__floats2half2_rn(p2, p3));
        }
        rs0 += __shfl_xor_sync(0xffffffffu, rs0, 1);
        rs0 += __shfl_xor_sync(0xffffffffu, rs0, 2);
        rs1 += __shfl_xor_sync(0xffffffffu, rs1, 1);
        rs1 += __shfl_xor_sync(0xffffffffu, rs1, 2);
        l0 += rs0; l1 += rs1;

        // O += P @ V : B-fragments of V^T via ldmatrix.trans on V tiles
#pragma unroll
        for (int ks = 0; ks < 4; ks++) {
            uint32_t bf[8][2];
#pragma unroll
            for (int nj = 0; nj < 4; nj++) {
                int vrow = 16 * ks + (q2 & 1) * 8 + r7;   // key index
                int vchk = nj * 2 + (q2 >> 1);            // dh 16B-chunk
                LDSM_X4_T(bf[2 * nj][0], bf[2 * nj][1], bf[2 * nj + 1][0], bf[2 * nj + 1][1],
                          vBuf + qoff(vrow, vchk));
            }
#pragma unroll
            for (int ni = 0; ni < 8; ni++) mma16(o[ni], pa[ks], bf[ni]);
        }
        __syncthreads();   // load-bearing: refill is issued BEFORE the wait here
    }

    float li0 = 1.f / l0, li1 = 1.f / l1;
    long row0 = (long)b * S_ + qb * 128 + wm + g;
    __half* c0p = ctx + (row0)     * D_ + hh * DH_;
    __half* c1p = ctx + (row0 + 8) * D_ + hh * DH_;
#pragma unroll
    for (int ni = 0; ni < 8; ni++) {
        int nc = ni * 8 + tq * 2;
        *(__half2*)(c0p + nc) = __floats2half2_rn(o[ni][0] * li0, o[ni][1] * li0);
        *(__half2*)(c1p + nc) = __floats2half2_rn(o[ni][2] * li1, o[ni][3] * li1);
    }
}

// ---------------- fp16 GEMM: 128x128 tile, BK=64, 3 stages, 2 CTAs/SM -------
template <bool BI, bool RE, bool HOUT>
__global__ void __launch_bounds__(256, 2) gemm_h(
    const __half* __restrict__ A, const __half* __restrict__ Bm, void* __restrict__ C,
    const float* __restrict__ bias, const float* __restrict__ resid,
    int Kd, int lda, int ldb, int ldc) {
    constexpr int STAGE = 32768, BOFF = 16384;
    extern __shared__ __align__(16) char smdyn[];
    uint32_t sb = smem_u32(smdyn);

    int tid = threadIdx.x, lane = tid & 31, warp = tid >> 5;
    int bm = blockIdx.y * 128, bn = blockIdx.x * 128;
    int wm = (warp % 4) * 32, wn = (warp / 4) * 64;
    int g = lane >> 2, tq = lane & 3;
    int q2 = lane >> 3, r7 = lane & 7;

    float acc[2][8][4];
#pragma unroll
    for (int mi = 0; mi < 2; mi++)
#pragma unroll
        for (int ni = 0; ni < 8; ni++)
#pragma unroll
            for (int r = 0; r < 4; r++) acc[mi][ni][r] = 0.f;

    int NC = Kd >> 6;
#define GH_ISSUE(st, k0)                                                              \
    do {                                                                              \
        uint32_t _as = sb + (st) * STAGE, _bs = _as + BOFF;                           \
        _Pragma("unroll")                                                             \
        for (int j = 0; j < 4; j++) {                                                 \
            int s = tid + 256 * j; int r = s >> 3, cu = s & 7;                        \
            CP_ASYNC16(_as + qoff(r, cu), A + (long)(bm + r) * lda + (k0) + cu * 8);  \
            CP_ASYNC16(_bs + qoff(r, cu), Bm + (long)(bn + r) * ldb + (k0) + cu * 8); \
        }                                                                             \
    } while (0)

    GH_ISSUE(0, 0); CP_COMMIT();
    GH_ISSUE(1, 64); CP_COMMIT();

    for (int ck = 0; ck < NC; ck++) {
        CP_WAIT1();
        __syncthreads();
        if (ck + 2 < NC) { int st = (ck + 2) % 3; GH_ISSUE(st, (ck + 2) << 6); }
        CP_COMMIT();
        uint32_t aBase = sb + (ck % 3) * STAGE, bBase = aBase + BOFF;
#pragma unroll
        for (int s = 0; s < 4; s++) {
            uint32_t af[2][4], bf[8][2];
#pragma unroll
            for (int mi = 0; mi < 2; mi++) {
                int m = wm + mi * 16 + (q2 & 1) * 8 + r7;
                LDSM_X4(af[mi][0], af[mi][1], af[mi][2], af[mi][3],
                        aBase + qoff(m, 2 * s + (q2 >> 1)));
            }
#pragma unroll
            for (int nj = 0; nj < 4; nj++) {
                int n = wn + nj * 16 + (q2 >> 1) * 8 + r7;
                LDSM_X4(bf[2 * nj][0], bf[2 * nj][1], bf[2 * nj + 1][0], bf[2 * nj + 1][1],
                        bBase + qoff(n, 2 * s + (q2 & 1)));
            }
#pragma unroll
            for (int mi = 0; mi < 2; mi++)
#pragma unroll
                for (int ni = 0; ni < 8; ni++)
                    mma16(acc[mi][ni], af[mi], bf[ni]);
        }
        // no tail sync: next iteration's top sync protects the stage rotation
    }
#undef GH_ISSUE

    __half* Ch = (__half*)C;
    float*  Cf = (float*)C;
#pragma unroll
    for (int mi = 0; mi < 2; mi++) {
#pragma unroll
        for (int rh = 0; rh < 2; rh++) {
            int row = bm + wm + mi * 16 + g + rh * 8;
#pragma unroll
            for (int ni = 0; ni < 8; ni++) {
                int n = bn + wn + ni * 8 + tq * 2;
                float v0 = acc[mi][ni][rh * 2], v1 = acc[mi][ni][rh * 2 + 1];
                if (BI) { v0 += bias[n]; v1 += bias[n + 1]; }
                if (HOUT) {
                    *(__half2*)(Ch + (long)row * ldc + n) = __floats2half2_rn(v0, v1);
                } else {
                    if (RE) {
                        float2 rv = *(const float2*)(resid + (long)row * ldc + n);
                        v0 += rv.x; v1 += rv.y;
                    }
                    float2 ov; ov.x = v0; ov.y = v1;
                    *(float2*)(Cf + (long)row * ldc + n) = ov;
                }
            }
        }
    }
}

// ---------------- MoE up: indexed-A grouped GEMM, GELU*gate epilogue --------
__global__ void __launch_bounds__(256, 2) gemm_up(
    const __half* __restrict__ Ah, const __half* __restrict__ w1t,
    __half* __restrict__ uws, const float* __restrict__ b1,
    const float* __restrict__ gd, const int* __restrict__ rowidx,
    const int* __restrict__ cnt) {
    constexpr int STAGE = 32768, BOFF = 16384;
    extern __shared__ __align__(16) char smdyn[];
    uint32_t sb = smem_u32(smdyn);

    int e = blockIdx.z;
    int c = cnt[e];
    int cp = (c + 127) & ~127;
    int bm = blockIdx.y * 128;
    if (bm >= cp) return;
    int bn = blockIdx.x * 128;

    int tid = threadIdx.x, lane = tid & 31, warp = tid >> 5;
    int wm = (warp % 4) * 32, wn = (warp / 4) * 64;
    int g = lane >> 2, tq = lane & 3;
    int q2 = lane >> 3, r7 = lane & 7;
    const __half* Bp = w1t + (long)e * (H_ * D_);
    const int* ridx = rowidx + (long)e * CAP_;

    int tokA[4];
#pragma unroll
    for (int j = 0; j < 4; j++) {
        int r = (tid + 256 * j) >> 3;
        tokA[j] = ridx[bm + r];
    }

    float acc[2][8][4];
#pragma unroll
    for (int mi = 0; mi < 2; mi++)
#pragma unroll
        for (int ni = 0; ni < 8; ni++)
#pragma unroll
            for (int r = 0; r < 4; r++) acc[mi][ni][r] = 0.f;

#define UP_ISSUE(st, k0)                                                              \
    do {                                                                              \
        uint32_t _as = sb + (st) * STAGE, _bs = _as + BOFF;                           \
        _Pragma("unroll")                                                             \
        for (int j = 0; j < 4; j++) {                                                 \
            int s = tid + 256 * j; int r = s >> 3, cu = s & 7;                        \
            CP_ASYNC16(_as + qoff(r, cu), Ah + (long)tokA[j] * D_ + (k0) + cu * 8);   \
            CP_ASYNC16(_bs + qoff(r, cu), Bp + (long)(bn + r) * D_ + (k0) + cu * 8);  \
        }                                                                             \
    } while (0)

    UP_ISSUE(0, 0); CP_COMMIT();
    UP_ISSUE(1, 64); CP_COMMIT();

    for (int ck = 0; ck < 16; ck++) {
        CP_WAIT1();
        __syncthreads();
        if (ck + 2 < 16) { int st = (ck + 2) % 3; UP_ISSUE(st, (ck + 2) << 6); }
        CP_COMMIT();
        uint32_t aBase = sb + (ck % 3) * STAGE, bBase = aBase + BOFF;
#pragma unroll
        for (int s = 0; s < 4; s++) {
            uint32_t af[2][4], bf[8][2];
#pragma unroll
            for (int mi = 0; mi < 2; mi++) {
                int m = wm + mi * 16 + (q2 & 1) * 8 + r7;
                LDSM_X4(af[mi][0], af[mi][1], af[mi][2], af[mi][3],
                        aBase + qoff(m, 2 * s + (q2 >> 1)));
            }
#pragma unroll
            for (int nj = 0; nj < 4; nj++) {
                int n = wn + nj * 16 + (q2 >> 1) * 8 + r7;
                LDSM_X4(bf[2 * nj][0], bf[2 * nj][1], bf[2 * nj + 1][0], bf[2 * nj + 1][1],
                        bBase + qoff(n, 2 * s + (q2 & 1)));
            }
#pragma unroll
            for (int mi = 0; mi < 2; mi++)
#pragma unroll
                for (int ni = 0; ni < 8; ni++)
                    mma16(acc[mi][ni], af[mi], bf[ni]);
        }
        // no tail sync (see gemm_h)
    }
#undef UP_ISSUE

    const float* b1e = b1 + (long)e * H_;
#pragma unroll
    for (int mi = 0; mi < 2; mi++) {
#pragma unroll
        for (int rh = 0; rh < 2; rh++) {
            int row = bm + wm + mi * 16 + g + rh * 8;
            int tok = ridx[row];
            float gv = gd[(long)tok * 16 + e];
            __half* orow = uws + ((long)e * CAP_ + row) * H_;
#pragma unroll
            for (int ni = 0; ni < 8; ni++) {
                int n = bn + wn + ni * 8 + tq * 2;
                float v0 = gelu_f(acc[mi][ni][rh * 2]     + b1e[n])     * gv;
                float v1 = gelu_f(acc[mi][ni][rh * 2 + 1] + b1e[n + 1]) * gv;
                *(__half2*)(orow + n) = __floats2half2_rn(v0, v1);
            }
        }
    }
}

// ---------------- MoE down: grouped GEMM, K=256 -----------------------------
__global__ void __launch_bounds__(256, 2) gemm_dn(
    const __half* __restrict__ uws, const __half* __restrict__ w2te,
    __half* __restrict__ outs, const int* __restrict__ cnt) {
    constexpr int STAGE = 32768, BOFF = 16384;
    extern __shared__ __align__(16) char smdyn[];
    uint32_t sb = smem_u32(smdyn);

    int e = blockIdx.z;
    int c = cnt[e];
    int cp = (c + 127) & ~127;
    int bm = blockIdx.y * 128;
    if (bm >= cp) return;
    int bn = blockIdx.x * 128;

    int tid = threadIdx.x, lane = tid & 31, warp = tid >> 5;
    int wm = (warp % 4) * 32, wn = (warp / 4) * 64;
    int g = lane >> 2, tq = lane & 3;
    int q2 = lane >> 3, r7 = lane & 7;
    const __half* Ap = uws + (long)e * CAP_ * H_;
    const __half* Bp = w2te + (long)e * (D_ * H_);

    float acc[2][8][4];
#pragma unroll
    for (int mi = 0; mi < 2; mi++)
#pragma unroll
        for (int ni = 0; ni < 8; ni++)
#pragma unroll
            for (int r = 0; r < 4; r++) acc[mi][ni][r] = 0.f;

#define DN_ISSUE(st, k0)                                                              \
    do {                                                                              \
        uint32_t _as = sb + (st) * STAGE, _bs = _as + BOFF;                           \
        _Pragma("unroll")                                                             \
        for (int j = 0; j < 4; j++) {                                                 \
            int s = tid + 256 * j; int r = s >> 3, cu = s & 7;                        \
            CP_ASYNC16(_as + qoff(r, cu), Ap + (long)(bm + r) * H_ + (k0) + cu * 8);  \
            CP_ASYNC16(_bs + qoff(r, cu), Bp + (long)(bn + r) * H_ + (k0) + cu * 8);  \
        }                                                                             \
    } while (0)

    DN_ISSUE(0, 0); CP_COMMIT();
    DN_ISSUE(1, 64); CP_COMMIT();

    for (int ck = 0; ck < 4; ck++) {
        CP_WAIT1();
        __syncthreads();
        if (ck + 2 < 4) { int st = (ck + 2) % 3; DN_ISSUE(st, (ck + 2) << 6); }
        CP_COMMIT();
        uint32_t aBase = sb + (ck % 3) * STAGE, bBase = aBase + BOFF;
#pragma unroll
        for (int s = 0; s < 4; s++) {
            uint32_t af[2][4], bf[8][2];
#pragma unroll
            for (int mi = 0; mi < 2; mi++) {
                int m = wm + mi * 16 + (q2 & 1) * 8 + r7;
                LDSM_X4(af[mi][0], af[mi][1], af[mi][2], af[mi][3],
                        aBase + qoff(m, 2 * s + (q2 >> 1)));
            }
#pragma unroll
            for (int nj = 0; nj < 4; nj++) {
                int n = wn + nj * 16 + (q2 >> 1) * 8 + r7;
                LDSM_X4(bf[2 * nj][0], bf[2 * nj][1], bf[2 * nj + 1][0], bf[2 * nj + 1][1],
                        bBase + qoff(n, 2 * s + (q2 & 1)));
            }
#pragma unroll
            for (int mi = 0; mi < 2; mi++)
#pragma unroll
                for (int ni = 0; ni < 8; ni++)
                    mma16(acc[mi][ni], af[mi], bf[ni]);
        }
        // no tail sync (see gemm_h)
    }
#undef DN_ISSUE

#pragma unroll
    for (int mi = 0; mi < 2; mi++) {
#pragma unroll
        for (int rh = 0; rh < 2; rh++) {
            int row = bm + wm + mi * 16 + g + rh * 8;
            __half* orow = outs + ((long)e * CAP_ + row) * D_;
#pragma unroll
            for (int ni = 0; ni < 8; ni++) {
                int n = bn + wn + ni * 8 + tq * 2;
                *(__half2*)(orow + n) =
                    __floats2half2_rn(acc[mi][ni][rh * 2], acc[mi][ni][rh * 2 + 1]);
            }
        }
    }
}

// ---------------- gate v2: smem-cached gate matrix, 128 tokens/block --------
__global__ void __launch_bounds__(256) gate_v2(
    const __half* __restrict__ h3, const float* __restrict__ gate_w,
    const int* __restrict__ task_id,
    float* __restrict__ probs, float* __restrict__ gate_dense) {
    extern __shared__ float gwT[];   // [16][1024]
    const float* gw = gate_w + (long)(*task_id) * (D_ * E_);
    int tid = threadIdx.x;
#pragma unroll 8
    for (int j = 0; j < 64; j++) {
        int idx = tid + 256 * j;
        int d = idx >> 4, e = idx & 15;
        gwT[e * 1024 + d] = gw[idx];
    }
    __syncthreads();
    int warp = tid >> 5, lane = tid & 31;
    for (int i = 0; i < 16; i++) {
        long tok = (long)blockIdx.x * 128 + i * 8 + warp;
        const __half* hrow = h3 + tok * D_;
        float acc[16];
#pragma unroll
        for (int e = 0; e < 16; e++) acc[e] = 0.f;
#pragma unroll
        for (int j = 0; j < 8; j++) {
            int d0 = (j * 32 + lane) * 4;
            __half2 a = *(const __half2*)(hrow + d0);
            __half2 b = *(const __half2*)(hrow + d0 + 2);
            float2 fa = __half22float2(a), fb = __half22float2(b);
#pragma unroll
            for (int e = 0; e < 16; e++) {
                float4 g4 = *(const float4*)&gwT[e * 1024 + d0];
                acc[e] += fa.x * g4.x + fa.y * g4.y + fb.x * g4.z + fb.y * g4.w;
            }
        }
#pragma unroll
        for (int e = 0; e < 16; e++) {
#pragma unroll
            for (int o = 16; o; o >>= 1)
                acc[e] += __shfl_xor_sync(0xffffffffu, acc[e], o);
        }
        if (lane == 0) {
            float mx = -1e30f;
#pragma unroll
            for (int e = 0; e < 16; e++) mx = fmaxf(mx, acc[e]);
            float sum = 0.f;
#pragma unroll
            for (int e = 0; e < 16; e++) { acc[e] = expf(acc[e] - mx); sum += acc[e]; }
            float inv = 1.f / sum;
            float p[16];
#pragma unroll
            for (int e = 0; e < 16; e++) { p[e] = acc[e] * inv; probs[tok * 16 + e] = p[e]; }
            bool used[16];
#pragma unroll
            for (int e = 0; e < 16; e++) used[e] = false;
            int tix[8]; float tvl[8]; float gsum = 0.f;
            for (int kk = 0; kk < 8; kk++) {
                float best = -1.f; int bi = 0;
                for (int e = 0; e < 16; e++)
                    if (!used[e] && p[e] > best) { best = p[e]; bi = e; }
                used[bi] = true; tix[kk] = bi; tvl[kk] = best; gsum += best;
            }
            float ginv = 1.f / (gsum + 1e-6f);
            float gdv[16];
#pragma unroll
            for (int e = 0; e < 16; e++) gdv[e] = 0.f;
            for (int kk = 0; kk < 8; kk++) gdv[tix[kk]] = tvl[kk] * ginv;
#pragma unroll
            for (int e = 0; e < 16; e++) gate_dense[tok * 16 + e] = gdv[e];
        }
    }
}

// ---------------- routing ----------------------------------------------------
__global__ void route_k(const float* __restrict__ gd, int* __restrict__ cnt,
                        int* __restrict__ rowidx, int* __restrict__ pairpos) {
    int t = blockIdx.x * 128 + threadIdx.x;
    int k = 0;
#pragma unroll
    for (int e = 0; e < E_; e++) {
        float v = gd[(long)t * 16 + e];
        if (v > 0.f && k < 8) {
            int pos = atomicAdd(&cnt[e], 1);
            rowidx[(long)e * CAP_ + pos] = t;
            pairpos[(long)t * 8 + k] = e * CAP_ + pos;
            k++;
        }
    }
}

// ---------------- gather: 2 tokens/block ------------------------------------
__global__ void __launch_bounds__(512) gather_k(
    const float* __restrict__ x, const __half* __restrict__ outs,
    const int* __restrict__ pairpos, const float* __restrict__ gd,
    const float* __restrict__ b2, float* __restrict__ out) {
    int half_ = threadIdx.x >> 8;
    int tid = threadIdx.x & 255;
    long t = (long)blockIdx.x * 2 + half_;
    __shared__ int pp[2][8];
    __shared__ float gdv[2][16];
    if (tid < 8) pp[half_][tid] = pairpos[t * 8 + tid];
    if (tid < 16) gdv[half_][tid] = gd[t * 16 + tid];
    __syncthreads();
    int d = tid * 4;
    float4 a = *(const float4*)(x + t * D_ + d);
#pragma unroll
    for (int k = 0; k < 8; k++) {
        const __half2* o2 = (const __half2*)(outs + (long)pp[half_][k] * D_ + d);
        float2 f0 = __half22float2(o2[0]), f1 = __half22float2(o2[1]);
        a.x += f0.x; a.y += f0.y; a.z += f1.x; a.w += f1.y;
    }
#pragma unroll
    for (int e = 0; e < 16; e++) {
        float4 bv = *(const float4*)(b2 + (long)e * D_ + d);
        float gv = gdv[half_][e];
        a.x += gv * bv.x; a.y += gv * bv.y; a.z += gv * bv.z; a.w += gv * bv.w;
    }
    *(float4*)(out + t * D_ + d) = a;
}

// ---------------- aux loss: 64 deterministic partials + final ----------------
__global__ void aux_part(const float* __restrict__ probs, float* __restrict__ part) {
    int b = blockIdx.x, tid = threadIdx.x;
    const float* p = probs + ((long)b * 256 + tid) * 16;
    float v[16];
#pragma unroll
    for (int e = 0; e < 16; e++) v[e] = p[e];
    __shared__ float red[256][17];
#pragma unroll
    for (int e = 0; e < 16; e++) red[tid][e] = v[e];
    __syncthreads();
    for (int s = 128; s; s >>= 1) {
        if (tid < s) {
#pragma unroll
            for (int e = 0; e < 16; e++) red[tid][e] += red[tid + s][e];
        }
        __syncthreads();
    }
    if (tid == 0) {
#pragma unroll
        for (int e = 0; e < 16; e++) part[b * 16 + e] = red[0][e];
    }
}
__global__ void aux_fin(const float* __restrict__ part, float* __restrict__ outv) {
    if (threadIdx.x == 0) {
        float aux = 0.f;
        for (int e = 0; e < 16; e++) {
            float s = 0.f;
            for (int b = 0; b < 64; b++) s += part[b * 16 + e];
            float mp = s * (1.f / T_);
            aux += mp * logf(mp + 1e-6f);
        }
        outv[0] = 5e-4f * aux;
    }
}

// ---------------- launch -----------------------------------------------------
extern "C" void kernel_launch(void* const* d_in, const int* in_sizes, int n_in,
                              void* d_out, int out_size) {
    const float* tgt        = (const float*)d_in[0];
    const float* ln1_g      = (const float*)d_in[2];
    const float* ln1_b      = (const float*)d_in[3];
    const float* ln3_g      = (const float*)d_in[4];
    const float* ln3_b      = (const float*)d_in[5];
    const float* in_proj_w  = (const float*)d_in[6];
    const float* in_proj_b  = (const float*)d_in[7];
    const float* out_proj_w = (const float*)d_in[8];
    const float* out_proj_b = (const float*)d_in[9];
    const float* gate_w     = (const float*)d_in[10];
    const float* w1         = (const float*)d_in[11];
    const float* b1         = (const float*)d_in[12];
    const float* w2         = (const float*)d_in[13];
    const float* b2         = (const float*)d_in[14];
    const int*   task_id    = (const int*)d_in[15];

    float* out       = (float*)d_out;
    float* out_x     = out;
    float* out_aux   = out + (size_t)T_ * D_;
    float* out_probs = out_aux + 1;

    __half *h16, *qkv16, *ctx16, *wi16, *wo16, *w1t16, *w2te16, *uws, *outs;
    float *x, *gd, *auxp;
    int *cnt, *rowidx, *pairpos;
    cudaGetSymbolAddress((void**)&h16,    g_h16);
    cudaGetSymbolAddress((void**)&qkv16,  g_qkv16);
    cudaGetSymbolAddress((void**)&ctx16,  g_ctx16);
    cudaGetSymbolAddress((void**)&x,      g_x);
    cudaGetSymbolAddress((void**)&gd,     g_gate);
    cudaGetSymbolAddress((void**)&wi16,   g_wi16);
    cudaGetSymbolAddress((void**)&wo16,   g_wo16);
    cudaGetSymbolAddress((void**)&w1t16,  g_w1t16);
    cudaGetSymbolAddress((void**)&w2te16, g_w2te16);
    cudaGetSymbolAddress((void**)&uws,    g_uws);
    cudaGetSymbolAddress((void**)&outs,   g_outs);
    cudaGetSymbolAddress((void**)&cnt,    g_cnt);
    cudaGetSymbolAddress((void**)&rowidx, g_rowidx);
    cudaGetSymbolAddress((void**)&pairpos,g_pairpos);
    cudaGetSymbolAddress((void**)&auxp,   g_auxp);

    const int GSM = 3 * 32768;      // 98304
    const int GATESM = 65536;
    cudaFuncSetAttribute(gemm_h<true, false, true >, cudaFuncAttributeMaxDynamicSharedMemorySize, GSM);
    cudaFuncSetAttribute(gemm_h<true, true,  false>, cudaFuncAttributeMaxDynamicSharedMemorySize, GSM);
    cudaFuncSetAttribute(gemm_up, cudaFuncAttributeMaxDynamicSharedMemorySize, GSM);
    cudaFuncSetAttribute(gemm_dn, cudaFuncAttributeMaxDynamicSharedMemorySize, GSM);
    cudaFuncSetAttribute(gate_v2, cudaFuncAttributeMaxDynamicSharedMemorySize, GATESM);

    // 0. weight preprocessing (merged converts + cnt zero) and transposes
    conv2_k<<<(unsigned)(4L * D_ * D_ / 1024), 256>>>(
        in_proj_w, wi16, 3L * D_ * D_, out_proj_w, wo16, cnt);
    transpose_h<float><<<dim3(8, 32, E_), 256>>>(
        w1, w1t16, D_, H_, H_, (long)D_ * H_, 0, (long)H_ * D_, 0, 1);
    transpose_h<float><<<dim3(32, 8, E_), 256>>>(
        w2, w2te16, H_, D_, D_, (long)H_ * D_, 0, (long)D_ * H_, 0, 1);

    // 1. h = LN1(tgt)
    ln_kernel<<<T_, 256>>>(tgt, ln1_g, ln1_b, h16);

    // 2. qkv = h @ in_proj_w^T + b (half out)
    gemm_h<true, false, true><<<dim3(24, 128), 256, GSM>>>(
        h16, wi16, qkv16, in_proj_b, nullptr, D_, D_, D_, 3 * D_);

    // 3. fused flash attention (direct V) -> ctx16
    flash_k<<<dim3(4, B_ * NH_), 256>>>(qkv16, ctx16);

    // 4. x = tgt + ctx @ out_proj_w^T + b (fp32 out)
    gemm_h<true, true, false><<<dim3(8, 128), 256, GSM>>>(
        ctx16, wo16, x, out_proj_b, tgt, D_, D_, D_, D_);

    // 5. h3 = LN3(x)
    ln_kernel<<<T_, 256>>>(x, ln3_g, ln3_b, h16);

    // 6. gate / aux
    gate_v2<<<T_ / 128, 256, GATESM>>>(h16, gate_w, task_id, out_probs, gd);
    aux_part<<<64, 256>>>(out_probs, auxp);
    aux_fin<<<1, 32>>>(auxp, out_aux);

    // 7. routing (cnt zeroed in conv2_k at graph start; re-zeroed each replay)
    route_k<<<T_ / 128, 128>>>(gd, cnt, rowidx, pairpos);

    // 8. sparse MoE up
    gemm_up<<<dim3(2, 128, E_), 256, GSM>>>(h16, w1t16, uws, b1, gd, rowidx, cnt);

    // 9. sparse MoE down
    gemm_dn<<<dim3(8, 128, E_), 256, GSM>>>(uws, w2te16, outs, cnt);

    // 10. gather: out = x + sum_k outs + gd @ b2
    gather_k<<<T_ / 2, 512>>>(x, outs, pairpos, gd, b2, out_x);

    (void)in_sizes; (void)n_in; (void)out_size;
}

// round 14
// speedup vs baseline: 1.0706x; 1.0016x over previous
#include <cuda_runtime.h>
#include <cuda_fp16.h>
#include <math.h>
#include <stdint.h>

#define B_   32
#define S_   512
#define D_   1024
#define NH_  16
#define E_   16
#define H_   256
#define DH_  64
#define T_   (B_ * S_)          // 16384
#define CAP_ 16384

// ---------------- scratch (static device memory) ---------------------------
__device__ __half g_h16[(size_t)T_ * D_];
__device__ __half g_qkv16[(size_t)T_ * 3 * D_];
__device__ __half g_ctx16[(size_t)T_ * D_];
__device__ float  g_x[(size_t)T_ * D_];
__device__ float  g_gate[(size_t)T_ * E_];
__device__ __half g_wi16[(size_t)3 * D_ * D_];
__device__ __half g_wo16[(size_t)D_ * D_];
__device__ __half g_w1t16[(size_t)E_ * H_ * D_];
__device__ __half g_w2te16[(size_t)E_ * D_ * H_];
__device__ __half g_uws[(size_t)E_ * CAP_ * H_];
__device__ __half g_outs[(size_t)E_ * CAP_ * D_];
__device__ int    g_cnt[E_];
__device__ int    g_rowidx[(size_t)E_ * CAP_];
__device__ int    g_pairpos[(size_t)T_ * 8];
__device__ float  g_auxp[64 * E_];

// ---------------- helpers ---------------------------------------------------
__device__ __forceinline__ uint32_t smem_u32(const void* p) {
    uint32_t a;
    asm("{ .reg .u64 t; cvta.to.shared.u64 t, %1; cvt.u32.u64 %0, t; }" : "=r"(a) : "l"(p));
    return a;
}
__device__ __forceinline__ uint32_t h2_as_u32(__half2 h) {
    return *reinterpret_cast<uint32_t*>(&h);
}
#define CP_ASYNC16(dst, src) \
    asm volatile("cp.async.ca.shared.global [%0], [%1], 16;" :: "r"(dst), "l"(src) : "memory")
#define CP_COMMIT() asm volatile("cp.async.commit_group;" ::: "memory")
#define CP_WAIT1()  asm volatile("cp.async.wait_group 1;" ::: "memory")
#define CP_WAIT0()  asm volatile("cp.async.wait_group 0;" ::: "memory")

#define LDSM_X4(r0, r1, r2, r3, addr) \
    asm volatile("ldmatrix.sync.aligned.m8n8.x4.shared.b16 {%0,%1,%2,%3}, [%4];" \
        : "=r"(r0), "=r"(r1), "=r"(r2), "=r"(r3) : "r"(addr))
#define LDSM_X4_T(r0, r1, r2, r3, addr) \
    asm volatile("ldmatrix.sync.aligned.m8n8.x4.trans.shared.b16 {%0,%1,%2,%3}, [%4];" \
        : "=r"(r0), "=r"(r1), "=r"(r2), "=r"(r3) : "r"(addr))

__device__ __forceinline__ void mma16(float* d, const uint32_t* a, const uint32_t* b) {
    asm volatile(
        "mma.sync.aligned.m16n8k16.row.col.f32.f16.f16.f32 "
        "{%0,%1,%2,%3},{%4,%5,%6,%7},{%8,%9},{%0,%1,%2,%3};"
        : "+f"(d[0]), "+f"(d[1]), "+f"(d[2]), "+f"(d[3])
        : "r"(a[0]), "r"(a[1]), "r"(a[2]), "r"(a[3]), "r"(b[0]), "r"(b[1]));
}

// smem tile: 64 halfs (128B) per row, SW128
__device__ __forceinline__ uint32_t qoff(int m, int c) {
    return (uint32_t)(m * 128 + ((c ^ (m & 7)) << 4));
}
__device__ __forceinline__ float gelu_f(float v) {
    return 0.5f * v * (1.f + erff(v * 0.70710678118654752f));
}

// ---------------- LayerNorm (fp32 in -> half out), float4 loads -------------
__global__ void ln_kernel(const float* __restrict__ x, const float* __restrict__ g,
                          const float* __restrict__ b, __half* __restrict__ y16) {
    long t = blockIdx.x;
    const float* row = x + t * D_;
    int tid = threadIdx.x;
    float4 v = *(const float4*)(row + tid * 4);
    float s = v.x + v.y + v.z + v.w;
    float sq = v.x * v.x + v.y * v.y + v.z * v.z + v.w * v.w;
#pragma unroll
    for (int o = 16; o; o >>= 1) {
        s  += __shfl_xor_sync(0xffffffffu, s, o);
        sq += __shfl_xor_sync(0xffffffffu, sq, o);
    }
    __shared__ float ws[8], wq[8];
    int w = tid >> 5, l = tid & 31;
    if (l == 0) { ws[w] = s; wq[w] = sq; }
    __syncthreads();
    if (tid == 0) {
        float a = 0.f, c = 0.f;
        for (int i = 0; i < 8; i++) { a += ws[i]; c += wq[i]; }
        ws[0] = a; wq[0] = c;
    }
    __syncthreads();
    float mean = ws[0] * (1.f / D_);
    float var  = wq[0] * (1.f / D_) - mean * mean;
    float inv  = rsqrtf(var + 1e-5f);
    int d = tid * 4;
    float4 gv = *(const float4*)(g + d);
    float4 bv = *(const float4*)(b + d);
    __half2 o0 = __floats2half2_rn((v.x - mean) * inv * gv.x + bv.x,
                                   (v.y - mean) * inv * gv.y + bv.y);
    __half2 o1 = __floats2half2_rn((v.z - mean) * inv * gv.z + bv.z,
                                   (v.w - mean) * inv * gv.w + bv.w);
    *(__half2*)(y16 + t * D_ + d)     = o0;
    *(__half2*)(y16 + t * D_ + d + 2) = o1;
}

// ---------------- fused fp32->fp16 convert (2 tensors) + cnt zero -----------
__global__ void conv2_k(const float* __restrict__ a, __half* __restrict__ oa, long na,
                        const float* __restrict__ b, __half* __restrict__ ob,
                        int* __restrict__ cnt) {
    if (blockIdx.x == 0 && threadIdx.x < E_) cnt[threadIdx.x] = 0;
    long i = (long)blockIdx.x * 1024 + threadIdx.x * 4;
    if (i < na) {
        float4 v = *(const float4*)(a + i);
        *(__half2*)(oa + i)     = __floats2half2_rn(v.x, v.y);
        *(__half2*)(oa + i + 2) = __floats2half2_rn(v.z, v.w);
    } else {
        long j = i - na;
        float4 v = *(const float4*)(b + j);
        *(__half2*)(ob + j)     = __floats2half2_rn(v.x, v.y);
        *(__half2*)(ob + j + 2) = __floats2half2_rn(v.z, v.w);
    }
}

// ---------------- batched tiled transpose -> half ---------------------------
template <typename TI>
__global__ void transpose_h(const TI* __restrict__ src, __half* __restrict__ dst,
                            int R, int C, long srcRS,
                            long sSo, long sSi, long sDo, long sDi, int nInner) {
    int zo = blockIdx.z / nInner, zi = blockIdx.z - zo * nInner;
    src += (long)zo * sSo + (long)zi * sSi;
    dst += (long)zo * sDo + (long)zi * sDi;
    __shared__ float tile[32][33];
    int r0 = blockIdx.y * 32, c0 = blockIdx.x * 32;
    int tx = threadIdx.x & 31, ty = threadIdx.x >> 5;
#pragma unroll
    for (int k = 0; k < 4; k++) {
        int r = r0 + ty + 8 * k;
        if (r < R && c0 + tx < C) tile[ty + 8 * k][tx] = (float)src[(long)r * srcRS + c0 + tx];
    }
    __syncthreads();
#pragma unroll
    for (int k = 0; k < 4; k++) {
        int c = c0 + ty + 8 * k;
        if (c < C && r0 + tx < R) dst[(long)c * R + r0 + tx] = __float2half(tile[tx][ty + 8 * k]);
    }
}

// ---------------- fused flash attention, direct-V (ldmatrix.trans) ----------
__global__ void __launch_bounds__(256) flash_k(
    const __half* __restrict__ qkv, __half* __restrict__ ctx) {
    int bh = blockIdx.y;
    int b = bh >> 4, hh = bh & 15;
    int qb = blockIdx.x;
    const __half* Qb = qkv + ((long)b * S_ + qb * 128) * (3 * D_) + hh * DH_;
    const __half* Kb = qkv + (long)b * S_ * (3 * D_) + D_ + hh * DH_;
    const __half* Vb = qkv + (long)b * S_ * (3 * D_) + 2 * D_ + hh * DH_;

    __shared__ __align__(16) __half Qs[128 * 64];
    __shared__ __align__(16) __half Ks[2][64 * 64];
    __shared__ __align__(16) __half Vs[2][64 * 64];
    uint32_t qB = smem_u32(Qs), kB = smem_u32(Ks), vB = smem_u32(Vs);

    int tid = threadIdx.x, lane = tid & 31, warp = tid >> 5;
    int wm = warp * 16;
    int g = lane >> 2, tq = lane & 3;
    int q2 = lane >> 3, r7 = lane & 7;
    const float L2E = 1.44269504088896f;

#pragma unroll
    for (int j = 0; j < 4; j++) {
        int s = tid + 256 * j;
        int r = s >> 3, cu = s & 7;
        CP_ASYNC16(qB + qoff(r, cu), Qb + (long)r * (3 * D_) + cu * 8);
    }
    CP_COMMIT();
#pragma unroll
    for (int j = 0; j < 2; j++) {
        int s = tid + 256 * j;
        int r = s >> 3, cu = s & 7;
        CP_ASYNC16(kB + qoff(r, cu), Kb + (long)r * (3 * D_) + cu * 8);
        CP_ASYNC16(vB + qoff(r, cu), Vb + (long)r * (3 * D_) + cu * 8);
    }
    CP_COMMIT();
    CP_WAIT0();
    __syncthreads();
    {
        __half2 sc = __floats2half2_rn(0.125f, 0.125f);
        __half2* qh = (__half2*)Qs;
#pragma unroll
        for (int i = 0; i < 16; i++) qh[tid + 256 * i] = __hmul2(qh[tid + 256 * i], sc);
    }
    __syncthreads();

    float o[8][4];
#pragma unroll
    for (int ni = 0; ni < 8; ni++)
#pragma unroll
        for (int r = 0; r < 4; r++) o[ni][r] = 0.f;
    float m0 = -1e30f, m1 = -1e30f, l0 = 0.f, l1 = 0.f;

    for (int c = 0; c < 8; c++) {
        int buf = c & 1;
        if (c + 1 < 8) {
            int nb = 1 - buf;
#pragma unroll
            for (int j = 0; j < 2; j++) {
                int s = tid + 256 * j;
                int r = s >> 3, cu = s & 7;
                CP_ASYNC16(kB + nb * 8192 + qoff(r, cu),
                           Kb + (long)((c + 1) * 64 + r) * (3 * D_) + cu * 8);
                CP_ASYNC16(vB + nb * 8192 + qoff(r, cu),
                           Vb + (long)((c + 1) * 64 + r) * (3 * D_) + cu * 8);
            }
            CP_COMMIT();
            CP_WAIT1();
        } else {
            CP_WAIT0();
        }
        __syncthreads();

        uint32_t kBuf = kB + buf * 8192, vBuf = vB + buf * 8192;
        float sv[8][4];
#pragma unroll
        for (int ni = 0; ni < 8; ni++)
#pragma unroll
            for (int r = 0; r < 4; r++) sv[ni][r] = 0.f;
#pragma unroll
        for (int ks = 0; ks < 4; ks++) {
            uint32_t af[4], bf[8][2];
            int am = wm + (q2 & 1) * 8 + r7;
            LDSM_X4(af[0], af[1], af[2], af[3], qB + qoff(am, 2 * ks + (q2 >> 1)));
#pragma unroll
            for (int nj = 0; nj < 4; nj++) {
                int bn = nj * 16 + (q2 >> 1) * 8 + r7;
                LDSM_X4(bf[2 * nj][0], bf[2 * nj][1], bf[2 * nj + 1][0], bf[2 * nj + 1][1],
                        kBuf + qoff(bn, 2 * ks + (q2 & 1)));
            }
#pragma unroll
            for (int ni = 0; ni < 8; ni++) mma16(sv[ni], af, bf[ni]);
        }

        float cm0 = -1e30f, cm1 = -1e30f;
#pragma unroll
        for (int ni = 0; ni < 8; ni++) {
            cm0 = fmaxf(cm0, fmaxf(sv[ni][0], sv[ni][1]));
            cm1 = fmaxf(cm1, fmaxf(sv[ni][2], sv[ni][3]));
        }
        cm0 = fmaxf(cm0, __shfl_xor_sync(0xffffffffu, cm0, 1));
        cm0 = fmaxf(cm0, __shfl_xor_sync(0xffffffffu, cm0, 2));
        cm1 = fmaxf(cm1, __shfl_xor_sync(0xffffffffu, cm1, 1));
        cm1 = fmaxf(cm1, __shfl_xor_sync(0xffffffffu, cm1, 2));
        float mn0 = fmaxf(m0, cm0), mn1 = fmaxf(m1, cm1);
        float sc0 = exp2f((m0 - mn0) * L2E), sc1 = exp2f((m1 - mn1) * L2E);
        m0 = mn0; m1 = mn1;
        l0 *= sc0; l1 *= sc1;
#pragma unroll
        for (int ni = 0; ni < 8; ni++) {
            o[ni][0] *= sc0; o[ni][1] *= sc0;
            o[ni][2] *= sc1; o[ni][3] *= sc1;
        }
        uint32_t pa[4][4];
        float rs0 = 0.f, rs1 = 0.f;
#pragma unroll
        for (int ni = 0; ni < 8; ni++) {
            float p0 = exp2f((sv[ni][0] - mn0) * L2E);
            float p1 = exp2f((sv[ni][1] - mn0) * L2E);
            float p2 = exp2f((sv[ni][2] - mn1) * L2E);
            float p3 = exp2f((sv[ni][3] - mn1) * L2E);
            rs0 += p0 + p1; rs1 += p2 + p3;
            int kk = ni >> 1, hi = ni & 1;
            pa[kk][hi * 2]     = h2_as_u32(__floats2half2_rn(p0, p1));
            pa[kk][hi * 2 + 1] = h2_as_u32(__floats2half2_rn(p2, p3));
        }
        rs0 += __shfl_xor_sync(0xffffffffu, rs0, 1);
        rs0 += __shfl_xor_sync(0xffffffffu, rs0, 2);
        rs1 += __shfl_xor_sync(0xffffffffu, rs1, 1);
        rs1 += __shfl_xor_sync(0xffffffffu, rs1, 2);
        l0 += rs0; l1 += rs1;

        // O += P @ V : B-fragments of V^T via ldmatrix.trans on V tiles
#pragma unroll
        for (int ks = 0; ks < 4; ks++) {
            uint32_t bf[8][2];
#pragma unroll
            for (int nj = 0; nj < 4; nj++) {
                int vrow = 16 * ks + (q2 & 1) * 8 + r7;   // key index
                int vchk = nj * 2 + (q2 >> 1);            // dh 16B-chunk
                LDSM_X4_T(bf[2 * nj][0], bf[2 * nj][1], bf[2 * nj + 1][0], bf[2 * nj + 1][1],
                          vBuf + qoff(vrow, vchk));
            }
#pragma unroll
            for (int ni = 0; ni < 8; ni++) mma16(o[ni], pa[ks], bf[ni]);
        }
        __syncthreads();   // load-bearing: refill is issued BEFORE the wait here
    }

    float li0 = 1.f / l0, li1 = 1.f / l1;
    long row0 = (long)b * S_ + qb * 128 + wm + g;
    __half* c0p = ctx + (row0)     * D_ + hh * DH_;
    __half* c1p = ctx + (row0 + 8) * D_ + hh * DH_;
#pragma unroll
    for (int ni = 0; ni < 8; ni++) {
        int nc = ni * 8 + tq * 2;
        *(__half2*)(c0p + nc) = __floats2half2_rn(o[ni][0] * li0, o[ni][1] * li0);
        *(__half2*)(c1p + nc) = __floats2half2_rn(o[ni][2] * li1, o[ni][3] * li1);
    }
}

// ---------------- fp16 GEMM: 128x128 tile, BK=64, 3 stages, 2 CTAs/SM -------
template <bool BI, bool RE, bool HOUT>
__global__ void __launch_bounds__(256, 2) gemm_h(
    const __half* __restrict__ A, const __half* __restrict__ Bm, void* __restrict__ C,
    const float* __restrict__ bias, const float* __restrict__ resid,
    int Kd, int lda, int ldb, int ldc) {
    constexpr int STAGE = 32768, BOFF = 16384;
    extern __shared__ __align__(16) char smdyn[];
    uint32_t sb = smem_u32(smdyn);

    int tid = threadIdx.x, lane = tid & 31, warp = tid >> 5;
    int bm = blockIdx.y * 128, bn = blockIdx.x * 128;
    int wm = (warp % 4) * 32, wn = (warp / 4) * 64;
    int g = lane >> 2, tq = lane & 3;
    int q2 = lane >> 3, r7 = lane & 7;

    float acc[2][8][4];
#pragma unroll
    for (int mi = 0; mi < 2; mi++)
#pragma unroll
        for (int ni = 0; ni < 8; ni++)
#pragma unroll
            for (int r = 0; r < 4; r++) acc[mi][ni][r] = 0.f;

    int NC = Kd >> 6;
#define GH_ISSUE(st, k0)                                                              \
    do {                                                                              \
        uint32_t _as = sb + (st) * STAGE, _bs = _as + BOFF;                           \
        _Pragma("unroll")                                                             \
        for (int j = 0; j < 4; j++) {                                                 \
            int s = tid + 256 * j; int r = s >> 3, cu = s & 7;                        \
            CP_ASYNC16(_as + qoff(r, cu), A + (long)(bm + r) * lda + (k0) + cu * 8);  \
            CP_ASYNC16(_bs + qoff(r, cu), Bm + (long)(bn + r) * ldb + (k0) + cu * 8); \
        }                                                                             \
    } while (0)

    GH_ISSUE(0, 0); CP_COMMIT();
    GH_ISSUE(1, 64); CP_COMMIT();

    for (int ck = 0; ck < NC; ck++) {
        CP_WAIT1();
        __syncthreads();
        if (ck + 2 < NC) { int st = (ck + 2) % 3; GH_ISSUE(st, (ck + 2) << 6); }
        CP_COMMIT();
        uint32_t aBase = sb + (ck % 3) * STAGE, bBase = aBase + BOFF;
#pragma unroll
        for (int s = 0; s < 4; s++) {
            uint32_t af[2][4], bf[8][2];
#pragma unroll
            for (int mi = 0; mi < 2; mi++) {
                int m = wm + mi * 16 + (q2 & 1) * 8 + r7;
                LDSM_X4(af[mi][0], af[mi][1], af[mi][2], af[mi][3],
                        aBase + qoff(m, 2 * s + (q2 >> 1)));
            }
#pragma unroll
            for (int nj = 0; nj < 4; nj++) {
                int n = wn + nj * 16 + (q2 >> 1) * 8 + r7;
                LDSM_X4(bf[2 * nj][0], bf[2 * nj][1], bf[2 * nj + 1][0], bf[2 * nj + 1][1],
                        bBase + qoff(n, 2 * s + (q2 & 1)));
            }
#pragma unroll
            for (int mi = 0; mi < 2; mi++)
#pragma unroll
                for (int ni = 0; ni < 8; ni++)
                    mma16(acc[mi][ni], af[mi], bf[ni]);
        }
        // no tail sync: next iteration's top sync protects the stage rotation
    }
#undef GH_ISSUE

    __half* Ch = (__half*)C;
    float*  Cf = (float*)C;
#pragma unroll
    for (int mi = 0; mi < 2; mi++) {
#pragma unroll
        for (int rh = 0; rh < 2; rh++) {
            int row = bm + wm + mi * 16 + g + rh * 8;
#pragma unroll
            for (int ni = 0; ni < 8; ni++) {
                int n = bn + wn + ni * 8 + tq * 2;
                float v0 = acc[mi][ni][rh * 2], v1 = acc[mi][ni][rh * 2 + 1];
                if (BI) { v0 += bias[n]; v1 += bias[n + 1]; }
                if (HOUT) {
                    *(__half2*)(Ch + (long)row * ldc + n) = __floats2half2_rn(v0, v1);
                } else {
                    if (RE) {
                        float2 rv = *(const float2*)(resid + (long)row * ldc + n);
                        v0 += rv.x; v1 += rv.y;
                    }
                    float2 ov; ov.x = v0; ov.y = v1;
                    *(float2*)(Cf + (long)row * ldc + n) = ov;
                }
            }
        }
    }
}

// ---------------- MoE up: indexed-A grouped GEMM, GELU*gate epilogue --------
__global__ void __launch_bounds__(256, 2) gemm_up(
    const __half* __restrict__ Ah, const __half* __restrict__ w1t,
    __half* __restrict__ uws, const float* __restrict__ b1,
    const float* __restrict__ gd, const int* __restrict__ rowidx,
    const int* __restrict__ cnt) {
    constexpr int STAGE = 32768, BOFF = 16384;
    extern __shared__ __align__(16) char smdyn[];
    uint32_t sb = smem_u32(smdyn);

    int e = blockIdx.z;
    int c = cnt[e];
    int cp = (c + 127) & ~127;
    int bm = blockIdx.y * 128;
    if (bm >= cp) return;
    int bn = blockIdx.x * 128;

    int tid = threadIdx.x, lane = tid & 31, warp = tid >> 5;
    int wm = (warp % 4) * 32, wn = (warp / 4) * 64;
    int g = lane >> 2, tq = lane & 3;
    int q2 = lane >> 3, r7 = lane & 7;
    const __half* Bp = w1t + (long)e * (H_ * D_);
    const int* ridx = rowidx + (long)e * CAP_;

    int tokA[4];
#pragma unroll
    for (int j = 0; j < 4; j++) {
        int r = (tid + 256 * j) >> 3;
        tokA[j] = ridx[bm + r];
    }

    float acc[2][8][4];
#pragma unroll
    for (int mi = 0; mi < 2; mi++)
#pragma unroll
        for (int ni = 0; ni < 8; ni++)
#pragma unroll
            for (int r = 0; r < 4; r++) acc[mi][ni][r] = 0.f;

#define UP_ISSUE(st, k0)                                                              \
    do {                                                                              \
        uint32_t _as = sb + (st) * STAGE, _bs = _as + BOFF;                           \
        _Pragma("unroll")                                                             \
        for (int j = 0; j < 4; j++) {                                                 \
            int s = tid + 256 * j; int r = s >> 3, cu = s & 7;                        \
            CP_ASYNC16(_as + qoff(r, cu), Ah + (long)tokA[j] * D_ + (k0) + cu * 8);   \
            CP_ASYNC16(_bs + qoff(r, cu), Bp + (long)(bn + r) * D_ + (k0) + cu * 8);  \
        }                                                                             \
    } while (0)

    UP_ISSUE(0, 0); CP_COMMIT();
    UP_ISSUE(1, 64); CP_COMMIT();

    for (int ck = 0; ck < 16; ck++) {
        CP_WAIT1();
        __syncthreads();
        if (ck + 2 < 16) { int st = (ck + 2) % 3; UP_ISSUE(st, (ck + 2) << 6); }
        CP_COMMIT();
        uint32_t aBase = sb + (ck % 3) * STAGE, bBase = aBase + BOFF;
#pragma unroll
        for (int s = 0; s < 4; s++) {
            uint32_t af[2][4], bf[8][2];
#pragma unroll
            for (int mi = 0; mi < 2; mi++) {
                int m = wm + mi * 16 + (q2 & 1) * 8 + r7;
                LDSM_X4(af[mi][0], af[mi][1], af[mi][2], af[mi][3],
                        aBase + qoff(m, 2 * s + (q2 >> 1)));
            }
#pragma unroll
            for (int nj = 0; nj < 4; nj++) {
                int n = wn + nj * 16 + (q2 >> 1) * 8 + r7;
                LDSM_X4(bf[2 * nj][0], bf[2 * nj][1], bf[2 * nj + 1][0], bf[2 * nj + 1][1],
                        bBase + qoff(n, 2 * s + (q2 & 1)));
            }
#pragma unroll
            for (int mi = 0; mi < 2; mi++)
#pragma unroll
                for (int ni = 0; ni < 8; ni++)
                    mma16(acc[mi][ni], af[mi], bf[ni]);
        }
        // no tail sync (see gemm_h)
    }
#undef UP_ISSUE

    const float* b1e = b1 + (long)e * H_;
#pragma unroll
    for (int mi = 0; mi < 2; mi++) {
#pragma unroll
        for (int rh = 0; rh < 2; rh++) {
            int row = bm + wm + mi * 16 + g + rh * 8;
            int tok = ridx[row];
            float gv = gd[(long)tok * 16 + e];
            __half* orow = uws + ((long)e * CAP_ + row) * H_;
#pragma unroll
            for (int ni = 0; ni < 8; ni++) {
                int n = bn + wn + ni * 8 + tq * 2;
                float v0 = gelu_f(acc[mi][ni][rh * 2]     + b1e[n])     * gv;
                float v1 = gelu_f(acc[mi][ni][rh * 2 + 1] + b1e[n + 1]) * gv;
                *(__half2*)(orow + n) = __floats2half2_rn(v0, v1);
            }
        }
    }
}

// ---------------- MoE down: grouped GEMM, K=256 -----------------------------
__global__ void __launch_bounds__(256, 2) gemm_dn(
    const __half* __restrict__ uws, const __half* __restrict__ w2te,
    __half* __restrict__ outs, const int* __restrict__ cnt) {
    constexpr int STAGE = 32768, BOFF = 16384;
    extern __shared__ __align__(16) char smdyn[];
    uint32_t sb = smem_u32(smdyn);

    int e = blockIdx.z;
    int c = cnt[e];
    int cp = (c + 127) & ~127;
    int bm = blockIdx.y * 128;
    if (bm >= cp) return;
    int bn = blockIdx.x * 128;

    int tid = threadIdx.x, lane = tid & 31, warp = tid >> 5;
    int wm = (warp % 4) * 32, wn = (warp / 4) * 64;
    int g = lane >> 2, tq = lane & 3;
    int q2 = lane >> 3, r7 = lane & 7;
    const __half* Ap = uws + (long)e * CAP_ * H_;
    const __half* Bp = w2te + (long)e * (D_ * H_);

    float acc[2][8][4];
#pragma unroll
    for (int mi = 0; mi < 2; mi++)
#pragma unroll
        for (int ni = 0; ni < 8; ni++)
#pragma unroll
            for (int r = 0; r < 4; r++) acc[mi][ni][r] = 0.f;

#define DN_ISSUE(st, k0)                                                              \
    do {                                                                              \
        uint32_t _as = sb + (st) * STAGE, _bs = _as + BOFF;                           \
        _Pragma("unroll")                                                             \
        for (int j = 0; j < 4; j++) {                                                 \
            int s = tid + 256 * j; int r = s >> 3, cu = s & 7;                        \
            CP_ASYNC16(_as + qoff(r, cu), Ap + (long)(bm + r) * H_ + (k0) + cu * 8);  \
            CP_ASYNC16(_bs + qoff(r, cu), Bp + (long)(bn + r) * H_ + (k0) + cu * 8);  \
        }                                                                             \
    } while (0)

    DN_ISSUE(0, 0); CP_COMMIT();
    DN_ISSUE(1, 64); CP_COMMIT();

    for (int ck = 0; ck < 4; ck++) {
        CP_WAIT1();
        __syncthreads();
        if (ck + 2 < 4) { int st = (ck + 2) % 3; DN_ISSUE(st, (ck + 2) << 6); }
        CP_COMMIT();
        uint32_t aBase = sb + (ck % 3) * STAGE, bBase = aBase + BOFF;
#pragma unroll
        for (int s = 0; s < 4; s++) {
            uint32_t af[2][4], bf[8][2];
#pragma unroll
            for (int mi = 0; mi < 2; mi++) {
                int m = wm + mi * 16 + (q2 & 1) * 8 + r7;
                LDSM_X4(af[mi][0], af[mi][1], af[mi][2], af[mi][3],
                        aBase + qoff(m, 2 * s + (q2 >> 1)));
            }
#pragma unroll
            for (int nj = 0; nj < 4; nj++) {
                int n = wn + nj * 16 + (q2 >> 1) * 8 + r7;
                LDSM_X4(bf[2 * nj][0], bf[2 * nj][1], bf[2 * nj + 1][0], bf[2 * nj + 1][1],
                        bBase + qoff(n, 2 * s + (q2 & 1)));
            }
#pragma unroll
            for (int mi = 0; mi < 2; mi++)
#pragma unroll
                for (int ni = 0; ni < 8; ni++)
                    mma16(acc[mi][ni], af[mi], bf[ni]);
        }
        // no tail sync (see gemm_h)
    }
#undef DN_ISSUE

#pragma unroll
    for (int mi = 0; mi < 2; mi++) {
#pragma unroll
        for (int rh = 0; rh < 2; rh++) {
            int row = bm + wm + mi * 16 + g + rh * 8;
            __half* orow = outs + ((long)e * CAP_ + row) * D_;
#pragma unroll
            for (int ni = 0; ni < 8; ni++) {
                int n = bn + wn + ni * 8 + tq * 2;
                *(__half2*)(orow + n) =
                    __floats2half2_rn(acc[mi][ni][rh * 2], acc[mi][ni][rh * 2 + 1]);
            }
        }
    }
}

// ---------------- gate v2: smem-cached gate matrix, 128 tokens/block --------
__global__ void __launch_bounds__(256) gate_v2(
    const __half* __restrict__ h3, const float* __restrict__ gate_w,
    const int* __restrict__ task_id,
    float* __restrict__ probs, float* __restrict__ gate_dense) {
    extern __shared__ float gwT[];   // [16][1024]
    const float* gw = gate_w + (long)(*task_id) * (D_ * E_);
    int tid = threadIdx.x;
#pragma unroll 8
    for (int j = 0; j < 64; j++) {
        int idx = tid + 256 * j;
        int d = idx >> 4, e = idx & 15;
        gwT[e * 1024 + d] = gw[idx];
    }
    __syncthreads();
    int warp = tid >> 5, lane = tid & 31;
    for (int i = 0; i < 16; i++) {
        long tok = (long)blockIdx.x * 128 + i * 8 + warp;
        const __half* hrow = h3 + tok * D_;
        float acc[16];
#pragma unroll
        for (int e = 0; e < 16; e++) acc[e] = 0.f;
#pragma unroll
        for (int j = 0; j < 8; j++) {
            int d0 = (j * 32 + lane) * 4;
            __half2 a = *(const __half2*)(hrow + d0);
            __half2 b = *(const __half2*)(hrow + d0 + 2);
            float2 fa = __half22float2(a), fb = __half22float2(b);
#pragma unroll
            for (int e = 0; e < 16; e++) {
                float4 g4 = *(const float4*)&gwT[e * 1024 + d0];
                acc[e] += fa.x * g4.x + fa.y * g4.y + fb.x * g4.z + fb.y * g4.w;
            }
        }
#pragma unroll
        for (int e = 0; e < 16; e++) {
#pragma unroll
            for (int o = 16; o; o >>= 1)
                acc[e] += __shfl_xor_sync(0xffffffffu, acc[e], o);
        }
        if (lane == 0) {
            float mx = -1e30f;
#pragma unroll
            for (int e = 0; e < 16; e++) mx = fmaxf(mx, acc[e]);
            float sum = 0.f;
#pragma unroll
            for (int e = 0; e < 16; e++) { acc[e] = expf(acc[e] - mx); sum += acc[e]; }
            float inv = 1.f / sum;
            float p[16];
#pragma unroll
            for (int e = 0; e < 16; e++) { p[e] = acc[e] * inv; probs[tok * 16 + e] = p[e]; }
            bool used[16];
#pragma unroll
            for (int e = 0; e < 16; e++) used[e] = false;
            int tix[8]; float tvl[8]; float gsum = 0.f;
            for (int kk = 0; kk < 8; kk++) {
                float best = -1.f; int bi = 0;
                for (int e = 0; e < 16; e++)
                    if (!used[e] && p[e] > best) { best = p[e]; bi = e; }
                used[bi] = true; tix[kk] = bi; tvl[kk] = best; gsum += best;
            }
            float ginv = 1.f / (gsum + 1e-6f);
            float gdv[16];
#pragma unroll
            for (int e = 0; e < 16; e++) gdv[e] = 0.f;
            for (int kk = 0; kk < 8; kk++) gdv[tix[kk]] = tvl[kk] * ginv;
#pragma unroll
            for (int e = 0; e < 16; e++) gate_dense[tok * 16 + e] = gdv[e];
        }
    }
}

// ---------------- routing ----------------------------------------------------
__global__ void route_k(const float* __restrict__ gd, int* __restrict__ cnt,
                        int* __restrict__ rowidx, int* __restrict__ pairpos) {
    int t = blockIdx.x * 128 + threadIdx.x;
    int k = 0;
#pragma unroll
    for (int e = 0; e < E_; e++) {
        float v = gd[(long)t * 16 + e];
        if (v > 0.f && k < 8) {
            int pos = atomicAdd(&cnt[e], 1);
            rowidx[(long)e * CAP_ + pos] = t;
            pairpos[(long)t * 8 + k] = e * CAP_ + pos;
            k++;
        }
    }
}

// ---------------- gather: 2 tokens/block ------------------------------------
__global__ void __launch_bounds__(512) gather_k(
    const float* __restrict__ x, const __half* __restrict__ outs,
    const int* __restrict__ pairpos, const float* __restrict__ gd,
    const float* __restrict__ b2, float* __restrict__ out) {
    int half_ = threadIdx.x >> 8;
    int tid = threadIdx.x & 255;
    long t = (long)blockIdx.x * 2 + half_;
    __shared__ int pp[2][8];
    __shared__ float gdv[2][16];
    if (tid < 8) pp[half_][tid] = pairpos[t * 8 + tid];
    if (tid < 16) gdv[half_][tid] = gd[t * 16 + tid];
    __syncthreads();
    int d = tid * 4;
    float4 a = *(const float4*)(x + t * D_ + d);
#pragma unroll
    for (int k = 0; k < 8; k++) {
        const __half2* o2 = (const __half2*)(outs + (long)pp[half_][k] * D_ + d);
        float2 f0 = __half22float2(o2[0]), f1 = __half22float2(o2[1]);
        a.x += f0.x; a.y += f0.y; a.z += f1.x; a.w += f1.y;
    }
#pragma unroll
    for (int e = 0; e < 16; e++) {
        float4 bv = *(const float4*)(b2 + (long)e * D_ + d);
        float gv = gdv[half_][e];
        a.x += gv * bv.x; a.y += gv * bv.y; a.z += gv * bv.z; a.w += gv * bv.w;
    }
    *(float4*)(out + t * D_ + d) = a;
}

// ---------------- aux loss: 64 deterministic partials + final ----------------
__global__ void aux_part(const float* __restrict__ probs, float* __restrict__ part) {
    int b = blockIdx.x, tid = threadIdx.x;
    const float* p = probs + ((long)b * 256 + tid) * 16;
    float v[16];
#pragma unroll
    for (int e = 0; e < 16; e++) v[e] = p[e];
    __shared__ float red[256][17];
#pragma unroll
    for (int e = 0; e < 16; e++) red[tid][e] = v[e];
    __syncthreads();
    for (int s = 128; s; s >>= 1) {
        if (tid < s) {
#pragma unroll
            for (int e = 0; e < 16; e++) red[tid][e] += red[tid + s][e];
        }
        __syncthreads();
    }
    if (tid == 0) {
#pragma unroll
        for (int e = 0; e < 16; e++) part[b * 16 + e] = red[0][e];
    }
}
__global__ void aux_fin(const float* __restrict__ part, float* __restrict__ outv) {
    if (threadIdx.x == 0) {
        float aux = 0.f;
        for (int e = 0; e < 16; e++) {
            float s = 0.f;
            for (int b = 0; b < 64; b++) s += part[b * 16 + e];
            float mp = s * (1.f / T_);
            aux += mp * logf(mp + 1e-6f);
        }
        outv[0] = 5e-4f * aux;
    }
}

// ---------------- launch -----------------------------------------------------
extern "C" void kernel_launch(void* const* d_in, const int* in_sizes, int n_in,
                              void* d_out, int out_size) {
    const float* tgt        = (const float*)d_in[0];
    const float* ln1_g      = (const float*)d_in[2];
    const float* ln1_b      = (const float*)d_in[3];
    const float* ln3_g      = (const float*)d_in[4];
    const float* ln3_b      = (const float*)d_in[5];
    const float* in_proj_w  = (const float*)d_in[6];
    const float* in_proj_b  = (const float*)d_in[7];
    const float* out_proj_w = (const float*)d_in[8];
    const float* out_proj_b = (const float*)d_in[9];
    const float* gate_w     = (const float*)d_in[10];
    const float* w1         = (const float*)d_in[11];
    const float* b1         = (const float*)d_in[12];
    const float* w2         = (const float*)d_in[13];
    const float* b2         = (const float*)d_in[14];
    const int*   task_id    = (const int*)d_in[15];

    float* out       = (float*)d_out;
    float* out_x     = out;
    float* out_aux   = out + (size_t)T_ * D_;
    float* out_probs = out_aux + 1;

    __half *h16, *qkv16, *ctx16, *wi16, *wo16, *w1t16, *w2te16, *uws, *outs;
    float *x, *gd, *auxp;
    int *cnt, *rowidx, *pairpos;
    cudaGetSymbolAddress((void**)&h16,    g_h16);
    cudaGetSymbolAddress((void**)&qkv16,  g_qkv16);
    cudaGetSymbolAddress((void**)&ctx16,  g_ctx16);
    cudaGetSymbolAddress((void**)&x,      g_x);
    cudaGetSymbolAddress((void**)&gd,     g_gate);
    cudaGetSymbolAddress((void**)&wi16,   g_wi16);
    cudaGetSymbolAddress((void**)&wo16,   g_wo16);
    cudaGetSymbolAddress((void**)&w1t16,  g_w1t16);
    cudaGetSymbolAddress((void**)&w2te16, g_w2te16);
    cudaGetSymbolAddress((void**)&uws,    g_uws);
    cudaGetSymbolAddress((void**)&outs,   g_outs);
    cudaGetSymbolAddress((void**)&cnt,    g_cnt);
    cudaGetSymbolAddress((void**)&rowidx, g_rowidx);
    cudaGetSymbolAddress((void**)&pairpos,g_pairpos);
    cudaGetSymbolAddress((void**)&auxp,   g_auxp);

    const int GSM = 3 * 32768;      // 98304
    const int GATESM = 65536;
    cudaFuncSetAttribute(gemm_h<true, false, true >, cudaFuncAttributeMaxDynamicSharedMemorySize, GSM);
    cudaFuncSetAttribute(gemm_h<true, true,  false>, cudaFuncAttributeMaxDynamicSharedMemorySize, GSM);
    cudaFuncSetAttribute(gemm_up, cudaFuncAttributeMaxDynamicSharedMemorySize, GSM);
    cudaFuncSetAttribute(gemm_dn, cudaFuncAttributeMaxDynamicSharedMemorySize, GSM);
    cudaFuncSetAttribute(gate_v2, cudaFuncAttributeMaxDynamicSharedMemorySize, GATESM);

    // 0. weight preprocessing (merged converts + cnt zero) and transposes
    conv2_k<<<(unsigned)(4L * D_ * D_ / 1024), 256>>>(
        in_proj_w, wi16, 3L * D_ * D_, out_proj_w, wo16, cnt);
    transpose_h<float><<<dim3(8, 32, E_), 256>>>(
        w1, w1t16, D_, H_, H_, (long)D_ * H_, 0, (long)H_ * D_, 0, 1);
    transpose_h<float><<<dim3(32, 8, E_), 256>>>(
        w2, w2te16, H_, D_, D_, (long)H_ * D_, 0, (long)D_ * H_, 0, 1);

    // 1. h = LN1(tgt)
    ln_kernel<<<T_, 256>>>(tgt, ln1_g, ln1_b, h16);

    // 2. qkv = h @ in_proj_w^T + b (half out)
    gemm_h<true, false, true><<<dim3(24, 128), 256, GSM>>>(
        h16, wi16, qkv16, in_proj_b, nullptr, D_, D_, D_, 3 * D_);

    // 3. fused flash attention (direct V) -> ctx16
    flash_k<<<dim3(4, B_ * NH_), 256>>>(qkv16, ctx16);

    // 4. x = tgt + ctx @ out_proj_w^T + b (fp32 out)
    gemm_h<true, true, false><<<dim3(8, 128), 256, GSM>>>(
        ctx16, wo16, x, out_proj_b, tgt, D_, D_, D_, D_);

    // 5. h3 = LN3(x)
    ln_kernel<<<T_, 256>>>(x, ln3_g, ln3_b, h16);

    // 6. gate / aux
    gate_v2<<<T_ / 128, 256, GATESM>>>(h16, gate_w, task_id, out_probs, gd);
    aux_part<<<64, 256>>>(out_probs, auxp);
    aux_fin<<<1, 32>>>(auxp, out_aux);

    // 7. routing (cnt zeroed in conv2_k at graph start; re-zeroed each replay)
    route_k<<<T_ / 128, 128>>>(gd, cnt, rowidx, pairpos);

    // 8. sparse MoE up
    gemm_up<<<dim3(2, 128, E_), 256, GSM>>>(h16, w1t16, uws, b1, gd, rowidx, cnt);

    // 9. sparse MoE down
    gemm_dn<<<dim3(8, 128, E_), 256, GSM>>>(uws, w2te16, outs, cnt);

    // 10. gather: out = x + sum_k outs + gd @ b2
    gather_k<<<T_ / 2, 512>>>(x, outs, pairpos, gd, b2, out_x);

    (void)in_sizes; (void)n_in; (void)out_size;
}

// round 15
// speedup vs baseline: 1.0709x; 1.0002x over previous
#include <cuda_runtime.h>
#include <cuda_fp16.h>
#include <math.h>
#include <stdint.h>

#define B_   32
#define S_   512
#define D_   1024
#define NH_  16
#define E_   16
#define H_   256
#define DH_  64
#define T_   (B_ * S_)          // 16384
#define CAP_ 16384

// ---------------- scratch (static device memory) ---------------------------
__device__ __half g_h16[(size_t)T_ * D_];
__device__ __half g_qkv16[(size_t)T_ * 3 * D_];
__device__ __half g_ctx16[(size_t)T_ * D_];
__device__ float  g_x[(size_t)T_ * D_];
__device__ float  g_gate[(size_t)T_ * E_];
__device__ __half g_wi16[(size_t)3 * D_ * D_];
__device__ __half g_wo16[(size_t)D_ * D_];
__device__ __half g_w1t16[(size_t)E_ * H_ * D_];
__device__ __half g_w2te16[(size_t)E_ * D_ * H_];
__device__ __half g_uws[(size_t)E_ * CAP_ * H_];
__device__ __half g_outs[(size_t)E_ * CAP_ * D_];
__device__ int    g_cnt[E_];
__device__ int    g_rowidx[(size_t)E_ * CAP_];
__device__ int    g_pairpos[(size_t)T_ * 8];
__device__ float  g_auxp[64 * E_];

// ---------------- helpers ---------------------------------------------------
__device__ __forceinline__ uint32_t smem_u32(const void* p) {
    uint32_t a;
    asm("{ .reg .u64 t; cvta.to.shared.u64 t, %1; cvt.u32.u64 %0, t; }" : "=r"(a) : "l"(p));
    return a;
}
__device__ __forceinline__ uint32_t h2_as_u32(__half2 h) {
    return *reinterpret_cast<uint32_t*>(&h);
}
#define CP_ASYNC16(dst, src) \
    asm volatile("cp.async.ca.shared.global [%0], [%1], 16;" :: "r"(dst), "l"(src) : "memory")
#define CP_COMMIT() asm volatile("cp.async.commit_group;" ::: "memory")
#define CP_WAIT1()  asm volatile("cp.async.wait_group 1;" ::: "memory")
#define CP_WAIT0()  asm volatile("cp.async.wait_group 0;" ::: "memory")

#define LDSM_X4(r0, r1, r2, r3, addr) \
    asm volatile("ldmatrix.sync.aligned.m8n8.x4.shared.b16 {%0,%1,%2,%3}, [%4];" \
        : "=r"(r0), "=r"(r1), "=r"(r2), "=r"(r3) : "r"(addr))
#define LDSM_X4_T(r0, r1, r2, r3, addr) \
    asm volatile("ldmatrix.sync.aligned.m8n8.x4.trans.shared.b16 {%0,%1,%2,%3}, [%4];" \
        : "=r"(r0), "=r"(r1), "=r"(r2), "=r"(r3) : "r"(addr))

__device__ __forceinline__ void mma16(float* d, const uint32_t* a, const uint32_t* b) {
    asm volatile(
        "mma.sync.aligned.m16n8k16.row.col.f32.f16.f16.f32 "
        "{%0,%1,%2,%3},{%4,%5,%6,%7},{%8,%9},{%0,%1,%2,%3};"
        : "+f"(d[0]), "+f"(d[1]), "+f"(d[2]), "+f"(d[3])
        : "r"(a[0]), "r"(a[1]), "r"(a[2]), "r"(a[3]), "r"(b[0]), "r"(b[1]));
}

// smem tile: 64 halfs (128B) per row, SW128
__device__ __forceinline__ uint32_t qoff(int m, int c) {
    return (uint32_t)(m * 128 + ((c ^ (m & 7)) << 4));
}
__device__ __forceinline__ float gelu_f(float v) {
    return 0.5f * v * (1.f + erff(v * 0.70710678118654752f));
}

// ---------------- LayerNorm: 2 rows per 512-thread block --------------------
__global__ void __launch_bounds__(512) ln_kernel(
    const float* __restrict__ x, const float* __restrict__ g,
    const float* __restrict__ b, __half* __restrict__ y16) {
    int half_ = threadIdx.x >> 8;
    int tid = threadIdx.x & 255;
    long t = (long)blockIdx.x * 2 + half_;
    const float* row = x + t * D_;
    float4 v = *(const float4*)(row + tid * 4);
    float s = v.x + v.y + v.z + v.w;
    float sq = v.x * v.x + v.y * v.y + v.z * v.z + v.w * v.w;
#pragma unroll
    for (int o = 16; o; o >>= 1) {
        s  += __shfl_xor_sync(0xffffffffu, s, o);
        sq += __shfl_xor_sync(0xffffffffu, sq, o);
    }
    __shared__ float ws[16], wq[16];
    int w = threadIdx.x >> 5, l = threadIdx.x & 31;
    if (l == 0) { ws[w] = s; wq[w] = sq; }
    __syncthreads();
    if (tid == 0) {
        float a = 0.f, c = 0.f;
        for (int i = 0; i < 8; i++) { a += ws[half_ * 8 + i]; c += wq[half_ * 8 + i]; }
        ws[half_ * 8] = a; wq[half_ * 8] = c;
    }
    __syncthreads();
    float mean = ws[half_ * 8] * (1.f / D_);
    float var  = wq[half_ * 8] * (1.f / D_) - mean * mean;
    float inv  = rsqrtf(var + 1e-5f);
    int d = tid * 4;
    float4 gv = *(const float4*)(g + d);
    float4 bv = *(const float4*)(b + d);
    __half2 o0 = __floats2half2_rn((v.x - mean) * inv * gv.x + bv.x,
                                   (v.y - mean) * inv * gv.y + bv.y);
    __half2 o1 = __floats2half2_rn((v.z - mean) * inv * gv.z + bv.z,
                                   (v.w - mean) * inv * gv.w + bv.w);
    *(__half2*)(y16 + t * D_ + d)     = o0;
    *(__half2*)(y16 + t * D_ + d + 2) = o1;
}

// ---------------- fused fp32->fp16 convert (2 tensors) + cnt zero -----------
__global__ void conv2_k(const float* __restrict__ a, __half* __restrict__ oa, long na,
                        const float* __restrict__ b, __half* __restrict__ ob,
                        int* __restrict__ cnt) {
    if (blockIdx.x == 0 && threadIdx.x < E_) cnt[threadIdx.x] = 0;
    long i = (long)blockIdx.x * 1024 + threadIdx.x * 4;
    if (i < na) {
        float4 v = *(const float4*)(a + i);
        *(__half2*)(oa + i)     = __floats2half2_rn(v.x, v.y);
        *(__half2*)(oa + i + 2) = __floats2half2_rn(v.z, v.w);
    } else {
        long j = i - na;
        float4 v = *(const float4*)(b + j);
        *(__half2*)(ob + j)     = __floats2half2_rn(v.x, v.y);
        *(__half2*)(ob + j + 2) = __floats2half2_rn(v.z, v.w);
    }
}

// ---------------- batched tiled transpose -> half ---------------------------
template <typename TI>
__global__ void transpose_h(const TI* __restrict__ src, __half* __restrict__ dst,
                            int R, int C, long srcRS,
                            long sSo, long sSi, long sDo, long sDi, int nInner) {
    int zo = blockIdx.z / nInner, zi = blockIdx.z - zo * nInner;
    src += (long)zo * sSo + (long)zi * sSi;
    dst += (long)zo * sDo + (long)zi * sDi;
    __shared__ float tile[32][33];
    int r0 = blockIdx.y * 32, c0 = blockIdx.x * 32;
    int tx = threadIdx.x & 31, ty = threadIdx.x >> 5;
#pragma unroll
    for (int k = 0; k < 4; k++) {
        int r = r0 + ty + 8 * k;
        if (r < R && c0 + tx < C) tile[ty + 8 * k][tx] = (float)src[(long)r * srcRS + c0 + tx];
    }
    __syncthreads();
#pragma unroll
    for (int k = 0; k < 4; k++) {
        int c = c0 + ty + 8 * k;
        if (c < C && r0 + tx < R) dst[(long)c * R + r0 + tx] = __float2half(tile[tx][ty + 8 * k]);
    }
}

// ---------------- fused flash attention, direct-V, 2 CTAs/SM ----------------
__global__ void __launch_bounds__(256, 2) flash_k(
    const __half* __restrict__ qkv, __half* __restrict__ ctx) {
    int bh = blockIdx.y;
    int b = bh >> 4, hh = bh & 15;
    int qb = blockIdx.x;
    const __half* Qb = qkv + ((long)b * S_ + qb * 128) * (3 * D_) + hh * DH_;
    const __half* Kb = qkv + (long)b * S_ * (3 * D_) + D_ + hh * DH_;
    const __half* Vb = qkv + (long)b * S_ * (3 * D_) + 2 * D_ + hh * DH_;

    __shared__ __align__(16) __half Qs[128 * 64];
    __shared__ __align__(16) __half Ks[2][64 * 64];
    __shared__ __align__(16) __half Vs[2][64 * 64];
    uint32_t qB = smem_u32(Qs), kB = smem_u32(Ks), vB = smem_u32(Vs);

    int tid = threadIdx.x, lane = tid & 31, warp = tid >> 5;
    int wm = warp * 16;
    int g = lane >> 2, tq = lane & 3;
    int q2 = lane >> 3, r7 = lane & 7;
    const float L2E = 1.44269504088896f;

#pragma unroll
    for (int j = 0; j < 4; j++) {
        int s = tid + 256 * j;
        int r = s >> 3, cu = s & 7;
        CP_ASYNC16(qB + qoff(r, cu), Qb + (long)r * (3 * D_) + cu * 8);
    }
    CP_COMMIT();
#pragma unroll
    for (int j = 0; j < 2; j++) {
        int s = tid + 256 * j;
        int r = s >> 3, cu = s & 7;
        CP_ASYNC16(kB + qoff(r, cu), Kb + (long)r * (3 * D_) + cu * 8);
        CP_ASYNC16(vB + qoff(r, cu), Vb + (long)r * (3 * D_) + cu * 8);
    }
    CP_COMMIT();
    CP_WAIT0();
    __syncthreads();
    {
        __half2 sc = __floats2half2_rn(0.125f, 0.125f);
        __half2* qh = (__half2*)Qs;
#pragma unroll
        for (int i = 0; i < 16; i++) qh[tid + 256 * i] = __hmul2(qh[tid + 256 * i], sc);
    }
    __syncthreads();

    float o[8][4];
#pragma unroll
    for (int ni = 0; ni < 8; ni++)
#pragma unroll
        for (int r = 0; r < 4; r++) o[ni][r] = 0.f;
    float m0 = -1e30f, m1 = -1e30f, l0 = 0.f, l1 = 0.f;

    for (int c = 0; c < 8; c++) {
        int buf = c & 1;
        if (c + 1 < 8) {
            int nb = 1 - buf;
#pragma unroll
            for (int j = 0; j < 2; j++) {
                int s = tid + 256 * j;
                int r = s >> 3, cu = s & 7;
                CP_ASYNC16(kB + nb * 8192 + qoff(r, cu),
                           Kb + (long)((c + 1) * 64 + r) * (3 * D_) + cu * 8);
                CP_ASYNC16(vB + nb * 8192 + qoff(r, cu),
                           Vb + (long)((c + 1) * 64 + r) * (3 * D_) + cu * 8);
            }
            CP_COMMIT();
            CP_WAIT1();
        } else {
            CP_WAIT0();
        }
        __syncthreads();

        uint32_t kBuf = kB + buf * 8192, vBuf = vB + buf * 8192;
        float sv[8][4];
#pragma unroll
        for (int ni = 0; ni < 8; ni++)
#pragma unroll
            for (int r = 0; r < 4; r++) sv[ni][r] = 0.f;
#pragma unroll
        for (int ks = 0; ks < 4; ks++) {
            uint32_t af[4], bf[8][2];
            int am = wm + (q2 & 1) * 8 + r7;
            LDSM_X4(af[0], af[1], af[2], af[3], qB + qoff(am, 2 * ks + (q2 >> 1)));
#pragma unroll
            for (int nj = 0; nj < 4; nj++) {
                int bn = nj * 16 + (q2 >> 1) * 8 + r7;
                LDSM_X4(bf[2 * nj][0], bf[2 * nj][1], bf[2 * nj + 1][0], bf[2 * nj + 1][1],
                        kBuf + qoff(bn, 2 * ks + (q2 & 1)));
            }
#pragma unroll
            for (int ni = 0; ni < 8; ni++) mma16(sv[ni], af, bf[ni]);
        }

        float cm0 = -1e30f, cm1 = -1e30f;
#pragma unroll
        for (int ni = 0; ni < 8; ni++) {
            cm0 = fmaxf(cm0, fmaxf(sv[ni][0], sv[ni][1]));
            cm1 = fmaxf(cm1, fmaxf(sv[ni][2], sv[ni][3]));
        }
        cm0 = fmaxf(cm0, __shfl_xor_sync(0xffffffffu, cm0, 1));
        cm0 = fmaxf(cm0, __shfl_xor_sync(0xffffffffu, cm0, 2));
        cm1 = fmaxf(cm1, __shfl_xor_sync(0xffffffffu, cm1, 1));
        cm1 = fmaxf(cm1, __shfl_xor_sync(0xffffffffu, cm1, 2));
        float mn0 = fmaxf(m0, cm0), mn1 = fmaxf(m1, cm1);
        float sc0 = exp2f((m0 - mn0) * L2E), sc1 = exp2f((m1 - mn1) * L2E);
        m0 = mn0; m1 = mn1;
        l0 *= sc0; l1 *= sc1;
#pragma unroll
        for (int ni = 0; ni < 8; ni++) {
            o[ni][0] *= sc0; o[ni][1] *= sc0;
            o[ni][2] *= sc1; o[ni][3] *= sc1;
        }
        uint32_t pa[4][4];
        float rs0 = 0.f, rs1 = 0.f;
#pragma unroll
        for (int ni = 0; ni < 8; ni++) {
            float p0 = exp2f((sv[ni][0] - mn0) * L2E);
            float p1 = exp2f((sv[ni][1] - mn0) * L2E);
            float p2 = exp2f((sv[ni][2] - mn1) * L2E);
            float p3 = exp2f((sv[ni][3] - mn1) * L2E);
            rs0 += p0 + p1; rs1 += p2 + p3;
            int kk = ni >> 1, hi = ni & 1;
            pa[kk][hi * 2]     = h2_as_u32(__floats2half2_rn(p0, p1));
            pa[kk][hi * 2 + 1] = h2_as_u32(__floats2half2_rn(p2, p3));
        }
        rs0 += __shfl_xor_sync(0xffffffffu, rs0, 1);
        rs0 += __shfl_xor_sync(0xffffffffu, rs0, 2);
        rs1 += __shfl_xor_sync(0xffffffffu, rs1, 1);
        rs1 += __shfl_xor_sync(0xffffffffu, rs1, 2);
        l0 += rs0; l1 += rs1;

        // O += P @ V : B-fragments of V^T via ldmatrix.trans on V tiles
#pragma unroll
        for (int ks = 0; ks < 4; ks++) {
            uint32_t bf[8][2];
#pragma unroll
            for (int nj = 0; nj < 4; nj++) {
                int vrow = 16 * ks + (q2 & 1) * 8 + r7;   // key index
                int vchk = nj * 2 + (q2 >> 1);            // dh 16B-chunk
                LDSM_X4_T(bf[2 * nj][0], bf[2 * nj][1], bf[2 * nj + 1][0], bf[2 * nj + 1][1],
                          vBuf + qoff(vrow, vchk));
            }
#pragma unroll
            for (int ni = 0; ni < 8; ni++) mma16(o[ni], pa[ks], bf[ni]);
        }
        __syncthreads();   // load-bearing: refill is issued BEFORE the wait here
    }

    float li0 = 1.f / l0, li1 = 1.f / l1;
    long row0 = (long)b * S_ + qb * 128 + wm + g;
    __half* c0p = ctx + (row0)     * D_ + hh * DH_;
    __half* c1p = ctx + (row0 + 8) * D_ + hh * DH_;
#pragma unroll
    for (int ni = 0; ni < 8; ni++) {
        int nc = ni * 8 + tq * 2;
        *(__half2*)(c0p + nc) = __floats2half2_rn(o[ni][0] * li0, o[ni][1] * li0);
        *(__half2*)(c1p + nc) = __floats2half2_rn(o[ni][2] * li1, o[ni][3] * li1);
    }
}

// ---------------- fp16 GEMM: 128x128 tile, BK=64, 3 stages, 2 CTAs/SM -------
template <bool BI, bool RE, bool HOUT>
__global__ void __launch_bounds__(256, 2) gemm_h(
    const __half* __restrict__ A, const __half* __restrict__ Bm, void* __restrict__ C,
    const float* __restrict__ bias, const float* __restrict__ resid,
    int Kd, int lda, int ldb, int ldc) {
    constexpr int STAGE = 32768, BOFF = 16384;
    extern __shared__ __align__(16) char smdyn[];
    uint32_t sb = smem_u32(smdyn);

    int tid = threadIdx.x, lane = tid & 31, warp = tid >> 5;
    int bm = blockIdx.y * 128, bn = blockIdx.x * 128;
    int wm = (warp % 4) * 32, wn = (warp / 4) * 64;
    int g = lane >> 2, tq = lane & 3;
    int q2 = lane >> 3, r7 = lane & 7;

    float acc[2][8][4];
#pragma unroll
    for (int mi = 0; mi < 2; mi++)
#pragma unroll
        for (int ni = 0; ni < 8; ni++)
#pragma unroll
            for (int r = 0; r < 4; r++) acc[mi][ni][r] = 0.f;

    int NC = Kd >> 6;
#define GH_ISSUE(st, k0)                                                              \
    do {                                                                              \
        uint32_t _as = sb + (st) * STAGE, _bs = _as + BOFF;                           \
        _Pragma("unroll")                                                             \
        for (int j = 0; j < 4; j++) {                                                 \
            int s = tid + 256 * j; int r = s >> 3, cu = s & 7;                        \
            CP_ASYNC16(_as + qoff(r, cu), A + (long)(bm + r) * lda + (k0) + cu * 8);  \
            CP_ASYNC16(_bs + qoff(r, cu), Bm + (long)(bn + r) * ldb + (k0) + cu * 8); \
        }                                                                             \
    } while (0)

    GH_ISSUE(0, 0); CP_COMMIT();
    GH_ISSUE(1, 64); CP_COMMIT();

    for (int ck = 0; ck < NC; ck++) {
        CP_WAIT1();
        __syncthreads();
        if (ck + 2 < NC) { int st = (ck + 2) % 3; GH_ISSUE(st, (ck + 2) << 6); }
        CP_COMMIT();
        uint32_t aBase = sb + (ck % 3) * STAGE, bBase = aBase + BOFF;
#pragma unroll
        for (int s = 0; s < 4; s++) {
            uint32_t af[2][4], bf[8][2];
#pragma unroll
            for (int mi = 0; mi < 2; mi++) {
                int m = wm + mi * 16 + (q2 & 1) * 8 + r7;
                LDSM_X4(af[mi][0], af[mi][1], af[mi][2], af[mi][3],
                        aBase + qoff(m, 2 * s + (q2 >> 1)));
            }
#pragma unroll
            for (int nj = 0; nj < 4; nj++) {
                int n = wn + nj * 16 + (q2 >> 1) * 8 + r7;
                LDSM_X4(bf[2 * nj][0], bf[2 * nj][1], bf[2 * nj + 1][0], bf[2 * nj + 1][1],
                        bBase + qoff(n, 2 * s + (q2 & 1)));
            }
#pragma unroll
            for (int mi = 0; mi < 2; mi++)
#pragma unroll
                for (int ni = 0; ni < 8; ni++)
                    mma16(acc[mi][ni], af[mi], bf[ni]);
        }
        // no tail sync: next iteration's top sync protects the stage rotation
    }
#undef GH_ISSUE

    __half* Ch = (__half*)C;
    float*  Cf = (float*)C;
#pragma unroll
    for (int mi = 0; mi < 2; mi++) {
#pragma unroll
        for (int rh = 0; rh < 2; rh++) {
            int row = bm + wm + mi * 16 + g + rh * 8;
#pragma unroll
            for (int ni = 0; ni < 8; ni++) {
                int n = bn + wn + ni * 8 + tq * 2;
                float v0 = acc[mi][ni][rh * 2], v1 = acc[mi][ni][rh * 2 + 1];
                if (BI) { v0 += bias[n]; v1 += bias[n + 1]; }
                if (HOUT) {
                    *(__half2*)(Ch + (long)row * ldc + n) = __floats2half2_rn(v0, v1);
                } else {
                    if (RE) {
                        float2 rv = *(const float2*)(resid + (long)row * ldc + n);
                        v0 += rv.x; v1 += rv.y;
                    }
                    float2 ov; ov.x = v0; ov.y = v1;
                    *(float2*)(Cf + (long)row * ldc + n) = ov;
                }
            }
        }
    }
}

// ---------------- MoE up: indexed-A grouped GEMM, GELU*gate epilogue --------
__global__ void __launch_bounds__(256, 2) gemm_up(
    const __half* __restrict__ Ah, const __half* __restrict__ w1t,
    __half* __restrict__ uws, const float* __restrict__ b1,
    const float* __restrict__ gd, const int* __restrict__ rowidx,
    const int* __restrict__ cnt) {
    constexpr int STAGE = 32768, BOFF = 16384;
    extern __shared__ __align__(16) char smdyn[];
    uint32_t sb = smem_u32(smdyn);

    int e = blockIdx.z;
    int c = cnt[e];
    int cp = (c + 127) & ~127;
    int bm = blockIdx.y * 128;
    if (bm >= cp) return;
    int bn = blockIdx.x * 128;

    int tid = threadIdx.x, lane = tid & 31, warp = tid >> 5;
    int wm = (warp % 4) * 32, wn = (warp / 4) * 64;
    int g = lane >> 2, tq = lane & 3;
    int q2 = lane >> 3, r7 = lane & 7;
    const __half* Bp = w1t + (long)e * (H_ * D_);
    const int* ridx = rowidx + (long)e * CAP_;

    int tokA[4];
#pragma unroll
    for (int j = 0; j < 4; j++) {
        int r = (tid + 256 * j) >> 3;
        tokA[j] = ridx[bm + r];
    }

    float acc[2][8][4];
#pragma unroll
    for (int mi = 0; mi < 2; mi++)
#pragma unroll
        for (int ni = 0; ni < 8; ni++)
#pragma unroll
            for (int r = 0; r < 4; r++) acc[mi][ni][r] = 0.f;

#define UP_ISSUE(st, k0)                                                              \
    do {                                                                              \
        uint32_t _as = sb + (st) * STAGE, _bs = _as + BOFF;                           \
        _Pragma("unroll")                                                             \
        for (int j = 0; j < 4; j++) {                                                 \
            int s = tid + 256 * j; int r = s >> 3, cu = s & 7;                        \
            CP_ASYNC16(_as + qoff(r, cu), Ah + (long)tokA[j] * D_ + (k0) + cu * 8);   \
            CP_ASYNC16(_bs + qoff(r, cu), Bp + (long)(bn + r) * D_ + (k0) + cu * 8);  \
        }                                                                             \
    } while (0)

    UP_ISSUE(0, 0); CP_COMMIT();
    UP_ISSUE(1, 64); CP_COMMIT();

    for (int ck = 0; ck < 16; ck++) {
        CP_WAIT1();
        __syncthreads();
        if (ck + 2 < 16) { int st = (ck + 2) % 3; UP_ISSUE(st, (ck + 2) << 6); }
        CP_COMMIT();
        uint32_t aBase = sb + (ck % 3) * STAGE, bBase = aBase + BOFF;
#pragma unroll
        for (int s = 0; s < 4; s++) {
            uint32_t af[2][4], bf[8][2];
#pragma unroll
            for (int mi = 0; mi < 2; mi++) {
                int m = wm + mi * 16 + (q2 & 1) * 8 + r7;
                LDSM_X4(af[mi][0], af[mi][1], af[mi][2], af[mi][3],
                        aBase + qoff(m, 2 * s + (q2 >> 1)));
            }
#pragma unroll
            for (int nj = 0; nj < 4; nj++) {
                int n = wn + nj * 16 + (q2 >> 1) * 8 + r7;
                LDSM_X4(bf[2 * nj][0], bf[2 * nj][1], bf[2 * nj + 1][0], bf[2 * nj + 1][1],
                        bBase + qoff(n, 2 * s + (q2 & 1)));
            }
#pragma unroll
            for (int mi = 0; mi < 2; mi++)
#pragma unroll
                for (int ni = 0; ni < 8; ni++)
                    mma16(acc[mi][ni], af[mi], bf[ni]);
        }
        // no tail sync (see gemm_h)
    }
#undef UP_ISSUE

    const float* b1e = b1 + (long)e * H_;
#pragma unroll
    for (int mi = 0; mi < 2; mi++) {
#pragma unroll
        for (int rh = 0; rh < 2; rh++) {
            int row = bm + wm + mi * 16 + g + rh * 8;
            int tok = ridx[row];
            float gv = gd[(long)tok * 16 + e];
            __half* orow = uws + ((long)e * CAP_ + row) * H_;
#pragma unroll
            for (int ni = 0; ni < 8; ni++) {
                int n = bn + wn + ni * 8 + tq * 2;
                float v0 = gelu_f(acc[mi][ni][rh * 2]     + b1e[n])     * gv;
                float v1 = gelu_f(acc[mi][ni][rh * 2 + 1] + b1e[n + 1]) * gv;
                *(__half2*)(orow + n) = __floats2half2_rn(v0, v1);
            }
        }
    }
}

// ---------------- MoE down: grouped GEMM, K=256 -----------------------------
__global__ void __launch_bounds__(256, 2) gemm_dn(
    const __half* __restrict__ uws, const __half* __restrict__ w2te,
    __half* __restrict__ outs, const int* __restrict__ cnt) {
    constexpr int STAGE = 32768, BOFF = 16384;
    extern __shared__ __align__(16) char smdyn[];
    uint32_t sb = smem_u32(smdyn);

    int e = blockIdx.z;
    int c = cnt[e];
    int cp = (c + 127) & ~127;
    int bm = blockIdx.y * 128;
    if (bm >= cp) return;
    int bn = blockIdx.x * 128;

    int tid = threadIdx.x, lane = tid & 31, warp = tid >> 5;
    int wm = (warp % 4) * 32, wn = (warp / 4) * 64;
    int g = lane >> 2, tq = lane & 3;
    int q2 = lane >> 3, r7 = lane & 7;
    const __half* Ap = uws + (long)e * CAP_ * H_;
    const __half* Bp = w2te + (long)e * (D_ * H_);

    float acc[2][8][4];
#pragma unroll
    for (int mi = 0; mi < 2; mi++)
#pragma unroll
        for (int ni = 0; ni < 8; ni++)
#pragma unroll
            for (int r = 0; r < 4; r++) acc[mi][ni][r] = 0.f;

#define DN_ISSUE(st, k0)                                                              \
    do {                                                                              \
        uint32_t _as = sb + (st) * STAGE, _bs = _as + BOFF;                           \
        _Pragma("unroll")                                                             \
        for (int j = 0; j < 4; j++) {                                                 \
            int s = tid + 256 * j; int r = s >> 3, cu = s & 7;                        \
            CP_ASYNC16(_as + qoff(r, cu), Ap + (long)(bm + r) * H_ + (k0) + cu * 8);  \
            CP_ASYNC16(_bs + qoff(r, cu), Bp + (long)(bn + r) * H_ + (k0) + cu * 8);  \
        }                                                                             \
    } while (0)

    DN_ISSUE(0, 0); CP_COMMIT();
    DN_ISSUE(1, 64); CP_COMMIT();

    for (int ck = 0; ck < 4; ck++) {
        CP_WAIT1();
        __syncthreads();
        if (ck + 2 < 4) { int st = (ck + 2) % 3; DN_ISSUE(st, (ck + 2) << 6); }
        CP_COMMIT();
        uint32_t aBase = sb + (ck % 3) * STAGE, bBase = aBase + BOFF;
#pragma unroll
        for (int s = 0; s < 4; s++) {
            uint32_t af[2][4], bf[8][2];
#pragma unroll
            for (int mi = 0; mi < 2; mi++) {
                int m = wm + mi * 16 + (q2 & 1) * 8 + r7;
                LDSM_X4(af[mi][0], af[mi][1], af[mi][2], af[mi][3],
                        aBase + qoff(m, 2 * s + (q2 >> 1)));
            }
#pragma unroll
            for (int nj = 0; nj < 4; nj++) {
                int n = wn + nj * 16 + (q2 >> 1) * 8 + r7;
                LDSM_X4(bf[2 * nj][0], bf[2 * nj][1], bf[2 * nj + 1][0], bf[2 * nj + 1][1],
                        bBase + qoff(n, 2 * s + (q2 & 1)));
            }
#pragma unroll
            for (int mi = 0; mi < 2; mi++)
#pragma unroll
                for (int ni = 0; ni < 8; ni++)
                    mma16(acc[mi][ni], af[mi], bf[ni]);
        }
        // no tail sync (see gemm_h)
    }
#undef DN_ISSUE

#pragma unroll
    for (int mi = 0; mi < 2; mi++) {
#pragma unroll
        for (int rh = 0; rh < 2; rh++) {
            int row = bm + wm + mi * 16 + g + rh * 8;
            __half* orow = outs + ((long)e * CAP_ + row) * D_;
#pragma unroll
            for (int ni = 0; ni < 8; ni++) {
                int n = bn + wn + ni * 8 + tq * 2;
                *(__half2*)(orow + n) =
                    __floats2half2_rn(acc[mi][ni][rh * 2], acc[mi][ni][rh * 2 + 1]);
            }
        }
    }
}

// ---------------- gate v2: smem-cached gate matrix, 128 tokens/block --------
__global__ void __launch_bounds__(256) gate_v2(
    const __half* __restrict__ h3, const float* __restrict__ gate_w,
    const int* __restrict__ task_id,
    float* __restrict__ probs, float* __restrict__ gate_dense) {
    extern __shared__ float gwT[];   // [16][1024]
    const float* gw = gate_w + (long)(*task_id) * (D_ * E_);
    int tid = threadIdx.x;
#pragma unroll 8
    for (int j = 0; j < 64; j++) {
        int idx = tid + 256 * j;
        int d = idx >> 4, e = idx & 15;
        gwT[e * 1024 + d] = gw[idx];
    }
    __syncthreads();
    int warp = tid >> 5, lane = tid & 31;
    for (int i = 0; i < 16; i++) {
        long tok = (long)blockIdx.x * 128 + i * 8 + warp;
        const __half* hrow = h3 + tok * D_;
        float acc[16];
#pragma unroll
        for (int e = 0; e < 16; e++) acc[e] = 0.f;
#pragma unroll
        for (int j = 0; j < 8; j++) {
            int d0 = (j * 32 + lane) * 4;
            __half2 a = *(const __half2*)(hrow + d0);
            __half2 b = *(const __half2*)(hrow + d0 + 2);
            float2 fa = __half22float2(a), fb = __half22float2(b);
#pragma unroll
            for (int e = 0; e < 16; e++) {
                float4 g4 = *(const float4*)&gwT[e * 1024 + d0];
                acc[e] += fa.x * g4.x + fa.y * g4.y + fb.x * g4.z + fb.y * g4.w;
            }
        }
#pragma unroll
        for (int e = 0; e < 16; e++) {
#pragma unroll
            for (int o = 16; o; o >>= 1)
                acc[e] += __shfl_xor_sync(0xffffffffu, acc[e], o);
        }
        if (lane == 0) {
            float mx = -1e30f;
#pragma unroll
            for (int e = 0; e < 16; e++) mx = fmaxf(mx, acc[e]);
            float sum = 0.f;
#pragma unroll
            for (int e = 0; e < 16; e++) { acc[e] = expf(acc[e] - mx); sum += acc[e]; }
            float inv = 1.f / sum;
            float p[16];
#pragma unroll
            for (int e = 0; e < 16; e++) { p[e] = acc[e] * inv; probs[tok * 16 + e] = p[e]; }
            bool used[16];
#pragma unroll
            for (int e = 0; e < 16; e++) used[e] = false;
            int tix[8]; float tvl[8]; float gsum = 0.f;
            for (int kk = 0; kk < 8; kk++) {
                float best = -1.f; int bi = 0;
                for (int e = 0; e < 16; e++)
                    if (!used[e] && p[e] > best) { best = p[e]; bi = e; }
                used[bi] = true; tix[kk] = bi; tvl[kk] = best; gsum += best;
            }
            float ginv = 1.f / (gsum + 1e-6f);
            float gdv[16];
#pragma unroll
            for (int e = 0; e < 16; e++) gdv[e] = 0.f;
            for (int kk = 0; kk < 8; kk++) gdv[tix[kk]] = tvl[kk] * ginv;
#pragma unroll
            for (int e = 0; e < 16; e++) gate_dense[tok * 16 + e] = gdv[e];
        }
    }
}

// ---------------- routing ----------------------------------------------------
__global__ void route_k(const float* __restrict__ gd, int* __restrict__ cnt,
                        int* __restrict__ rowidx, int* __restrict__ pairpos) {
    int t = blockIdx.x * 128 + threadIdx.x;
    int k = 0;
#pragma unroll
    for (int e = 0; e < E_; e++) {
        float v = gd[(long)t * 16 + e];
        if (v > 0.f && k < 8) {
            int pos = atomicAdd(&cnt[e], 1);
            rowidx[(long)e * CAP_ + pos] = t;
            pairpos[(long)t * 8 + k] = e * CAP_ + pos;
            k++;
        }
    }
}

// ---------------- gather: 2 tokens/block ------------------------------------
__global__ void __launch_bounds__(512) gather_k(
    const float* __restrict__ x, const __half* __restrict__ outs,
    const int* __restrict__ pairpos, const float* __restrict__ gd,
    const float* __restrict__ b2, float* __restrict__ out) {
    int half_ = threadIdx.x >> 8;
    int tid = threadIdx.x & 255;
    long t = (long)blockIdx.x * 2 + half_;
    __shared__ int pp[2][8];
    __shared__ float gdv[2][16];
    if (tid < 8) pp[half_][tid] = pairpos[t * 8 + tid];
    if (tid < 16) gdv[half_][tid] = gd[t * 16 + tid];
    __syncthreads();
    int d = tid * 4;
    float4 a = *(const float4*)(x + t * D_ + d);
#pragma unroll
    for (int k = 0; k < 8; k++) {
        const __half2* o2 = (const __half2*)(outs + (long)pp[half_][k] * D_ + d);
        float2 f0 = __half22float2(o2[0]), f1 = __half22float2(o2[1]);
        a.x += f0.x; a.y += f0.y; a.z += f1.x; a.w += f1.y;
    }
#pragma unroll
    for (int e = 0; e < 16; e++) {
        float4 bv = *(const float4*)(b2 + (long)e * D_ + d);
        float gv = gdv[half_][e];
        a.x += gv * bv.x; a.y += gv * bv.y; a.z += gv * bv.z; a.w += gv * bv.w;
    }
    *(float4*)(out + t * D_ + d) = a;
}

// ---------------- aux loss: 64 deterministic partials + final ----------------
__global__ void aux_part(const float* __restrict__ probs, float* __restrict__ part) {
    int b = blockIdx.x, tid = threadIdx.x;
    const float* p = probs + ((long)b * 256 + tid) * 16;
    float v[16];
#pragma unroll
    for (int e = 0; e < 16; e++) v[e] = p[e];
    __shared__ float red[256][17];
#pragma unroll
    for (int e = 0; e < 16; e++) red[tid][e] = v[e];
    __syncthreads();
    for (int s = 128; s; s >>= 1) {
        if (tid < s) {
#pragma unroll
            for (int e = 0; e < 16; e++) red[tid][e] += red[tid + s][e];
        }
        __syncthreads();
    }
    if (tid == 0) {
#pragma unroll
        for (int e = 0; e < 16; e++) part[b * 16 + e] = red[0][e];
    }
}
__global__ void aux_fin(const float* __restrict__ part, float* __restrict__ outv) {
    if (threadIdx.x == 0) {
        float aux = 0.f;
        for (int e = 0; e < 16; e++) {
            float s = 0.f;
            for (int b = 0; b < 64; b++) s += part[b * 16 + e];
            float mp = s * (1.f / T_);
            aux += mp * logf(mp + 1e-6f);
        }
        outv[0] = 5e-4f * aux;
    }
}

// ---------------- launch -----------------------------------------------------
extern "C" void kernel_launch(void* const* d_in, const int* in_sizes, int n_in,
                              void* d_out, int out_size) {
    const float* tgt        = (const float*)d_in[0];
    const float* ln1_g      = (const float*)d_in[2];
    const float* ln1_b      = (const float*)d_in[3];
    const float* ln3_g      = (const float*)d_in[4];
    const float* ln3_b      = (const float*)d_in[5];
    const float* in_proj_w  = (const float*)d_in[6];
    const float* in_proj_b  = (const float*)d_in[7];
    const float* out_proj_w = (const float*)d_in[8];
    const float* out_proj_b = (const float*)d_in[9];
    const float* gate_w     = (const float*)d_in[10];
    const float* w1         = (const float*)d_in[11];
    const float* b1         = (const float*)d_in[12];
    const float* w2         = (const float*)d_in[13];
    const float* b2         = (const float*)d_in[14];
    const int*   task_id    = (const int*)d_in[15];

    float* out       = (float*)d_out;
    float* out_x     = out;
    float* out_aux   = out + (size_t)T_ * D_;
    float* out_probs = out_aux + 1;

    __half *h16, *qkv16, *ctx16, *wi16, *wo16, *w1t16, *w2te16, *uws, *outs;
    float *x, *gd, *auxp;
    int *cnt, *rowidx, *pairpos;
    cudaGetSymbolAddress((void**)&h16,    g_h16);
    cudaGetSymbolAddress((void**)&qkv16,  g_qkv16);
    cudaGetSymbolAddress((void**)&ctx16,  g_ctx16);
    cudaGetSymbolAddress((void**)&x,      g_x);
    cudaGetSymbolAddress((void**)&gd,     g_gate);
    cudaGetSymbolAddress((void**)&wi16,   g_wi16);
    cudaGetSymbolAddress((void**)&wo16,   g_wo16);
    cudaGetSymbolAddress((void**)&w1t16,  g_w1t16);
    cudaGetSymbolAddress((void**)&w2te16, g_w2te16);
    cudaGetSymbolAddress((void**)&uws,    g_uws);
    cudaGetSymbolAddress((void**)&outs,   g_outs);
    cudaGetSymbolAddress((void**)&cnt,    g_cnt);
    cudaGetSymbolAddress((void**)&rowidx, g_rowidx);
    cudaGetSymbolAddress((void**)&pairpos,g_pairpos);
    cudaGetSymbolAddress((void**)&auxp,   g_auxp);

    const int GSM = 3 * 32768;      // 98304
    const int GATESM = 65536;
    cudaFuncSetAttribute(gemm_h<true, false, true >, cudaFuncAttributeMaxDynamicSharedMemorySize, GSM);
    cudaFuncSetAttribute(gemm_h<true, true,  false>, cudaFuncAttributeMaxDynamicSharedMemorySize, GSM);
    cudaFuncSetAttribute(gemm_up, cudaFuncAttributeMaxDynamicSharedMemorySize, GSM);
    cudaFuncSetAttribute(gemm_dn, cudaFuncAttributeMaxDynamicSharedMemorySize, GSM);
    cudaFuncSetAttribute(gate_v2, cudaFuncAttributeMaxDynamicSharedMemorySize, GATESM);

    // 0. weight preprocessing (merged converts + cnt zero) and transposes
    conv2_k<<<(unsigned)(4L * D_ * D_ / 1024), 256>>>(
        in_proj_w, wi16, 3L * D_ * D_, out_proj_w, wo16, cnt);
    transpose_h<float><<<dim3(8, 32, E_), 256>>>(
        w1, w1t16, D_, H_, H_, (long)D_ * H_, 0, (long)H_ * D_, 0, 1);
    transpose_h<float><<<dim3(32, 8, E_), 256>>>(
        w2, w2te16, H_, D_, D_, (long)H_ * D_, 0, (long)D_ * H_, 0, 1);

    // 1. h = LN1(tgt)
    ln_kernel<<<T_ / 2, 512>>>(tgt, ln1_g, ln1_b, h16);

    // 2. qkv = h @ in_proj_w^T + b (half out)
    gemm_h<true, false, true><<<dim3(24, 128), 256, GSM>>>(
        h16, wi16, qkv16, in_proj_b, nullptr, D_, D_, D_, 3 * D_);

    // 3. fused flash attention (direct V) -> ctx16
    flash_k<<<dim3(4, B_ * NH_), 256>>>(qkv16, ctx16);

    // 4. x = tgt + ctx @ out_proj_w^T + b (fp32 out)
    gemm_h<true, true, false><<<dim3(8, 128), 256, GSM>>>(
        ctx16, wo16, x, out_proj_b, tgt, D_, D_, D_, D_);

    // 5. h3 = LN3(x)
    ln_kernel<<<T_ / 2, 512>>>(x, ln3_g, ln3_b, h16);

    // 6. gate / aux
    gate_v2<<<T_ / 128, 256, GATESM>>>(h16, gate_w, task_id, out_probs, gd);
    aux_part<<<64, 256>>>(out_probs, auxp);
    aux_fin<<<1, 32>>>(auxp, out_aux);

    // 7. routing (cnt zeroed in conv2_k at graph start; re-zeroed each replay)
    route_k<<<T_ / 128, 128>>>(gd, cnt, rowidx, pairpos);

    // 8. sparse MoE up
    gemm_up<<<dim3(2, 128, E_), 256, GSM>>>(h16, w1t16, uws, b1, gd, rowidx, cnt);

    // 9. sparse MoE down
    gemm_dn<<<dim3(8, 128, E_), 256, GSM>>>(uws, w2te16, outs, cnt);

    // 10. gather: out = x + sum_k outs + gd @ b2
    gather_k<<<T_ / 2, 512>>>(x, outs, pairpos, gd, b2, out_x);

    (void)in_sizes; (void)n_in; (void)out_size;
}

// round 16
// speedup vs baseline: 1.0716x; 1.0007x over previous
#include <cuda_runtime.h>
#include <cuda_fp16.h>
#include <math.h>
#include <stdint.h>

#define B_   32
#define S_   512
#define D_   1024
#define NH_  16
#define E_   16
#define H_   256
#define DH_  64
#define T_   (B_ * S_)          // 16384
#define CAP_ 16384

// ---------------- scratch (static device memory) ---------------------------
__device__ __half g_h16[(size_t)T_ * D_];
__device__ __half g_qkv16[(size_t)T_ * 3 * D_];
__device__ __half g_ctx16[(size_t)T_ * D_];
__device__ float  g_x[(size_t)T_ * D_];
__device__ float  g_gate[(size_t)T_ * E_];
__device__ __half g_wi16[(size_t)3 * D_ * D_];
__device__ __half g_wo16[(size_t)D_ * D_];
__device__ __half g_w1t16[(size_t)E_ * H_ * D_];
__device__ __half g_w2te16[(size_t)E_ * D_ * H_];
__device__ __half g_uws[(size_t)E_ * CAP_ * H_];
__device__ __half g_outs[(size_t)E_ * CAP_ * D_];
__device__ int    g_cnt[E_];
__device__ int    g_rowidx[(size_t)E_ * CAP_];
__device__ int    g_pairpos[(size_t)T_ * 8];
__device__ float  g_auxp[64 * E_];

// ---------------- helpers ---------------------------------------------------
__device__ __forceinline__ uint32_t smem_u32(const void* p) {
    uint32_t a;
    asm("{ .reg .u64 t; cvta.to.shared.u64 t, %1; cvt.u32.u64 %0, t; }" : "=r"(a) : "l"(p));
    return a;
}
__device__ __forceinline__ uint32_t h2_as_u32(__half2 h) {
    return *reinterpret_cast<uint32_t*>(&h);
}
#define CP_ASYNC16(dst, src) \
    asm volatile("cp.async.ca.shared.global [%0], [%1], 16;" :: "r"(dst), "l"(src) : "memory")
#define CP_COMMIT() asm volatile("cp.async.commit_group;" ::: "memory")
#define CP_WAIT1()  asm volatile("cp.async.wait_group 1;" ::: "memory")
#define CP_WAIT0()  asm volatile("cp.async.wait_group 0;" ::: "memory")

#define LDSM_X4(r0, r1, r2, r3, addr) \
    asm volatile("ldmatrix.sync.aligned.m8n8.x4.shared.b16 {%0,%1,%2,%3}, [%4];" \
        : "=r"(r0), "=r"(r1), "=r"(r2), "=r"(r3) : "r"(addr))
#define LDSM_X4_T(r0, r1, r2, r3, addr) \
    asm volatile("ldmatrix.sync.aligned.m8n8.x4.trans.shared.b16 {%0,%1,%2,%3}, [%4];" \
        : "=r"(r0), "=r"(r1), "=r"(r2), "=r"(r3) : "r"(addr))

__device__ __forceinline__ void mma16(float* d, const uint32_t* a, const uint32_t* b) {
    asm volatile(
        "mma.sync.aligned.m16n8k16.row.col.f32.f16.f16.f32 "
        "{%0,%1,%2,%3},{%4,%5,%6,%7},{%8,%9},{%0,%1,%2,%3};"
        : "+f"(d[0]), "+f"(d[1]), "+f"(d[2]), "+f"(d[3])
        : "r"(a[0]), "r"(a[1]), "r"(a[2]), "r"(a[3]), "r"(b[0]), "r"(b[1]));
}

// smem tile: 64 halfs (128B) per row, SW128
__device__ __forceinline__ uint32_t qoff(int m, int c) {
    return (uint32_t)(m * 128 + ((c ^ (m & 7)) << 4));
}
__device__ __forceinline__ float gelu_f(float v) {
    return 0.5f * v * (1.f + erff(v * 0.70710678118654752f));
}

// ---------------- LayerNorm (round-14 form: 1 row / 256 threads) ------------
__global__ void ln_kernel(const float* __restrict__ x, const float* __restrict__ g,
                          const float* __restrict__ b, __half* __restrict__ y16) {
    long t = blockIdx.x;
    const float* row = x + t * D_;
    int tid = threadIdx.x;
    float4 v = *(const float4*)(row + tid * 4);
    float s = v.x + v.y + v.z + v.w;
    float sq = v.x * v.x + v.y * v.y + v.z * v.z + v.w * v.w;
#pragma unroll
    for (int o = 16; o; o >>= 1) {
        s  += __shfl_xor_sync(0xffffffffu, s, o);
        sq += __shfl_xor_sync(0xffffffffu, sq, o);
    }
    __shared__ float ws[8], wq[8];
    int w = tid >> 5, l = tid & 31;
    if (l == 0) { ws[w] = s; wq[w] = sq; }
    __syncthreads();
    if (tid == 0) {
        float a = 0.f, c = 0.f;
        for (int i = 0; i < 8; i++) { a += ws[i]; c += wq[i]; }
        ws[0] = a; wq[0] = c;
    }
    __syncthreads();
    float mean = ws[0] * (1.f / D_);
    float var  = wq[0] * (1.f / D_) - mean * mean;
    float inv  = rsqrtf(var + 1e-5f);
    int d = tid * 4;
    float4 gv = *(const float4*)(g + d);
    float4 bv = *(const float4*)(b + d);
    __half2 o0 = __floats2half2_rn((v.x - mean) * inv * gv.x + bv.x,
                                   (v.y - mean) * inv * gv.y + bv.y);
    __half2 o1 = __floats2half2_rn((v.z - mean) * inv * gv.z + bv.z,
                                   (v.w - mean) * inv * gv.w + bv.w);
    *(__half2*)(y16 + t * D_ + d)     = o0;
    *(__half2*)(y16 + t * D_ + d + 2) = o1;
}

// ---------------- fused fp32->fp16 convert (2 tensors) + cnt zero -----------
__global__ void conv2_k(const float* __restrict__ a, __half* __restrict__ oa, long na,
                        const float* __restrict__ b, __half* __restrict__ ob,
                        int* __restrict__ cnt) {
    if (blockIdx.x == 0 && threadIdx.x < E_) cnt[threadIdx.x] = 0;
    long i = (long)blockIdx.x * 1024 + threadIdx.x * 4;
    if (i < na) {
        float4 v = *(const float4*)(a + i);
        *(__half2*)(oa + i)     = __floats2half2_rn(v.x, v.y);
        *(__half2*)(oa + i + 2) = __floats2half2_rn(v.z, v.w);
    } else {
        long j = i - na;
        float4 v = *(const float4*)(b + j);
        *(__half2*)(ob + j)     = __floats2half2_rn(v.x, v.y);
        *(__half2*)(ob + j + 2) = __floats2half2_rn(v.z, v.w);
    }
}

// ---------------- batched tiled transpose -> half ---------------------------
template <typename TI>
__global__ void transpose_h(const TI* __restrict__ src, __half* __restrict__ dst,
                            int R, int C, long srcRS,
                            long sSo, long sSi, long sDo, long sDi, int nInner) {
    int zo = blockIdx.z / nInner, zi = blockIdx.z - zo * nInner;
    src += (long)zo * sSo + (long)zi * sSi;
    dst += (long)zo * sDo + (long)zi * sDi;
    __shared__ float tile[32][33];
    int r0 = blockIdx.y * 32, c0 = blockIdx.x * 32;
    int tx = threadIdx.x & 31, ty = threadIdx.x >> 5;
#pragma unroll
    for (int k = 0; k < 4; k++) {
        int r = r0 + ty + 8 * k;
        if (r < R && c0 + tx < C) tile[ty + 8 * k][tx] = (float)src[(long)r * srcRS + c0 + tx];
    }
    __syncthreads();
#pragma unroll
    for (int k = 0; k < 4; k++) {
        int c = c0 + ty + 8 * k;
        if (c < C && r0 + tx < R) dst[(long)c * R + r0 + tx] = __float2half(tile[tx][ty + 8 * k]);
    }
}

// ---------------- fused flash attention, direct-V, 2 CTAs/SM ----------------
__global__ void __launch_bounds__(256, 2) flash_k(
    const __half* __restrict__ qkv, __half* __restrict__ ctx) {
    int bh = blockIdx.y;
    int b = bh >> 4, hh = bh & 15;
    int qb = blockIdx.x;
    const __half* Qb = qkv + ((long)b * S_ + qb * 128) * (3 * D_) + hh * DH_;
    const __half* Kb = qkv + (long)b * S_ * (3 * D_) + D_ + hh * DH_;
    const __half* Vb = qkv + (long)b * S_ * (3 * D_) + 2 * D_ + hh * DH_;

    __shared__ __align__(16) __half Qs[128 * 64];
    __shared__ __align__(16) __half Ks[2][64 * 64];
    __shared__ __align__(16) __half Vs[2][64 * 64];
    uint32_t qB = smem_u32(Qs), kB = smem_u32(Ks), vB = smem_u32(Vs);

    int tid = threadIdx.x, lane = tid & 31, warp = tid >> 5;
    int wm = warp * 16;
    int g = lane >> 2, tq = lane & 3;
    int q2 = lane >> 3, r7 = lane & 7;
    const float L2E = 1.44269504088896f;

#pragma unroll
    for (int j = 0; j < 4; j++) {
        int s = tid + 256 * j;
        int r = s >> 3, cu = s & 7;
        CP_ASYNC16(qB + qoff(r, cu), Qb + (long)r * (3 * D_) + cu * 8);
    }
    CP_COMMIT();
#pragma unroll
    for (int j = 0; j < 2; j++) {
        int s = tid + 256 * j;
        int r = s >> 3, cu = s & 7;
        CP_ASYNC16(kB + qoff(r, cu), Kb + (long)r * (3 * D_) + cu * 8);
        CP_ASYNC16(vB + qoff(r, cu), Vb + (long)r * (3 * D_) + cu * 8);
    }
    CP_COMMIT();
    CP_WAIT0();
    __syncthreads();
    {
        __half2 sc = __floats2half2_rn(0.125f, 0.125f);
        __half2* qh = (__half2*)Qs;
#pragma unroll
        for (int i = 0; i < 16; i++) qh[tid + 256 * i] = __hmul2(qh[tid + 256 * i], sc);
    }
    __syncthreads();

    float o[8][4];
#pragma unroll
    for (int ni = 0; ni < 8; ni++)
#pragma unroll
        for (int r = 0; r < 4; r++) o[ni][r] = 0.f;
    float m0 = -1e30f, m1 = -1e30f, l0 = 0.f, l1 = 0.f;

    for (int c = 0; c < 8; c++) {
        int buf = c & 1;
        if (c + 1 < 8) {
            int nb = 1 - buf;
#pragma unroll
            for (int j = 0; j < 2; j++) {
                int s = tid + 256 * j;
                int r = s >> 3, cu = s & 7;
                CP_ASYNC16(kB + nb * 8192 + qoff(r, cu),
                           Kb + (long)((c + 1) * 64 + r) * (3 * D_) + cu * 8);
                CP_ASYNC16(vB + nb * 8192 + qoff(r, cu),
                           Vb + (long)((c + 1) * 64 + r) * (3 * D_) + cu * 8);
            }
            CP_COMMIT();
            CP_WAIT1();
        } else {
            CP_WAIT0();
        }
        __syncthreads();

        uint32_t kBuf = kB + buf * 8192, vBuf = vB + buf * 8192;
        float sv[8][4];
#pragma unroll
        for (int ni = 0; ni < 8; ni++)
#pragma unroll
            for (int r = 0; r < 4; r++) sv[ni][r] = 0.f;
#pragma unroll
        for (int ks = 0; ks < 4; ks++) {
            uint32_t af[4], bf[8][2];
            int am = wm + (q2 & 1) * 8 + r7;
            LDSM_X4(af[0], af[1], af[2], af[3], qB + qoff(am, 2 * ks + (q2 >> 1)));
#pragma unroll
            for (int nj = 0; nj < 4; nj++) {
                int bn = nj * 16 + (q2 >> 1) * 8 + r7;
                LDSM_X4(bf[2 * nj][0], bf[2 * nj][1], bf[2 * nj + 1][0], bf[2 * nj + 1][1],
                        kBuf + qoff(bn, 2 * ks + (q2 & 1)));
            }
#pragma unroll
            for (int ni = 0; ni < 8; ni++) mma16(sv[ni], af, bf[ni]);
        }

        float cm0 = -1e30f, cm1 = -1e30f;
#pragma unroll
        for (int ni = 0; ni < 8; ni++) {
            cm0 = fmaxf(cm0, fmaxf(sv[ni][0], sv[ni][1]));
            cm1 = fmaxf(cm1, fmaxf(sv[ni][2], sv[ni][3]));
        }
        cm0 = fmaxf(cm0, __shfl_xor_sync(0xffffffffu, cm0, 1));
        cm0 = fmaxf(cm0, __shfl_xor_sync(0xffffffffu, cm0, 2));
        cm1 = fmaxf(cm1, __shfl_xor_sync(0xffffffffu, cm1, 1));
        cm1 = fmaxf(cm1, __shfl_xor_sync(0xffffffffu, cm1, 2));
        float mn0 = fmaxf(m0, cm0), mn1 = fmaxf(m1, cm1);
        float sc0 = exp2f((m0 - mn0) * L2E), sc1 = exp2f((m1 - mn1) * L2E);
        m0 = mn0; m1 = mn1;
        l0 *= sc0; l1 *= sc1;
#pragma unroll
        for (int ni = 0; ni < 8; ni++) {
            o[ni][0] *= sc0; o[ni][1] *= sc0;
            o[ni][2] *= sc1; o[ni][3] *= sc1;
        }
        uint32_t pa[4][4];
        float rs0 = 0.f, rs1 = 0.f;
#pragma unroll
        for (int ni = 0; ni < 8; ni++) {
            float p0 = exp2f((sv[ni][0] - mn0) * L2E);
            float p1 = exp2f((sv[ni][1] - mn0) * L2E);
            float p2 = exp2f((sv[ni][2] - mn1) * L2E);
            float p3 = exp2f((sv[ni][3] - mn1) * L2E);
            rs0 += p0 + p1; rs1 += p2 + p3;
            int kk = ni >> 1, hi = ni & 1;
            pa[kk][hi * 2]     = h2_as_u32(__floats2half2_rn(p0, p1));
            pa[kk][hi * 2 + 1] = h2_as_u32(__floats2half2_rn(p2, p3));
        }
        rs0 += __shfl_xor_sync(0xffffffffu, rs0, 1);
        rs0 += __shfl_xor_sync(0xffffffffu, rs0, 2);
        rs1 += __shfl_xor_sync(0xffffffffu, rs1, 1);
        rs1 += __shfl_xor_sync(0xffffffffu, rs1, 2);
        l0 += rs0; l1 += rs1;

        // O += P @ V : B-fragments of V^T via ldmatrix.trans on V tiles
#pragma unroll
        for (int ks = 0; ks < 4; ks++) {
            uint32_t bf[8][2];
#pragma unroll
            for (int nj = 0; nj < 4; nj++) {
                int vrow = 16 * ks + (q2 & 1) * 8 + r7;   // key index
                int vchk = nj * 2 + (q2 >> 1);            // dh 16B-chunk
                LDSM_X4_T(bf[2 * nj][0], bf[2 * nj][1], bf[2 * nj + 1][0], bf[2 * nj + 1][1],
                          vBuf + qoff(vrow, vchk));
            }
#pragma unroll
            for (int ni = 0; ni < 8; ni++) mma16(o[ni], pa[ks], bf[ni]);
        }
        __syncthreads();   // load-bearing: refill is issued BEFORE the wait here
    }

    float li0 = 1.f / l0, li1 = 1.f / l1;
    long row0 = (long)b * S_ + qb * 128 + wm + g;
    __half* c0p = ctx + (row0)     * D_ + hh * DH_;
    __half* c1p = ctx + (row0 + 8) * D_ + hh * DH_;
#pragma unroll
    for (int ni = 0; ni < 8; ni++) {
        int nc = ni * 8 + tq * 2;
        *(__half2*)(c0p + nc) = __floats2half2_rn(o[ni][0] * li0, o[ni][1] * li0);
        *(__half2*)(c1p + nc) = __floats2half2_rn(o[ni][2] * li1, o[ni][3] * li1);
    }
}

// ---------------- fp16 GEMM: 128x128 tile, BK=64, 3 stages, 2 CTAs/SM -------
template <bool BI, bool RE, bool HOUT>
__global__ void __launch_bounds__(256, 2) gemm_h(
    const __half* __restrict__ A, const __half* __restrict__ Bm, void* __restrict__ C,
    const float* __restrict__ bias, const float* __restrict__ resid,
    int Kd, int lda, int ldb, int ldc) {
    constexpr int STAGE = 32768, BOFF = 16384;
    extern __shared__ __align__(16) char smdyn[];
    uint32_t sb = smem_u32(smdyn);

    int tid = threadIdx.x, lane = tid & 31, warp = tid >> 5;
    int bm = blockIdx.y * 128, bn = blockIdx.x * 128;
    int wm = (warp % 4) * 32, wn = (warp / 4) * 64;
    int g = lane >> 2, tq = lane & 3;
    int q2 = lane >> 3, r7 = lane & 7;

    float acc[2][8][4];
#pragma unroll
    for (int mi = 0; mi < 2; mi++)
#pragma unroll
        for (int ni = 0; ni < 8; ni++)
#pragma unroll
            for (int r = 0; r < 4; r++) acc[mi][ni][r] = 0.f;

    int NC = Kd >> 6;
#define GH_ISSUE(st, k0)                                                              \
    do {                                                                              \
        uint32_t _as = sb + (st) * STAGE, _bs = _as + BOFF;                           \
        _Pragma("unroll")                                                             \
        for (int j = 0; j < 4; j++) {                                                 \
            int s = tid + 256 * j; int r = s >> 3, cu = s & 7;                        \
            CP_ASYNC16(_as + qoff(r, cu), A + (long)(bm + r) * lda + (k0) + cu * 8);  \
            CP_ASYNC16(_bs + qoff(r, cu), Bm + (long)(bn + r) * ldb + (k0) + cu * 8); \
        }                                                                             \
    } while (0)

    GH_ISSUE(0, 0); CP_COMMIT();
    GH_ISSUE(1, 64); CP_COMMIT();

    for (int ck = 0; ck < NC; ck++) {
        CP_WAIT1();
        __syncthreads();
        if (ck + 2 < NC) { int st = (ck + 2) % 3; GH_ISSUE(st, (ck + 2) << 6); }
        CP_COMMIT();
        uint32_t aBase = sb + (ck % 3) * STAGE, bBase = aBase + BOFF;
#pragma unroll
        for (int s = 0; s < 4; s++) {
            uint32_t af[2][4], bf[8][2];
#pragma unroll
            for (int mi = 0; mi < 2; mi++) {
                int m = wm + mi * 16 + (q2 & 1) * 8 + r7;
                LDSM_X4(af[mi][0], af[mi][1], af[mi][2], af[mi][3],
                        aBase + qoff(m, 2 * s + (q2 >> 1)));
            }
#pragma unroll
            for (int nj = 0; nj < 4; nj++) {
                int n = wn + nj * 16 + (q2 >> 1) * 8 + r7;
                LDSM_X4(bf[2 * nj][0], bf[2 * nj][1], bf[2 * nj + 1][0], bf[2 * nj + 1][1],
                        bBase + qoff(n, 2 * s + (q2 & 1)));
            }
#pragma unroll
            for (int mi = 0; mi < 2; mi++)
#pragma unroll
                for (int ni = 0; ni < 8; ni++)
                    mma16(acc[mi][ni], af[mi], bf[ni]);
        }
        // no tail sync: next iteration's top sync protects the stage rotation
    }
#undef GH_ISSUE

    __half* Ch = (__half*)C;
    float*  Cf = (float*)C;
#pragma unroll
    for (int mi = 0; mi < 2; mi++) {
#pragma unroll
        for (int rh = 0; rh < 2; rh++) {
            int row = bm + wm + mi * 16 + g + rh * 8;
#pragma unroll
            for (int ni = 0; ni < 8; ni++) {
                int n = bn + wn + ni * 8 + tq * 2;
                float v0 = acc[mi][ni][rh * 2], v1 = acc[mi][ni][rh * 2 + 1];
                if (BI) { v0 += bias[n]; v1 += bias[n + 1]; }
                if (HOUT) {
                    *(__half2*)(Ch + (long)row * ldc + n) = __floats2half2_rn(v0, v1);
                } else {
                    if (RE) {
                        float2 rv = *(const float2*)(resid + (long)row * ldc + n);
                        v0 += rv.x; v1 += rv.y;
                    }
                    float2 ov; ov.x = v0; ov.y = v1;
                    *(float2*)(Cf + (long)row * ldc + n) = ov;
                }
            }
        }
    }
}

// ---------------- MoE up: indexed-A grouped GEMM, GELU*gate epilogue --------
__global__ void __launch_bounds__(256, 2) gemm_up(
    const __half* __restrict__ Ah, const __half* __restrict__ w1t,
    __half* __restrict__ uws, const float* __restrict__ b1,
    const float* __restrict__ gd, const int* __restrict__ rowidx,
    const int* __restrict__ cnt) {
    constexpr int STAGE = 32768, BOFF = 16384;
    extern __shared__ __align__(16) char smdyn[];
    uint32_t sb = smem_u32(smdyn);

    int e = blockIdx.z;
    int c = cnt[e];
    int cp = (c + 127) & ~127;
    int bm = blockIdx.y * 128;
    if (bm >= cp) return;
    int bn = blockIdx.x * 128;

    int tid = threadIdx.x, lane = tid & 31, warp = tid >> 5;
    int wm = (warp % 4) * 32, wn = (warp / 4) * 64;
    int g = lane >> 2, tq = lane & 3;
    int q2 = lane >> 3, r7 = lane & 7;
    const __half* Bp = w1t + (long)e * (H_ * D_);
    const int* ridx = rowidx + (long)e * CAP_;

    int tokA[4];
#pragma unroll
    for (int j = 0; j < 4; j++) {
        int r = (tid + 256 * j) >> 3;
        tokA[j] = ridx[bm + r];
    }

    float acc[2][8][4];
#pragma unroll
    for (int mi = 0; mi < 2; mi++)
#pragma unroll
        for (int ni = 0; ni < 8; ni++)
#pragma unroll
            for (int r = 0; r < 4; r++) acc[mi][ni][r] = 0.f;

#define UP_ISSUE(st, k0)                                                              \
    do {                                                                              \
        uint32_t _as = sb + (st) * STAGE, _bs = _as + BOFF;                           \
        _Pragma("unroll")                                                             \
        for (int j = 0; j < 4; j++) {                                                 \
            int s = tid + 256 * j; int r = s >> 3, cu = s & 7;                        \
            CP_ASYNC16(_as + qoff(r, cu), Ah + (long)tokA[j] * D_ + (k0) + cu * 8);   \
            CP_ASYNC16(_bs + qoff(r, cu), Bp + (long)(bn + r) * D_ + (k0) + cu * 8);  \
        }                                                                             \
    } while (0)

    UP_ISSUE(0, 0); CP_COMMIT();
    UP_ISSUE(1, 64); CP_COMMIT();

    for (int ck = 0; ck < 16; ck++) {
        CP_WAIT1();
        __syncthreads();
        if (ck + 2 < 16) { int st = (ck + 2) % 3; UP_ISSUE(st, (ck + 2) << 6); }
        CP_COMMIT();
        uint32_t aBase = sb + (ck % 3) * STAGE, bBase = aBase + BOFF;
#pragma unroll
        for (int s = 0; s < 4; s++) {
            uint32_t af[2][4], bf[8][2];
#pragma unroll
            for (int mi = 0; mi < 2; mi++) {
                int m = wm + mi * 16 + (q2 & 1) * 8 + r7;
                LDSM_X4(af[mi][0], af[mi][1], af[mi][2], af[mi][3],
                        aBase + qoff(m, 2 * s + (q2 >> 1)));
            }
#pragma unroll
            for (int nj = 0; nj < 4; nj++) {
                int n = wn + nj * 16 + (q2 >> 1) * 8 + r7;
                LDSM_X4(bf[2 * nj][0], bf[2 * nj][1], bf[2 * nj + 1][0], bf[2 * nj + 1][1],
                        bBase + qoff(n, 2 * s + (q2 & 1)));
            }
#pragma unroll
            for (int mi = 0; mi < 2; mi++)
#pragma unroll
                for (int ni = 0; ni < 8; ni++)
                    mma16(acc[mi][ni], af[mi], bf[ni]);
        }
        // no tail sync (see gemm_h)
    }
#undef UP_ISSUE

    const float* b1e = b1 + (long)e * H_;
#pragma unroll
    for (int mi = 0; mi < 2; mi++) {
#pragma unroll
        for (int rh = 0; rh < 2; rh++) {
            int row = bm + wm + mi * 16 + g + rh * 8;
            int tok = ridx[row];
            float gv = gd[(long)tok * 16 + e];
            __half* orow = uws + ((long)e * CAP_ + row) * H_;
#pragma unroll
            for (int ni = 0; ni < 8; ni++) {
                int n = bn + wn + ni * 8 + tq * 2;
                float v0 = gelu_f(acc[mi][ni][rh * 2]     + b1e[n])     * gv;
                float v1 = gelu_f(acc[mi][ni][rh * 2 + 1] + b1e[n + 1]) * gv;
                *(__half2*)(orow + n) = __floats2half2_rn(v0, v1);
            }
        }
    }
}

// ---------------- MoE down: grouped GEMM, K=256, + gd*b2 in epilogue --------
__global__ void __launch_bounds__(256, 2) gemm_dn(
    const __half* __restrict__ uws, const __half* __restrict__ w2te,
    __half* __restrict__ outs, const int* __restrict__ cnt,
    const int* __restrict__ rowidx, const float* __restrict__ gd,
    const float* __restrict__ b2) {
    constexpr int STAGE = 32768, BOFF = 16384;
    extern __shared__ __align__(16) char smdyn[];
    uint32_t sb = smem_u32(smdyn);

    int e = blockIdx.z;
    int c = cnt[e];
    int cp = (c + 127) & ~127;
    int bm = blockIdx.y * 128;
    if (bm >= cp) return;
    int bn = blockIdx.x * 128;

    int tid = threadIdx.x, lane = tid & 31, warp = tid >> 5;
    int wm = (warp % 4) * 32, wn = (warp / 4) * 64;
    int g = lane >> 2, tq = lane & 3;
    int q2 = lane >> 3, r7 = lane & 7;
    const __half* Ap = uws + (long)e * CAP_ * H_;
    const __half* Bp = w2te + (long)e * (D_ * H_);
    const int* ridx = rowidx + (long)e * CAP_;

    float acc[2][8][4];
#pragma unroll
    for (int mi = 0; mi < 2; mi++)
#pragma unroll
        for (int ni = 0; ni < 8; ni++)
#pragma unroll
            for (int r = 0; r < 4; r++) acc[mi][ni][r] = 0.f;

#define DN_ISSUE(st, k0)                                                              \
    do {                                                                              \
        uint32_t _as = sb + (st) * STAGE, _bs = _as + BOFF;                           \
        _Pragma("unroll")                                                             \
        for (int j = 0; j < 4; j++) {                                                 \
            int s = tid + 256 * j; int r = s >> 3, cu = s & 7;                        \
            CP_ASYNC16(_as + qoff(r, cu), Ap + (long)(bm + r) * H_ + (k0) + cu * 8);  \
            CP_ASYNC16(_bs + qoff(r, cu), Bp + (long)(bn + r) * H_ + (k0) + cu * 8);  \
        }                                                                             \
    } while (0)

    DN_ISSUE(0, 0); CP_COMMIT();
    DN_ISSUE(1, 64); CP_COMMIT();

    for (int ck = 0; ck < 4; ck++) {
        CP_WAIT1();
        __syncthreads();
        if (ck + 2 < 4) { int st = (ck + 2) % 3; DN_ISSUE(st, (ck + 2) << 6); }
        CP_COMMIT();
        uint32_t aBase = sb + (ck % 3) * STAGE, bBase = aBase + BOFF;
#pragma unroll
        for (int s = 0; s < 4; s++) {
            uint32_t af[2][4], bf[8][2];
#pragma unroll
            for (int mi = 0; mi < 2; mi++) {
                int m = wm + mi * 16 + (q2 & 1) * 8 + r7;
                LDSM_X4(af[mi][0], af[mi][1], af[mi][2], af[mi][3],
                        aBase + qoff(m, 2 * s + (q2 >> 1)));
            }
#pragma unroll
            for (int nj = 0; nj < 4; nj++) {
                int n = wn + nj * 16 + (q2 >> 1) * 8 + r7;
                LDSM_X4(bf[2 * nj][0], bf[2 * nj][1], bf[2 * nj + 1][0], bf[2 * nj + 1][1],
                        bBase + qoff(n, 2 * s + (q2 & 1)));
            }
#pragma unroll
            for (int mi = 0; mi < 2; mi++)
#pragma unroll
                for (int ni = 0; ni < 8; ni++)
                    mma16(acc[mi][ni], af[mi], bf[ni]);
        }
        // no tail sync (see gemm_h)
    }
#undef DN_ISSUE

    const float* b2e = b2 + (long)e * D_;
#pragma unroll
    for (int mi = 0; mi < 2; mi++) {
#pragma unroll
        for (int rh = 0; rh < 2; rh++) {
            int row = bm + wm + mi * 16 + g + rh * 8;
            int tok = ridx[row];
            float gv = gd[(long)tok * 16 + e];
            __half* orow = outs + ((long)e * CAP_ + row) * D_;
#pragma unroll
            for (int ni = 0; ni < 8; ni++) {
                int n = bn + wn + ni * 8 + tq * 2;
                float2 bvv = *(const float2*)(b2e + n);
                *(__half2*)(orow + n) = __floats2half2_rn(
                    acc[mi][ni][rh * 2]     + gv * bvv.x,
                    acc[mi][ni][rh * 2 + 1] + gv * bvv.y);
            }
        }
    }
}

// ---------------- gate v2: smem-cached gate matrix, 128 tokens/block --------
__global__ void __launch_bounds__(256) gate_v2(
    const __half* __restrict__ h3, const float* __restrict__ gate_w,
    const int* __restrict__ task_id,
    float* __restrict__ probs, float* __restrict__ gate_dense) {
    extern __shared__ float gwT[];   // [16][1024]
    const float* gw = gate_w + (long)(*task_id) * (D_ * E_);
    int tid = threadIdx.x;
#pragma unroll 8
    for (int j = 0; j < 64; j++) {
        int idx = tid + 256 * j;
        int d = idx >> 4, e = idx & 15;
        gwT[e * 1024 + d] = gw[idx];
    }
    __syncthreads();
    int warp = tid >> 5, lane = tid & 31;
    for (int i = 0; i < 16; i++) {
        long tok = (long)blockIdx.x * 128 + i * 8 + warp;
        const __half* hrow = h3 + tok * D_;
        float acc[16];
#pragma unroll
        for (int e = 0; e < 16; e++) acc[e] = 0.f;
#pragma unroll
        for (int j = 0; j < 8; j++) {
            int d0 = (j * 32 + lane) * 4;
            __half2 a = *(const __half2*)(hrow + d0);
            __half2 b = *(const __half2*)(hrow + d0 + 2);
            float2 fa = __half22float2(a), fb = __half22float2(b);
#pragma unroll
            for (int e = 0; e < 16; e++) {
                float4 g4 = *(const float4*)&gwT[e * 1024 + d0];
                acc[e] += fa.x * g4.x + fa.y * g4.y + fb.x * g4.z + fb.y * g4.w;
            }
        }
#pragma unroll
        for (int e = 0; e < 16; e++) {
#pragma unroll
            for (int o = 16; o; o >>= 1)
                acc[e] += __shfl_xor_sync(0xffffffffu, acc[e], o);
        }
        if (lane == 0) {
            float mx = -1e30f;
#pragma unroll
            for (int e = 0; e < 16; e++) mx = fmaxf(mx, acc[e]);
            float sum = 0.f;
#pragma unroll
            for (int e = 0; e < 16; e++) { acc[e] = expf(acc[e] - mx); sum += acc[e]; }
            float inv = 1.f / sum;
            float p[16];
#pragma unroll
            for (int e = 0; e < 16; e++) { p[e] = acc[e] * inv; probs[tok * 16 + e] = p[e]; }
            bool used[16];
#pragma unroll
            for (int e = 0; e < 16; e++) used[e] = false;
            int tix[8]; float tvl[8]; float gsum = 0.f;
            for (int kk = 0; kk < 8; kk++) {
                float best = -1.f; int bi = 0;
                for (int e = 0; e < 16; e++)
                    if (!used[e] && p[e] > best) { best = p[e]; bi = e; }
                used[bi] = true; tix[kk] = bi; tvl[kk] = best; gsum += best;
            }
            float ginv = 1.f / (gsum + 1e-6f);
            float gdv[16];
#pragma unroll
            for (int e = 0; e < 16; e++) gdv[e] = 0.f;
            for (int kk = 0; kk < 8; kk++) gdv[tix[kk]] = tvl[kk] * ginv;
#pragma unroll
            for (int e = 0; e < 16; e++) gate_dense[tok * 16 + e] = gdv[e];
        }
    }
}

// ---------------- routing ----------------------------------------------------
__global__ void route_k(const float* __restrict__ gd, int* __restrict__ cnt,
                        int* __restrict__ rowidx, int* __restrict__ pairpos) {
    int t = blockIdx.x * 128 + threadIdx.x;
    int k = 0;
#pragma unroll
    for (int e = 0; e < E_; e++) {
        float v = gd[(long)t * 16 + e];
        if (v > 0.f && k < 8) {
            int pos = atomicAdd(&cnt[e], 1);
            rowidx[(long)e * CAP_ + pos] = t;
            pairpos[(long)t * 8 + k] = e * CAP_ + pos;
            k++;
        }
    }
}

// ---------------- gather: out = x + sum_k outs[pp[k]] (b2 already folded) ---
__global__ void __launch_bounds__(512) gather_k(
    const float* __restrict__ x, const __half* __restrict__ outs,
    const int* __restrict__ pairpos, float* __restrict__ out) {
    int half_ = threadIdx.x >> 8;
    int tid = threadIdx.x & 255;
    long t = (long)blockIdx.x * 2 + half_;
    __shared__ int pp[2][8];
    if (tid < 8) pp[half_][tid] = pairpos[t * 8 + tid];
    __syncthreads();
    int d = tid * 4;
    float4 a = *(const float4*)(x + t * D_ + d);
#pragma unroll
    for (int k = 0; k < 8; k++) {
        const __half2* o2 = (const __half2*)(outs + (long)pp[half_][k] * D_ + d);
        float2 f0 = __half22float2(o2[0]), f1 = __half22float2(o2[1]);
        a.x += f0.x; a.y += f0.y; a.z += f1.x; a.w += f1.y;
    }
    *(float4*)(out + t * D_ + d) = a;
}

// ---------------- aux loss: 64 deterministic partials + final ----------------
__global__ void aux_part(const float* __restrict__ probs, float* __restrict__ part) {
    int b = blockIdx.x, tid = threadIdx.x;
    const float* p = probs + ((long)b * 256 + tid) * 16;
    float v[16];
#pragma unroll
    for (int e = 0; e < 16; e++) v[e] = p[e];
    __shared__ float red[256][17];
#pragma unroll
    for (int e = 0; e < 16; e++) red[tid][e] = v[e];
    __syncthreads();
    for (int s = 128; s; s >>= 1) {
        if (tid < s) {
#pragma unroll
            for (int e = 0; e < 16; e++) red[tid][e] += red[tid + s][e];
        }
        __syncthreads();
    }
    if (tid == 0) {
#pragma unroll
        for (int e = 0; e < 16; e++) part[b * 16 + e] = red[0][e];
    }
}
__global__ void aux_fin(const float* __restrict__ part, float* __restrict__ outv) {
    if (threadIdx.x == 0) {
        float aux = 0.f;
        for (int e = 0; e < 16; e++) {
            float s = 0.f;
            for (int b = 0; b < 64; b++) s += part[b * 16 + e];
            float mp = s * (1.f / T_);
            aux += mp * logf(mp + 1e-6f);
        }
        outv[0] = 5e-4f * aux;
    }
}

// ---------------- launch -----------------------------------------------------
extern "C" void kernel_launch(void* const* d_in, const int* in_sizes, int n_in,
                              void* d_out, int out_size) {
    const float* tgt        = (const float*)d_in[0];
    const float* ln1_g      = (const float*)d_in[2];
    const float* ln1_b      = (const float*)d_in[3];
    const float* ln3_g      = (const float*)d_in[4];
    const float* ln3_b      = (const float*)d_in[5];
    const float* in_proj_w  = (const float*)d_in[6];
    const float* in_proj_b  = (const float*)d_in[7];
    const float* out_proj_w = (const float*)d_in[8];
    const float* out_proj_b = (const float*)d_in[9];
    const float* gate_w     = (const float*)d_in[10];
    const float* w1         = (const float*)d_in[11];
    const float* b1         = (const float*)d_in[12];
    const float* w2         = (const float*)d_in[13];
    const float* b2         = (const float*)d_in[14];
    const int*   task_id    = (const int*)d_in[15];

    float* out       = (float*)d_out;
    float* out_x     = out;
    float* out_aux   = out + (size_t)T_ * D_;
    float* out_probs = out_aux + 1;

    __half *h16, *qkv16, *ctx16, *wi16, *wo16, *w1t16, *w2te16, *uws, *outs;
    float *x, *gd, *auxp;
    int *cnt, *rowidx, *pairpos;
    cudaGetSymbolAddress((void**)&h16,    g_h16);
    cudaGetSymbolAddress((void**)&qkv16,  g_qkv16);
    cudaGetSymbolAddress((void**)&ctx16,  g_ctx16);
    cudaGetSymbolAddress((void**)&x,      g_x);
    cudaGetSymbolAddress((void**)&gd,     g_gate);
    cudaGetSymbolAddress((void**)&wi16,   g_wi16);
    cudaGetSymbolAddress((void**)&wo16,   g_wo16);
    cudaGetSymbolAddress((void**)&w1t16,  g_w1t16);
    cudaGetSymbolAddress((void**)&w2te16, g_w2te16);
    cudaGetSymbolAddress((void**)&uws,    g_uws);
    cudaGetSymbolAddress((void**)&outs,   g_outs);
    cudaGetSymbolAddress((void**)&cnt,    g_cnt);
    cudaGetSymbolAddress((void**)&rowidx, g_rowidx);
    cudaGetSymbolAddress((void**)&pairpos,g_pairpos);
    cudaGetSymbolAddress((void**)&auxp,   g_auxp);

    const int GSM = 3 * 32768;      // 98304
    const int GATESM = 65536;
    cudaFuncSetAttribute(gemm_h<true, false, true >, cudaFuncAttributeMaxDynamicSharedMemorySize, GSM);
    cudaFuncSetAttribute(gemm_h<true, true,  false>, cudaFuncAttributeMaxDynamicSharedMemorySize, GSM);
    cudaFuncSetAttribute(gemm_up, cudaFuncAttributeMaxDynamicSharedMemorySize, GSM);
    cudaFuncSetAttribute(gemm_dn, cudaFuncAttributeMaxDynamicSharedMemorySize, GSM);
    cudaFuncSetAttribute(gate_v2, cudaFuncAttributeMaxDynamicSharedMemorySize, GATESM);

    // 0. weight preprocessing (merged converts + cnt zero) and transposes
    conv2_k<<<(unsigned)(4L * D_ * D_ / 1024), 256>>>(
        in_proj_w, wi16, 3L * D_ * D_, out_proj_w, wo16, cnt);
    transpose_h<float><<<dim3(8, 32, E_), 256>>>(
        w1, w1t16, D_, H_, H_, (long)D_ * H_, 0, (long)H_ * D_, 0, 1);
    transpose_h<float><<<dim3(32, 8, E_), 256>>>(
        w2, w2te16, H_, D_, D_, (long)H_ * D_, 0, (long)D_ * H_, 0, 1);

    // 1. h = LN1(tgt)
    ln_kernel<<<T_, 256>>>(tgt, ln1_g, ln1_b, h16);

    // 2. qkv = h @ in_proj_w^T + b (half out)
    gemm_h<true, false, true><<<dim3(24, 128), 256, GSM>>>(
        h16, wi16, qkv16, in_proj_b, nullptr, D_, D_, D_, 3 * D_);

    // 3. fused flash attention (direct V) -> ctx16
    flash_k<<<dim3(4, B_ * NH_), 256>>>(qkv16, ctx16);

    // 4. x = tgt + ctx @ out_proj_w^T + b (fp32 out)
    gemm_h<true, true, false><<<dim3(8, 128), 256, GSM>>>(
        ctx16, wo16, x, out_proj_b, tgt, D_, D_, D_, D_);

    // 5. h3 = LN3(x)
    ln_kernel<<<T_, 256>>>(x, ln3_g, ln3_b, h16);

    // 6. gate / aux
    gate_v2<<<T_ / 128, 256, GATESM>>>(h16, gate_w, task_id, out_probs, gd);
    aux_part<<<64, 256>>>(out_probs, auxp);
    aux_fin<<<1, 32>>>(auxp, out_aux);

    // 7. routing (cnt zeroed in conv2_k each replay)
    route_k<<<T_ / 128, 128>>>(gd, cnt, rowidx, pairpos);

    // 8. sparse MoE up
    gemm_up<<<dim3(2, 128, E_), 256, GSM>>>(h16, w1t16, uws, b1, gd, rowidx, cnt);

    // 9. sparse MoE down (+ gd*b2 folded into epilogue)
    gemm_dn<<<dim3(8, 128, E_), 256, GSM>>>(uws, w2te16, outs, cnt, rowidx, gd, b2);

    // 10. gather: out = x + sum_k outs
    gather_k<<<T_ / 2, 512>>>(x, outs, pairpos, out_x);

    (void)in_sizes; (void)n_in; (void)out_size;
}